// round 2
// baseline (speedup 1.0000x reference)
#include <cuda_runtime.h>
#include <math.h>
#include <stdint.h>

#define BSZ 4
#define T 2048
#define H 1024
#define S 512
#define R 16
#define E 4
#define FDIM 38            // 6 + 2*R
#define M_TOT (BSZ*T)      // 8192
#define EH (E*H)           // 4096
#define K2 (2*EH)          // 8192
#define ETA 0.1f
#define EPS 1e-6f

// ----------------------------------------------------------------------------
// Scratch (static device globals; no allocation at runtime)
// ----------------------------------------------------------------------------
__device__ float g_zr[M_TOT * S];
__device__ float g_zi[M_TOT * S];
__device__ float g_ur[E * M_TOT * R];
__device__ float g_ui[E * M_TOT * R];
__device__ float g_fr[E * M_TOT * FDIM];
__device__ float g_fi[E * M_TOT * FDIM];
__device__ float g_YC[(size_t)M_TOT * K2];      // [8192, 8192]  yr|yi stacked along cols
__device__ float g_frf[M_TOT * H];
__device__ float g_fif[M_TOT * H];
__device__ float g_Wrst[(size_t)K2 * H];        // [fu_Wr ; -fu_Wi]
__device__ float g_Wist[(size_t)K2 * H];        // [fu_Wi ;  fu_Wr]
__device__ float g_CC[(size_t)M_TOT * (4*H)];   // [x | frf | fif | mag]

// ----------------------------------------------------------------------------
// Generic SIMT SGEMM: C[M,N] = A[M,K] @ B[K,N] + bias[N], 128x128x8 tile,
// 256 threads, 8x8 per thread, register-prefetch double buffering.
// Requires M%128==0, N%128==0, K%8==0.
// EPI==1: gate epilogue: g = sigmoid(v); C = g*e1 + (1-g)*e2
// ----------------------------------------------------------------------------
template<int EPI>
__global__ __launch_bounds__(256)
void sgemm_k(const float* __restrict__ A, const float* __restrict__ B,
             float* __restrict__ C, int M, int N, int K,
             const float* __restrict__ bias,
             const float* __restrict__ e1, const float* __restrict__ e2)
{
    __shared__ float As[8][128];
    __shared__ float Bs[8][128];
    const int tid = threadIdx.x;
    const int bx = blockIdx.x, by = blockIdx.y;
    const int tx = tid & 15, ty = tid >> 4;
    const int aRow = tid >> 1, aCol = (tid & 1) * 4;
    const int bRow = tid >> 5, bCol = (tid & 31) * 4;
    const float* Ap = A + (size_t)(by * 128 + aRow) * K + aCol;
    const float* Bp = B + (size_t)bRow * N + bx * 128 + bCol;

    float acc[8][8];
    #pragma unroll
    for (int i = 0; i < 8; i++)
        #pragma unroll
        for (int j = 0; j < 8; j++) acc[i][j] = 0.f;

    // prologue: fetch k-tile 0
    float4 a4 = *(const float4*)(Ap);
    float4 b4 = *(const float4*)(Bp);

    for (int k0 = 0; k0 < K; k0 += 8) {
        As[aCol + 0][aRow] = a4.x;
        As[aCol + 1][aRow] = a4.y;
        As[aCol + 2][aRow] = a4.z;
        As[aCol + 3][aRow] = a4.w;
        *(float4*)&Bs[bRow][bCol] = b4;
        __syncthreads();

        // prefetch next k-tile while computing this one
        if (k0 + 8 < K) {
            a4 = *(const float4*)(Ap + k0 + 8);
            b4 = *(const float4*)(Bp + (size_t)(k0 + 8) * N);
        }

        #pragma unroll
        for (int kk = 0; kk < 8; kk++) {
            float4 a0 = *(const float4*)&As[kk][ty * 8];
            float4 a1 = *(const float4*)&As[kk][ty * 8 + 4];
            float4 b0 = *(const float4*)&Bs[kk][tx * 8];
            float4 b1 = *(const float4*)&Bs[kk][tx * 8 + 4];
            float ar[8] = {a0.x, a0.y, a0.z, a0.w, a1.x, a1.y, a1.z, a1.w};
            float br[8] = {b0.x, b0.y, b0.z, b0.w, b1.x, b1.y, b1.z, b1.w};
            #pragma unroll
            for (int i = 0; i < 8; i++)
                #pragma unroll
                for (int j = 0; j < 8; j++)
                    acc[i][j] = fmaf(ar[i], br[j], acc[i][j]);
        }
        __syncthreads();
    }

    #pragma unroll
    for (int i = 0; i < 8; i++) {
        int row = by * 128 + ty * 8 + i;
        #pragma unroll
        for (int j = 0; j < 8; j++) {
            int col = bx * 128 + tx * 8 + j;
            size_t idx = (size_t)row * N + col;
            float v = acc[i][j] + bias[col];
            if (EPI == 0) {
                C[idx] = v;
            } else {
                float g = 1.f / (1.f + expf(-v));
                C[idx] = g * e1[idx] + (1.f - g) * e2[idx];
            }
        }
    }
}

// ----------------------------------------------------------------------------
// u = z @ A (complex): per engine, ur = zr@Ar - zi@Ai ; ui = zr@Ai + zi@Ar
// A_e is [S, R] row-major. Output g_ur/g_ui layout: [E][M_TOT][R].
// Block: 256 thr = 16 rows x 16 r-lanes. grid = (M_TOT/16, E)
// ----------------------------------------------------------------------------
__global__ __launch_bounds__(256)
void proj_u_kernel(const float* __restrict__ A_r, const float* __restrict__ A_i)
{
    __shared__ float sAr[256][R];
    __shared__ float sAi[256][R];
    const int e = blockIdx.y;
    const int row = blockIdx.x * 16 + (threadIdx.x >> 4);
    const int r = threadIdx.x & 15;
    const float* ArE = A_r + (size_t)e * S * R;
    const float* AiE = A_i + (size_t)e * S * R;
    float aur = 0.f, aui = 0.f;
    for (int k0 = 0; k0 < S; k0 += 256) {
        for (int i = threadIdx.x; i < 256 * R; i += 256) {
            int kk = i >> 4, rr = i & 15;
            sAr[kk][rr] = ArE[(size_t)(k0 + kk) * R + rr];
            sAi[kk][rr] = AiE[(size_t)(k0 + kk) * R + rr];
        }
        __syncthreads();
        const float* zrp = g_zr + (size_t)row * S + k0;
        const float* zip = g_zi + (size_t)row * S + k0;
        #pragma unroll 8
        for (int k = 0; k < 256; k++) {
            float zr = zrp[k], zi = zip[k];
            float ar = sAr[k][r], ai = sAi[k][r];
            aur = fmaf(zr, ar, aur);
            aur = fmaf(-zi, ai, aur);
            aui = fmaf(zr, ai, aui);
            aui = fmaf(zi, ar, aui);
        }
        __syncthreads();
    }
    size_t o = ((size_t)e * M_TOT + row) * R + r;
    g_ur[o] = aur;
    g_ui[o] = aui;
}

// ----------------------------------------------------------------------------
// Sequential complex diagonal recurrence. One warp per (e,b); lanes 0..15 = r.
// Writes features g_fr/g_fi [E][M_TOT][FDIM].
// ----------------------------------------------------------------------------
__global__ void recur_kernel(const float* __restrict__ lam_r,
                             const float* __restrict__ lam_i)
{
    const int eb = blockIdx.x;
    const int e = eb >> 2;     // / BSZ
    const int b = eb & 3;
    const int lane = threadIdx.x;
    if (lane >= R) return;

    const float lr = (1.f - ETA) * lam_r[e * R + lane];
    const float li = (1.f - ETA) * lam_i[e * R + lane];

    const float* urp = g_ur + ((size_t)e * M_TOT + (size_t)b * T) * R + lane;
    const float* uip = g_ui + ((size_t)e * M_TOT + (size_t)b * T) * R + lane;
    float* frp = g_fr + ((size_t)e * M_TOT + (size_t)b * T) * FDIM;
    float* fip = g_fi + ((size_t)e * M_TOT + (size_t)b * T) * FDIM;

    float hr = 0.f, hi = 0.f, acc = 0.f;
    const unsigned mask = 0xFFFFu;

    float u_r = urp[0];
    float u_i = uip[0];

    for (int t = 0; t < T; t++) {
        // prefetch next step's drive
        int tn = (t + 1 < T) ? (t + 1) : t;
        float nu_r = urp[(size_t)tn * R];
        float nu_i = uip[(size_t)tn * R];

        float nhr = lr * hr - li * hi + ETA * u_r;
        float nhi = lr * hi + li * hr + ETA * u_i;
        float m2 = nhr * nhr + nhi * nhi;

        float s = m2, mx = m2;
        #pragma unroll
        for (int off = 8; off >= 1; off >>= 1) {
            s += __shfl_xor_sync(mask, s, off, 16);
            mx = fmaxf(mx, __shfl_xor_sync(mask, mx, off, 16));
        }
        float m_mean = s * (1.f / 16.f);
        acc = 0.99f * acc + 0.01f * m_mean;
        float inv = rsqrtf(m_mean + EPS);
        float hnr = nhr * inv, hni = nhi * inv;

        float sr = hnr, si = hni;
        #pragma unroll
        for (int off = 8; off >= 1; off >>= 1) {
            sr += __shfl_xor_sync(mask, sr, off, 16);
            si += __shfl_xor_sync(mask, si, off, 16);
        }
        float mr = sr * (1.f / 16.f);
        float mi = si * (1.f / 16.f);

        float* fr_t = frp + (size_t)t * FDIM;
        float* fi_t = fip + (size_t)t * FDIM;
        fr_t[6 + lane]      = hnr;
        fr_t[6 + R + lane]  = hni;
        fi_t[6 + lane]      = hni;
        fi_t[6 + R + lane]  = -hnr;
        if (lane == 0) {
            fr_t[0] = mr;
            fr_t[1] = mi;
            fr_t[2] = sqrtf(m_mean + EPS);
            fr_t[3] = sqrtf(mx + EPS);
            fr_t[4] = acc;
            fr_t[5] = log1pf(acc);
            fi_t[0] = mi;
            fi_t[1] = -mr;
            fi_t[2] = 0.f; fi_t[3] = 0.f; fi_t[4] = 0.f; fi_t[5] = 0.f;
        }
        hr = nhr; hi = nhi;
        u_r = nu_r; u_i = nu_i;
    }
}

// ----------------------------------------------------------------------------
// Engine head: per engine, yr = fr@Wr - fi@Wi + br ; yi = fr@Wi + fi@Wr + bi
// K = FDIM = 38. Writes into g_YC: yr at col e*H+h, yi at col EH + e*H+h.
// Tile: 32 rows x 64 cols, 256 threads. grid = (H/64, M_TOT/32, E)
// ----------------------------------------------------------------------------
__global__ __launch_bounds__(256)
void engine_head_kernel(const float* __restrict__ eh_Wr,
                        const float* __restrict__ eh_Wi,
                        const float* __restrict__ eh_br,
                        const float* __restrict__ eh_bi)
{
    __shared__ float sFr[32][FDIM + 1];
    __shared__ float sFi[32][FDIM + 1];
    __shared__ float sWr[FDIM][64];
    __shared__ float sWi[FDIM][64];

    const int e = blockIdx.z;
    const int row0 = blockIdx.y * 32;
    const int col0 = blockIdx.x * 64;
    const int tid = threadIdx.x;

    for (int i = tid; i < 32 * FDIM; i += 256) {
        int rr = i / FDIM, kk = i % FDIM;
        size_t off = ((size_t)e * M_TOT + row0 + rr) * FDIM + kk;
        sFr[rr][kk] = g_fr[off];
        sFi[rr][kk] = g_fi[off];
    }
    for (int i = tid; i < FDIM * 64; i += 256) {
        int kk = i / 64, cc = i % 64;
        size_t off = ((size_t)e * FDIM + kk) * H + col0 + cc;
        sWr[kk][cc] = eh_Wr[off];
        sWi[kk][cc] = eh_Wi[off];
    }
    __syncthreads();

    const int c = tid & 63;
    const int rg = tid >> 6;   // 0..3

    float accR[8], accI[8];
    #pragma unroll
    for (int i = 0; i < 8; i++) { accR[i] = 0.f; accI[i] = 0.f; }

    for (int k = 0; k < FDIM; k++) {
        float wr = sWr[k][c], wi = sWi[k][c];
        #pragma unroll
        for (int i = 0; i < 8; i++) {
            float fr = sFr[rg + i * 4][k];
            float fi = sFi[rg + i * 4][k];
            accR[i] = fmaf(fr, wr, accR[i]);
            accR[i] = fmaf(-fi, wi, accR[i]);
            accI[i] = fmaf(fr, wi, accI[i]);
            accI[i] = fmaf(fi, wr, accI[i]);
        }
    }

    const float br = eh_br[e * H + col0 + c];
    const float bi = eh_bi[e * H + col0 + c];
    #pragma unroll
    for (int i = 0; i < 8; i++) {
        int row = row0 + rg + i * 4;
        g_YC[(size_t)row * K2 + e * H + col0 + c]      = accR[i] + br;
        g_YC[(size_t)row * K2 + EH + e * H + col0 + c] = accI[i] + bi;
    }
}

// ----------------------------------------------------------------------------
// Build stacked fusion weights: Wrst = [fu_Wr ; -fu_Wi], Wist = [fu_Wi ; fu_Wr]
// ----------------------------------------------------------------------------
__global__ void build_stacked_kernel(const float* __restrict__ fu_Wr,
                                     const float* __restrict__ fu_Wi)
{
    int idx = blockIdx.x * blockDim.x + threadIdx.x;
    if (idx >= EH * H) return;  // 4096*1024 per half
    g_Wrst[idx]                    = fu_Wr[idx];
    g_Wist[idx]                    = fu_Wi[idx];
    g_Wrst[(size_t)EH * H + idx]   = -fu_Wi[idx];
    g_Wist[(size_t)EH * H + idx]   = fu_Wr[idx];
}

// ----------------------------------------------------------------------------
// Concat: CC = [x | frf | fif | sqrt(frf^2+fif^2+EPS)]  -> [8192, 4096]
// ----------------------------------------------------------------------------
__global__ void concat_kernel(const float* __restrict__ x)
{
    int idx = blockIdx.x * blockDim.x + threadIdx.x;
    if (idx >= M_TOT * H) return;
    int row = idx / H, h = idx % H;
    float fr = g_frf[idx], fi = g_fif[idx];
    size_t base = (size_t)row * (4 * H);
    g_CC[base + h]           = x[idx];
    g_CC[base + H + h]       = fr;
    g_CC[base + 2 * H + h]   = fi;
    g_CC[base + 3 * H + h]   = sqrtf(fr * fr + fi * fi + EPS);
}

// ----------------------------------------------------------------------------
// Launch
// ----------------------------------------------------------------------------
extern "C" void kernel_launch(void* const* d_in, const int* in_sizes, int n_in,
                              void* d_out, int out_size)
{
    const float* x      = (const float*)d_in[0];
    const float* sig_Wr = (const float*)d_in[1];
    const float* sig_Wi = (const float*)d_in[2];
    const float* sig_br = (const float*)d_in[3];
    const float* sig_bi = (const float*)d_in[4];
    const float* A_r    = (const float*)d_in[5];
    const float* A_i    = (const float*)d_in[6];
    const float* lam_r  = (const float*)d_in[7];
    const float* lam_i  = (const float*)d_in[8];
    const float* eh_Wr  = (const float*)d_in[9];
    const float* eh_Wi  = (const float*)d_in[10];
    const float* eh_br  = (const float*)d_in[11];
    const float* eh_bi  = (const float*)d_in[12];
    const float* fu_Wr  = (const float*)d_in[13];
    const float* fu_Wi  = (const float*)d_in[14];
    const float* fu_br  = (const float*)d_in[15];
    const float* fu_bi  = (const float*)d_in[16];
    const float* g_W    = (const float*)d_in[17];
    const float* g_b    = (const float*)d_in[18];
    float* out = (float*)d_out;

    float *zr, *zi, *YC, *frf, *fif, *Wrst, *Wist, *CC;
    cudaGetSymbolAddress((void**)&zr,   g_zr);
    cudaGetSymbolAddress((void**)&zi,   g_zi);
    cudaGetSymbolAddress((void**)&YC,   g_YC);
    cudaGetSymbolAddress((void**)&frf,  g_frf);
    cudaGetSymbolAddress((void**)&fif,  g_fif);
    cudaGetSymbolAddress((void**)&Wrst, g_Wrst);
    cudaGetSymbolAddress((void**)&Wist, g_Wist);
    cudaGetSymbolAddress((void**)&CC,   g_CC);

    // Stage 0 (independent): stacked fusion weights
    build_stacked_kernel<<<(EH * H + 255) / 256, 256>>>(fu_Wr, fu_Wi);

    // Stage 1: signal projection zr/zi = x @ sig_W + b   [8192,1024]@[1024,512]
    sgemm_k<0><<<dim3(S / 128, M_TOT / 128), 256>>>(x, sig_Wr, zr, M_TOT, S, H, sig_br, nullptr, nullptr);
    sgemm_k<0><<<dim3(S / 128, M_TOT / 128), 256>>>(x, sig_Wi, zi, M_TOT, S, H, sig_bi, nullptr, nullptr);

    // Stage 2: complex drive u = z @ A per engine
    proj_u_kernel<<<dim3(M_TOT / 16, E), 256>>>(A_r, A_i);

    // Stage 3: sequential recurrence -> features
    recur_kernel<<<E * BSZ, 32>>>(lam_r, lam_i);

    // Stage 4: engine head -> YC = [yr_c | yi_c]
    engine_head_kernel<<<dim3(H / 64, M_TOT / 32, E), 256>>>(eh_Wr, eh_Wi, eh_br, eh_bi);

    // Stage 5: fusion GEMMs (complex via K-stacking)
    sgemm_k<0><<<dim3(H / 128, M_TOT / 128), 256>>>(YC, Wrst, frf, M_TOT, H, K2, fu_br, nullptr, nullptr);
    sgemm_k<0><<<dim3(H / 128, M_TOT / 128), 256>>>(YC, Wist, fif, M_TOT, H, K2, fu_bi, nullptr, nullptr);

    // Stage 6: concat for gate
    concat_kernel<<<(M_TOT * H + 255) / 256, 256>>>(x);

    // Stage 7: gate GEMM + fused sigmoid/blend epilogue -> out
    sgemm_k<1><<<dim3(H / 128, M_TOT / 128), 256>>>(CC, g_W, out, M_TOT, H, 4 * H, g_b, frf, x);
}

// round 3
// speedup vs baseline: 3.3758x; 3.3758x over previous
#include <cuda_runtime.h>
#include <math.h>
#include <stdint.h>

#define BSZ 4
#define T 2048
#define H 1024
#define S 512
#define R 16
#define E 4
#define FDIM 38             // 6 + 2*R
#define M_TOT (BSZ*T)       // 8192
#define GDIM (E*2*FDIM)     // 304   feature width [fr|fi] per engine
#define CCW (H + GDIM + H)  // 2352  gate concat width
#define ETA 0.1f
#define EPS 1e-6f

// ----------------------------------------------------------------------------
// Scratch (static device globals)
// ----------------------------------------------------------------------------
__device__ float g_Bc[H * 128];                 // combined input proj [1024,128]
__device__ float g_ubias[128];
__device__ float g_U[M_TOT * 128];              // drives [m, e*32 + (0..15 ur | 16..31 ui)]
__device__ float g_G[(size_t)M_TOT * GDIM];     // features [m, e*76 + (fr38|fi38)]
__device__ float g_WF[(size_t)GDIM * 2048];     // collapsed head+fusion weights
__device__ float g_CB[2048];                    // [cr | ci] bias for FRF
__device__ float g_FRF[(size_t)M_TOT * 2048];   // [frf | fif]
__device__ float g_Wg2[(size_t)CCW * H];        // gate weights [gW1; GcG; gW4]
__device__ float g_cgate[H];
__device__ float g_CC2[(size_t)M_TOT * CCW];    // [x | G | mag]

// ----------------------------------------------------------------------------
// Generic SIMT SGEMM: C[M,N] = A[M,K] @ B[K,N] + bias[N], 128x128x8 tile,
// 256 threads, 8x8/thread, register-prefetch double buffering.
// EPI==1: g = sigmoid(v); C = g*e1 + (1-g)*e2 (e1/e2 with own row strides)
// ----------------------------------------------------------------------------
template<int EPI>
__global__ __launch_bounds__(256)
void sgemm_k(const float* __restrict__ A, const float* __restrict__ B,
             float* __restrict__ C, int M, int N, int K,
             const float* __restrict__ bias,
             const float* __restrict__ e1, int ld1,
             const float* __restrict__ e2, int ld2)
{
    __shared__ float As[8][128];
    __shared__ float Bs[8][128];
    const int tid = threadIdx.x;
    const int bx = blockIdx.x, by = blockIdx.y;
    const int tx = tid & 15, ty = tid >> 4;
    const int aRow = tid >> 1, aCol = (tid & 1) * 4;
    const int bRow = tid >> 5, bCol = (tid & 31) * 4;
    const float* Ap = A + (size_t)(by * 128 + aRow) * K + aCol;
    const float* Bp = B + (size_t)bRow * N + bx * 128 + bCol;

    float acc[8][8];
    #pragma unroll
    for (int i = 0; i < 8; i++)
        #pragma unroll
        for (int j = 0; j < 8; j++) acc[i][j] = 0.f;

    float4 a4 = *(const float4*)(Ap);
    float4 b4 = *(const float4*)(Bp);

    for (int k0 = 0; k0 < K; k0 += 8) {
        As[aCol + 0][aRow] = a4.x;
        As[aCol + 1][aRow] = a4.y;
        As[aCol + 2][aRow] = a4.z;
        As[aCol + 3][aRow] = a4.w;
        *(float4*)&Bs[bRow][bCol] = b4;
        __syncthreads();

        if (k0 + 8 < K) {
            a4 = *(const float4*)(Ap + k0 + 8);
            b4 = *(const float4*)(Bp + (size_t)(k0 + 8) * N);
        }

        #pragma unroll
        for (int kk = 0; kk < 8; kk++) {
            float4 a0 = *(const float4*)&As[kk][ty * 8];
            float4 a1 = *(const float4*)&As[kk][ty * 8 + 4];
            float4 b0 = *(const float4*)&Bs[kk][tx * 8];
            float4 b1 = *(const float4*)&Bs[kk][tx * 8 + 4];
            float ar[8] = {a0.x, a0.y, a0.z, a0.w, a1.x, a1.y, a1.z, a1.w};
            float br[8] = {b0.x, b0.y, b0.z, b0.w, b1.x, b1.y, b1.z, b1.w};
            #pragma unroll
            for (int i = 0; i < 8; i++)
                #pragma unroll
                for (int j = 0; j < 8; j++)
                    acc[i][j] = fmaf(ar[i], br[j], acc[i][j]);
        }
        __syncthreads();
    }

    #pragma unroll
    for (int i = 0; i < 8; i++) {
        int row = by * 128 + ty * 8 + i;
        #pragma unroll
        for (int j = 0; j < 8; j++) {
            int col = bx * 128 + tx * 8 + j;
            float v = acc[i][j] + bias[col];
            if (EPI == 0) {
                C[(size_t)row * N + col] = v;
            } else {
                float g = 1.f / (1.f + expf(-v));
                C[(size_t)row * N + col] =
                    g * e1[(size_t)row * ld1 + col] + (1.f - g) * e2[(size_t)row * ld2 + col];
            }
        }
    }
}

// ----------------------------------------------------------------------------
// Precompute Bc[h, e*32 + r(ur) / 16+r(ui)] = sig_W(h,:) composed with A[e](:,r)
// grid (64, E), block 256: 16 h-rows x 16 r per block.
// ----------------------------------------------------------------------------
__global__ __launch_bounds__(256)
void combine_proj_kernel(const float* __restrict__ sig_Wr, const float* __restrict__ sig_Wi,
                         const float* __restrict__ A_r, const float* __restrict__ A_i)
{
    __shared__ float sAr[128][16], sAi[128][16];
    __shared__ float sWr[16][128], sWi[16][128];
    const int e = blockIdx.y;
    const int h0 = blockIdx.x * 16;
    const int tid = threadIdx.x;
    const int h_loc = tid >> 4, r = tid & 15;
    float aur = 0.f, aui = 0.f;

    for (int s0 = 0; s0 < S; s0 += 128) {
        for (int i = tid; i < 128 * 16; i += 256) {
            int s = i >> 4, rr = i & 15;
            sAr[s][rr] = A_r[((size_t)e * S + s0 + s) * R + rr];
            sAi[s][rr] = A_i[((size_t)e * S + s0 + s) * R + rr];
        }
        for (int i = tid; i < 16 * 128; i += 256) {
            int hh = i >> 7, ss = i & 127;
            sWr[hh][ss] = sig_Wr[(size_t)(h0 + hh) * S + s0 + ss];
            sWi[hh][ss] = sig_Wi[(size_t)(h0 + hh) * S + s0 + ss];
        }
        __syncthreads();
        #pragma unroll 4
        for (int s = 0; s < 128; s++) {
            float wr = sWr[h_loc][s], wi = sWi[h_loc][s];
            float ar = sAr[s][r],     ai = sAi[s][r];
            aur = fmaf(wr, ar, aur);
            aur = fmaf(-wi, ai, aur);
            aui = fmaf(wr, ai, aui);
            aui = fmaf(wi, ar, aui);
        }
        __syncthreads();
    }
    g_Bc[(size_t)(h0 + h_loc) * 128 + e * 32 + r]      = aur;
    g_Bc[(size_t)(h0 + h_loc) * 128 + e * 32 + 16 + r] = aui;
}

// u-bias from sig_br/sig_bi through A. 1 block, 128 threads.
__global__ void ubias_kernel(const float* __restrict__ sig_br, const float* __restrict__ sig_bi,
                             const float* __restrict__ A_r, const float* __restrict__ A_i)
{
    int j = threadIdx.x;             // e*32 + half*16 + r
    int e = j >> 5, half = (j >> 4) & 1, r = j & 15;
    float acc = 0.f;
    for (int s = 0; s < S; s++) {
        float ar = A_r[((size_t)e * S + s) * R + r];
        float ai = A_i[((size_t)e * S + s) * R + r];
        float br = sig_br[s], bi = sig_bi[s];
        acc += half ? (br * ai + bi * ar) : (br * ar - bi * ai);
    }
    g_ubias[j] = acc;
}

// ----------------------------------------------------------------------------
// Collapsed head+fusion weights WF [304, 2048].
// Per engine: P=ehWr·fuWr, Q=ehWi·fuWi, U=ehWr·fuWi, V=ehWi·fuWr  ([38,1024] each)
// WF[e*76+f,     0:1024]=P-Q   WF[e*76+f,     1024:]=U+V
// WF[e*76+38+f,  0:1024]=-(U+V) WF[e*76+38+f, 1024:]=P-Q
// grid (32, E), block 256: 38 rows x 32 cols per block.
// ----------------------------------------------------------------------------
__global__ __launch_bounds__(256)
void pquv_kernel(const float* __restrict__ eh_Wr, const float* __restrict__ eh_Wi,
                 const float* __restrict__ fu_Wr, const float* __restrict__ fu_Wi)
{
    __shared__ float sAr[40][32], sAi[40][32];
    __shared__ float sBr[32][33], sBi[32][33];
    const int e = blockIdx.y;
    const int col0 = blockIdx.x * 32;
    const int tid = threadIdx.x;
    const int c = tid & 31, rg = tid >> 5;

    float P[5] = {0,0,0,0,0}, Q[5] = {0,0,0,0,0}, Uu[5] = {0,0,0,0,0}, V[5] = {0,0,0,0,0};

    for (int k0 = 0; k0 < H; k0 += 32) {
        for (int i = tid; i < FDIM * 32; i += 256) {
            int f = i >> 5, k = i & 31;
            sAr[f][k] = eh_Wr[((size_t)e * FDIM + f) * H + k0 + k];
            sAi[f][k] = eh_Wi[((size_t)e * FDIM + f) * H + k0 + k];
        }
        for (int i = tid; i < 32 * 32; i += 256) {
            int k = i >> 5, cc = i & 31;
            sBr[k][cc] = fu_Wr[((size_t)e * H + k0 + k) * H + col0 + cc];
            sBi[k][cc] = fu_Wi[((size_t)e * H + k0 + k) * H + col0 + cc];
        }
        __syncthreads();
        #pragma unroll 4
        for (int k = 0; k < 32; k++) {
            float br = sBr[k][c], bi = sBi[k][c];
            #pragma unroll
            for (int ii = 0; ii < 5; ii++) {
                int row = rg * 5 + ii;
                float ar = sAr[row][k], ai = sAi[row][k];
                P[ii]  = fmaf(ar, br, P[ii]);
                Q[ii]  = fmaf(ai, bi, Q[ii]);
                Uu[ii] = fmaf(ar, bi, Uu[ii]);
                V[ii]  = fmaf(ai, br, V[ii]);
            }
        }
        __syncthreads();
    }
    #pragma unroll
    for (int ii = 0; ii < 5; ii++) {
        int row = rg * 5 + ii;
        if (row < FDIM) {
            float wc1 = P[ii] - Q[ii];
            float wc2 = Uu[ii] + V[ii];
            size_t b1 = (size_t)(e * 76 + row) * 2048;
            size_t b2 = (size_t)(e * 76 + 38 + row) * 2048;
            int cg = col0 + c;
            g_WF[b1 + cg]        = wc1;
            g_WF[b1 + 1024 + cg] = wc2;
            g_WF[b2 + cg]        = -wc2;
            g_WF[b2 + 1024 + cg] = wc1;
        }
    }
}

// cr/ci: bias constants from eh_b through fu_W, plus fu_b. grid 8 x 128.
__global__ void crci_kernel(const float* __restrict__ eh_br, const float* __restrict__ eh_bi,
                            const float* __restrict__ fu_Wr, const float* __restrict__ fu_Wi,
                            const float* __restrict__ fu_br, const float* __restrict__ fu_bi)
{
    int o = blockIdx.x * 128 + threadIdx.x;
    float cr = fu_br[o], ci = fu_bi[o];
    for (int eh = 0; eh < E * H; eh++) {
        float br = eh_br[eh], bi = eh_bi[eh];
        float wr = fu_Wr[(size_t)eh * H + o], wi = fu_Wi[(size_t)eh * H + o];
        cr += br * wr - bi * wi;
        ci += br * wi + bi * wr;
    }
    g_CB[o] = cr;
    g_CB[1024 + o] = ci;
}

// gate bias: g_b + cr@gW2 + ci@gW3. grid 8 x 128. (after crci)
__global__ void cgate_kernel(const float* __restrict__ g_W, const float* __restrict__ g_b)
{
    int o = blockIdx.x * 128 + threadIdx.x;
    float acc = g_b[o];
    for (int h = 0; h < H; h++) {
        acc += g_CB[h] * g_W[(size_t)(H + h) * H + o];
        acc += g_CB[1024 + h] * g_W[(size_t)(2 * H + h) * H + o];
    }
    g_cgate[o] = acc;
}

// Wg2 rows 0:1024 <- gW1, rows 1328:2352 <- gW4.
__global__ void wg2copy_kernel(const float* __restrict__ g_W)
{
    int idx = blockIdx.x * 256 + threadIdx.x;
    if (idx >= H * H) return;
    g_Wg2[idx] = g_W[idx];
    g_Wg2[(size_t)(H + GDIM) * H + idx] = g_W[(size_t)3 * H * H + idx];
}

// GcG = WF @ g_W[H:3H, :]  -> Wg2 rows 1024:1328.  grid (32, 8), block 256.
__global__ __launch_bounds__(256)
void gcg_kernel(const float* __restrict__ g_W)
{
    __shared__ float sA[40][32];
    __shared__ float sB[32][33];
    const int p0 = blockIdx.y * 38;
    const int col0 = blockIdx.x * 32;
    const int tid = threadIdx.x;
    const int c = tid & 31, rg = tid >> 5;
    float acc[5] = {0,0,0,0,0};

    for (int k0 = 0; k0 < 2048; k0 += 32) {
        for (int i = tid; i < 38 * 32; i += 256) {
            int pp = i >> 5, k = i & 31;
            sA[pp][k] = g_WF[(size_t)(p0 + pp) * 2048 + k0 + k];
        }
        for (int i = tid; i < 32 * 32; i += 256) {
            int k = i >> 5, cc = i & 31;
            sB[k][cc] = g_W[(size_t)(H + k0 + k) * H + col0 + cc];
        }
        __syncthreads();
        #pragma unroll 4
        for (int k = 0; k < 32; k++) {
            float b = sB[k][c];
            #pragma unroll
            for (int ii = 0; ii < 5; ii++)
                acc[ii] = fmaf(sA[rg * 5 + ii][k], b, acc[ii]);
        }
        __syncthreads();
    }
    #pragma unroll
    for (int ii = 0; ii < 5; ii++) {
        int row = rg * 5 + ii;
        if (row < 38)
            g_Wg2[(size_t)(H + p0 + row) * H + col0 + c] = acc[ii];
    }
}

// ----------------------------------------------------------------------------
// Sequential recurrence. One warp per (e,b); lanes 0..15 = r. Reads g_U,
// writes features G [m, e*76 + (fr:0..37 | fi:38..75)].
// ----------------------------------------------------------------------------
__global__ void recur_kernel(const float* __restrict__ lam_r,
                             const float* __restrict__ lam_i)
{
    const int eb = blockIdx.x;
    const int e = eb >> 2;
    const int b = eb & 3;
    const int lane = threadIdx.x;
    if (lane >= R) return;

    const float lr = (1.f - ETA) * lam_r[e * R + lane];
    const float li = (1.f - ETA) * lam_i[e * R + lane];

    const float* up = g_U + (size_t)b * T * 128 + e * 32 + lane;
    float* gp = g_G + (size_t)b * T * GDIM + e * 76;

    float hr = 0.f, hi = 0.f, acc = 0.f;
    const unsigned mask = 0xFFFFu;

    float u_r = up[0];
    float u_i = up[16];

    for (int t = 0; t < T; t++) {
        int tn = (t + 1 < T) ? (t + 1) : t;
        float nu_r = up[(size_t)tn * 128];
        float nu_i = up[(size_t)tn * 128 + 16];

        float nhr = lr * hr - li * hi + ETA * u_r;
        float nhi = lr * hi + li * hr + ETA * u_i;
        float m2 = nhr * nhr + nhi * nhi;

        float s = m2, mx = m2;
        #pragma unroll
        for (int off = 8; off >= 1; off >>= 1) {
            s += __shfl_xor_sync(mask, s, off, 16);
            mx = fmaxf(mx, __shfl_xor_sync(mask, mx, off, 16));
        }
        float m_mean = s * (1.f / 16.f);
        acc = 0.99f * acc + 0.01f * m_mean;
        float inv = rsqrtf(m_mean + EPS);
        float hnr = nhr * inv, hni = nhi * inv;

        float sr = hnr, si = hni;
        #pragma unroll
        for (int off = 8; off >= 1; off >>= 1) {
            sr += __shfl_xor_sync(mask, sr, off, 16);
            si += __shfl_xor_sync(mask, si, off, 16);
        }
        float mr = sr * (1.f / 16.f);
        float mi = si * (1.f / 16.f);

        float* g_t = gp + (size_t)t * GDIM;
        g_t[6 + lane]           = hnr;   // fr: hnr
        g_t[6 + R + lane]       = hni;   // fr: hni
        g_t[38 + 6 + lane]      = hni;   // fi: hni
        g_t[38 + 6 + R + lane]  = -hnr;  // fi: -hnr
        if (lane == 0) {
            g_t[0] = mr;
            g_t[1] = mi;
            g_t[2] = sqrtf(m_mean + EPS);
            g_t[3] = sqrtf(mx + EPS);
            g_t[4] = acc;
            g_t[5] = log1pf(acc);
            g_t[38 + 0] = mi;
            g_t[38 + 1] = -mr;
            g_t[38 + 2] = 0.f; g_t[38 + 3] = 0.f; g_t[38 + 4] = 0.f; g_t[38 + 5] = 0.f;
        }
        hr = nhr; hi = nhi;
        u_r = nu_r; u_i = nu_i;
    }
}

// ----------------------------------------------------------------------------
// Gate concat CC2 = [x | G | mag]. grid M_TOT, block 256.
// ----------------------------------------------------------------------------
__global__ void concat2_kernel(const float* __restrict__ x)
{
    const int row = blockIdx.x;
    float* dst = g_CC2 + (size_t)row * CCW;
    const float* xr = x + (size_t)row * H;
    const float* gr = g_G + (size_t)row * GDIM;
    const float* fr = g_FRF + (size_t)row * 2048;
    for (int c = threadIdx.x; c < CCW; c += 256) {
        float v;
        if (c < H) v = xr[c];
        else if (c < H + GDIM) v = gr[c - H];
        else {
            int h = c - H - GDIM;
            float a = fr[h], b = fr[1024 + h];
            v = sqrtf(a * a + b * b + EPS);
        }
        dst[c] = v;
    }
}

// ----------------------------------------------------------------------------
// Launch
// ----------------------------------------------------------------------------
extern "C" void kernel_launch(void* const* d_in, const int* in_sizes, int n_in,
                              void* d_out, int out_size)
{
    const float* x      = (const float*)d_in[0];
    const float* sig_Wr = (const float*)d_in[1];
    const float* sig_Wi = (const float*)d_in[2];
    const float* sig_br = (const float*)d_in[3];
    const float* sig_bi = (const float*)d_in[4];
    const float* A_r    = (const float*)d_in[5];
    const float* A_i    = (const float*)d_in[6];
    const float* lam_r  = (const float*)d_in[7];
    const float* lam_i  = (const float*)d_in[8];
    const float* eh_Wr  = (const float*)d_in[9];
    const float* eh_Wi  = (const float*)d_in[10];
    const float* eh_br  = (const float*)d_in[11];
    const float* eh_bi  = (const float*)d_in[12];
    const float* fu_Wr  = (const float*)d_in[13];
    const float* fu_Wi  = (const float*)d_in[14];
    const float* fu_br  = (const float*)d_in[15];
    const float* fu_bi  = (const float*)d_in[16];
    const float* gW     = (const float*)d_in[17];
    const float* gb     = (const float*)d_in[18];
    float* out = (float*)d_out;

    float *Bc, *ubias, *U, *G, *WF, *CB, *FRF, *Wg2, *cgate, *CC2;
    cudaGetSymbolAddress((void**)&Bc,    g_Bc);
    cudaGetSymbolAddress((void**)&ubias, g_ubias);
    cudaGetSymbolAddress((void**)&U,     g_U);
    cudaGetSymbolAddress((void**)&G,     g_G);
    cudaGetSymbolAddress((void**)&WF,    g_WF);
    cudaGetSymbolAddress((void**)&CB,    g_CB);
    cudaGetSymbolAddress((void**)&FRF,   g_FRF);
    cudaGetSymbolAddress((void**)&Wg2,   g_Wg2);
    cudaGetSymbolAddress((void**)&cgate, g_cgate);
    cudaGetSymbolAddress((void**)&CC2,   g_CC2);

    // --- precompute (weight composition) ---
    combine_proj_kernel<<<dim3(64, E), 256>>>(sig_Wr, sig_Wi, A_r, A_i);
    ubias_kernel<<<1, 128>>>(sig_br, sig_bi, A_r, A_i);
    pquv_kernel<<<dim3(32, E), 256>>>(eh_Wr, eh_Wi, fu_Wr, fu_Wi);
    crci_kernel<<<8, 128>>>(eh_br, eh_bi, fu_Wr, fu_Wi, fu_br, fu_bi);
    wg2copy_kernel<<<(H * H + 255) / 256, 256>>>(gW);
    gcg_kernel<<<dim3(32, 8), 256>>>(gW);
    cgate_kernel<<<8, 128>>>(gW, gb);

    // --- main path ---
    // U = x @ Bc + ubias         [8192,1024]@[1024,128]
    sgemm_k<0><<<dim3(1, M_TOT / 128), 256>>>(x, Bc, U, M_TOT, 128, H, ubias,
                                              nullptr, 0, nullptr, 0);
    // recurrence -> G
    recur_kernel<<<E * BSZ, 32>>>(lam_r, lam_i);
    // FRF = G @ WF + [cr|ci]     [8192,304]@[304,2048]
    sgemm_k<0><<<dim3(2048 / 128, M_TOT / 128), 256>>>(G, WF, FRF, M_TOT, 2048, GDIM, CB,
                                                       nullptr, 0, nullptr, 0);
    // CC2 = [x | G | mag]
    concat2_kernel<<<M_TOT, 256>>>(x);
    // gate: v = CC2 @ Wg2 + cgate ; out = sig(v)*frf + (1-sig(v))*x
    sgemm_k<1><<<dim3(H / 128, M_TOT / 128), 256>>>(CC2, Wg2, out, M_TOT, H, CCW, cgate,
                                                    FRF, 2048, x, H);
}

// round 5
// speedup vs baseline: 3.9489x; 1.1698x over previous
#include <cuda_runtime.h>
#include <math.h>
#include <stdint.h>

#define BSZ 4
#define T 2048
#define H 1024
#define S 512
#define R 16
#define E 4
#define FDIM 38             // 6 + 2*R
#define M_TOT (BSZ*T)       // 8192
#define GDIM (E*2*FDIM)     // 304   feature width [fr|fi] per engine
#define CCW (H + GDIM + H)  // 2352  gate concat width
#define ETA 0.1f
#define EPS 1e-6f

// ----------------------------------------------------------------------------
// Scratch (static device globals)
// ----------------------------------------------------------------------------
__device__ float g_Bc[H * 128];                 // combined input proj [1024,128]
__device__ float g_ubias[128];
__device__ float g_U[M_TOT * 128];              // drives [m, e*32 + (0..15 ur | 16..31 ui)]
__device__ float g_G[(size_t)M_TOT * GDIM];     // features [m, e*76 + (fr38|fi38)]
__device__ float g_WF[(size_t)GDIM * 2048];     // collapsed head+fusion weights
__device__ float g_CB[2048];                    // [cr | ci] bias for FRF
__device__ float g_CBpart[32][2048];            // crci partials
__device__ float g_cgpart[8][1024];             // cgate partials
__device__ float g_FRF[(size_t)M_TOT * 2048];   // [frf | fif]
__device__ float g_Wg2[(size_t)CCW * H];        // gate weights [gW1; GcG; gW4]
__device__ float g_cgate[H];
__device__ float g_CC2[(size_t)M_TOT * CCW];    // [x | G | mag]

// ----------------------------------------------------------------------------
// Generic SIMT SGEMM: C[M,N] = A[M,K] @ B[K,N] + bias[N], 128x128x8 tile,
// 256 threads, 8x8/thread, register-prefetch double buffering.
// EPI==1: g = sigmoid(v); C = g*e1 + (1-g)*e2 (e1/e2 with own row strides)
// ----------------------------------------------------------------------------
template<int EPI>
__global__ __launch_bounds__(256)
void sgemm_k(const float* __restrict__ A, const float* __restrict__ B,
             float* __restrict__ C, int M, int N, int K,
             const float* __restrict__ bias,
             const float* __restrict__ e1, int ld1,
             const float* __restrict__ e2, int ld2)
{
    __shared__ float As[8][128];
    __shared__ float Bs[8][128];
    const int tid = threadIdx.x;
    const int bx = blockIdx.x, by = blockIdx.y;
    const int tx = tid & 15, ty = tid >> 4;
    const int aRow = tid >> 1, aCol = (tid & 1) * 4;
    const int bRow = tid >> 5, bCol = (tid & 31) * 4;
    const float* Ap = A + (size_t)(by * 128 + aRow) * K + aCol;
    const float* Bp = B + (size_t)bRow * N + bx * 128 + bCol;

    float acc[8][8];
    #pragma unroll
    for (int i = 0; i < 8; i++)
        #pragma unroll
        for (int j = 0; j < 8; j++) acc[i][j] = 0.f;

    float4 a4 = *(const float4*)(Ap);
    float4 b4 = *(const float4*)(Bp);

    for (int k0 = 0; k0 < K; k0 += 8) {
        As[aCol + 0][aRow] = a4.x;
        As[aCol + 1][aRow] = a4.y;
        As[aCol + 2][aRow] = a4.z;
        As[aCol + 3][aRow] = a4.w;
        *(float4*)&Bs[bRow][bCol] = b4;
        __syncthreads();

        if (k0 + 8 < K) {
            a4 = *(const float4*)(Ap + k0 + 8);
            b4 = *(const float4*)(Bp + (size_t)(k0 + 8) * N);
        }

        #pragma unroll
        for (int kk = 0; kk < 8; kk++) {
            float4 a0 = *(const float4*)&As[kk][ty * 8];
            float4 a1 = *(const float4*)&As[kk][ty * 8 + 4];
            float4 b0 = *(const float4*)&Bs[kk][tx * 8];
            float4 b1 = *(const float4*)&Bs[kk][tx * 8 + 4];
            float ar[8] = {a0.x, a0.y, a0.z, a0.w, a1.x, a1.y, a1.z, a1.w};
            float br[8] = {b0.x, b0.y, b0.z, b0.w, b1.x, b1.y, b1.z, b1.w};
            #pragma unroll
            for (int i = 0; i < 8; i++)
                #pragma unroll
                for (int j = 0; j < 8; j++)
                    acc[i][j] = fmaf(ar[i], br[j], acc[i][j]);
        }
        __syncthreads();
    }

    #pragma unroll
    for (int i = 0; i < 8; i++) {
        int row = by * 128 + ty * 8 + i;
        #pragma unroll
        for (int j = 0; j < 8; j++) {
            int col = bx * 128 + tx * 8 + j;
            float v = acc[i][j] + bias[col];
            if (EPI == 0) {
                C[(size_t)row * N + col] = v;
            } else {
                float g = 1.f / (1.f + expf(-v));
                C[(size_t)row * N + col] =
                    g * e1[(size_t)row * ld1 + col] + (1.f - g) * e2[(size_t)row * ld2 + col];
            }
        }
    }
}

// ----------------------------------------------------------------------------
// Precompute Bc[h, e*32 + r(ur) / 16+r(ui)] = sig_W(h,:) composed with A[e](:,r)
// ----------------------------------------------------------------------------
__global__ __launch_bounds__(256)
void combine_proj_kernel(const float* __restrict__ sig_Wr, const float* __restrict__ sig_Wi,
                         const float* __restrict__ A_r, const float* __restrict__ A_i)
{
    __shared__ float sAr[128][16], sAi[128][16];
    __shared__ float sWr[16][128], sWi[16][128];
    const int e = blockIdx.y;
    const int h0 = blockIdx.x * 16;
    const int tid = threadIdx.x;
    const int h_loc = tid >> 4, r = tid & 15;
    float aur = 0.f, aui = 0.f;

    for (int s0 = 0; s0 < S; s0 += 128) {
        for (int i = tid; i < 128 * 16; i += 256) {
            int s = i >> 4, rr = i & 15;
            sAr[s][rr] = A_r[((size_t)e * S + s0 + s) * R + rr];
            sAi[s][rr] = A_i[((size_t)e * S + s0 + s) * R + rr];
        }
        for (int i = tid; i < 16 * 128; i += 256) {
            int hh = i >> 7, ss = i & 127;
            sWr[hh][ss] = sig_Wr[(size_t)(h0 + hh) * S + s0 + ss];
            sWi[hh][ss] = sig_Wi[(size_t)(h0 + hh) * S + s0 + ss];
        }
        __syncthreads();
        #pragma unroll 4
        for (int s = 0; s < 128; s++) {
            float wr = sWr[h_loc][s], wi = sWi[h_loc][s];
            float ar = sAr[s][r],     ai = sAi[s][r];
            aur = fmaf(wr, ar, aur);
            aur = fmaf(-wi, ai, aur);
            aui = fmaf(wr, ai, aui);
            aui = fmaf(wi, ar, aui);
        }
        __syncthreads();
    }
    g_Bc[(size_t)(h0 + h_loc) * 128 + e * 32 + r]      = aur;
    g_Bc[(size_t)(h0 + h_loc) * 128 + e * 32 + 16 + r] = aui;
}

// u-bias from sig_br/sig_bi through A. 1 block, 128 threads.
__global__ void ubias_kernel(const float* __restrict__ sig_br, const float* __restrict__ sig_bi,
                             const float* __restrict__ A_r, const float* __restrict__ A_i)
{
    int j = threadIdx.x;             // e*32 + half*16 + r
    int e = j >> 5, half = (j >> 4) & 1, r = j & 15;
    float acc = 0.f;
    for (int s = 0; s < S; s++) {
        float ar = A_r[((size_t)e * S + s) * R + r];
        float ai = A_i[((size_t)e * S + s) * R + r];
        float br = sig_br[s], bi = sig_bi[s];
        acc += half ? (br * ai + bi * ar) : (br * ar - bi * ai);
    }
    g_ubias[j] = acc;
}

// ----------------------------------------------------------------------------
// Collapsed head+fusion weights WF [304, 2048].
// ----------------------------------------------------------------------------
__global__ __launch_bounds__(256)
void pquv_kernel(const float* __restrict__ eh_Wr, const float* __restrict__ eh_Wi,
                 const float* __restrict__ fu_Wr, const float* __restrict__ fu_Wi)
{
    __shared__ float sAr[40][32], sAi[40][32];
    __shared__ float sBr[32][33], sBi[32][33];
    const int e = blockIdx.y;
    const int col0 = blockIdx.x * 32;
    const int tid = threadIdx.x;
    const int c = tid & 31, rg = tid >> 5;

    float P[5] = {0,0,0,0,0}, Q[5] = {0,0,0,0,0}, Uu[5] = {0,0,0,0,0}, V[5] = {0,0,0,0,0};

    for (int k0 = 0; k0 < H; k0 += 32) {
        for (int i = tid; i < FDIM * 32; i += 256) {
            int f = i >> 5, k = i & 31;
            sAr[f][k] = eh_Wr[((size_t)e * FDIM + f) * H + k0 + k];
            sAi[f][k] = eh_Wi[((size_t)e * FDIM + f) * H + k0 + k];
        }
        for (int i = tid; i < 32 * 32; i += 256) {
            int k = i >> 5, cc = i & 31;
            sBr[k][cc] = fu_Wr[((size_t)e * H + k0 + k) * H + col0 + cc];
            sBi[k][cc] = fu_Wi[((size_t)e * H + k0 + k) * H + col0 + cc];
        }
        __syncthreads();
        #pragma unroll 4
        for (int k = 0; k < 32; k++) {
            float br = sBr[k][c], bi = sBi[k][c];
            #pragma unroll
            for (int ii = 0; ii < 5; ii++) {
                int row = rg * 5 + ii;
                float ar = sAr[row][k], ai = sAi[row][k];
                P[ii]  = fmaf(ar, br, P[ii]);
                Q[ii]  = fmaf(ai, bi, Q[ii]);
                Uu[ii] = fmaf(ar, bi, Uu[ii]);
                V[ii]  = fmaf(ai, br, V[ii]);
            }
        }
        __syncthreads();
    }
    #pragma unroll
    for (int ii = 0; ii < 5; ii++) {
        int row = rg * 5 + ii;
        if (row < FDIM) {
            float wc1 = P[ii] - Q[ii];
            float wc2 = Uu[ii] + V[ii];
            size_t b1 = (size_t)(e * 76 + row) * 2048;
            size_t b2 = (size_t)(e * 76 + 38 + row) * 2048;
            int cg = col0 + c;
            g_WF[b1 + cg]        = wc1;
            g_WF[b1 + 1024 + cg] = wc2;
            g_WF[b2 + cg]        = -wc2;
            g_WF[b2 + 1024 + cg] = wc1;
        }
    }
}

// ----------------------------------------------------------------------------
// crci, parallelized: partial sums over eh chunks, deterministic reduce.
// part: grid (8, 32), block 128. o = bx*128+tid in [0,1024); eh chunk = by*128.
// ----------------------------------------------------------------------------
__global__ void crci_part_kernel(const float* __restrict__ eh_br, const float* __restrict__ eh_bi,
                                 const float* __restrict__ fu_Wr, const float* __restrict__ fu_Wi)
{
    const int o = blockIdx.x * 128 + threadIdx.x;
    const int eh0 = blockIdx.y * 128;
    float cr = 0.f, ci = 0.f;
    #pragma unroll 4
    for (int k = 0; k < 128; k++) {
        int eh = eh0 + k;
        float br = eh_br[eh], bi = eh_bi[eh];
        float wr = fu_Wr[(size_t)eh * H + o], wi = fu_Wi[(size_t)eh * H + o];
        cr = fmaf(br, wr, cr); cr = fmaf(-bi, wi, cr);
        ci = fmaf(br, wi, ci); ci = fmaf(bi, wr, ci);
    }
    g_CBpart[blockIdx.y][o]        = cr;
    g_CBpart[blockIdx.y][1024 + o] = ci;
}

__global__ void crci_reduce_kernel(const float* __restrict__ fu_br, const float* __restrict__ fu_bi)
{
    int o = blockIdx.x * 256 + threadIdx.x;   // 0..2047
    float acc = (o < 1024) ? fu_br[o] : fu_bi[o - 1024];
    #pragma unroll
    for (int j = 0; j < 32; j++) acc += g_CBpart[j][o];
    g_CB[o] = acc;
}

// ----------------------------------------------------------------------------
// cgate, parallelized: partial sums over h chunks. grid (8, 8), block 128.
// ----------------------------------------------------------------------------
__global__ void cgate_part_kernel(const float* __restrict__ g_W)
{
    const int o = blockIdx.x * 128 + threadIdx.x;
    const int h0 = blockIdx.y * 128;
    float acc = 0.f;
    #pragma unroll 4
    for (int k = 0; k < 128; k++) {
        int h = h0 + k;
        acc = fmaf(g_CB[h],        g_W[(size_t)(H + h) * H + o],     acc);
        acc = fmaf(g_CB[1024 + h], g_W[(size_t)(2 * H + h) * H + o], acc);
    }
    g_cgpart[blockIdx.y][o] = acc;
}

__global__ void cgate_reduce_kernel(const float* __restrict__ g_b)
{
    int o = blockIdx.x * 256 + threadIdx.x;   // 0..1023
    float acc = g_b[o];
    #pragma unroll
    for (int j = 0; j < 8; j++) acc += g_cgpart[j][o];
    g_cgate[o] = acc;
}

// Wg2 rows 0:1024 <- gW1, rows 1328:2352 <- gW4.
__global__ void wg2copy_kernel(const float* __restrict__ g_W)
{
    int idx = blockIdx.x * 256 + threadIdx.x;
    if (idx >= H * H) return;
    g_Wg2[idx] = g_W[idx];
    g_Wg2[(size_t)(H + GDIM) * H + idx] = g_W[(size_t)3 * H * H + idx];
}

// GcG = WF @ g_W[H:3H, :]  -> Wg2 rows 1024:1328.  grid (32, 8), block 256.
__global__ __launch_bounds__(256)
void gcg_kernel(const float* __restrict__ g_W)
{
    __shared__ float sA[40][32];
    __shared__ float sB[32][33];
    const int p0 = blockIdx.y * 38;
    const int col0 = blockIdx.x * 32;
    const int tid = threadIdx.x;
    const int c = tid & 31, rg = tid >> 5;
    float acc[5] = {0,0,0,0,0};

    for (int k0 = 0; k0 < 2048; k0 += 32) {
        for (int i = tid; i < 38 * 32; i += 256) {
            int pp = i >> 5, k = i & 31;
            sA[pp][k] = g_WF[(size_t)(p0 + pp) * 2048 + k0 + k];
        }
        for (int i = tid; i < 32 * 32; i += 256) {
            int k = i >> 5, cc = i & 31;
            sB[k][cc] = g_W[(size_t)(H + k0 + k) * H + col0 + cc];
        }
        __syncthreads();
        #pragma unroll 4
        for (int k = 0; k < 32; k++) {
            float b = sB[k][c];
            #pragma unroll
            for (int ii = 0; ii < 5; ii++)
                acc[ii] = fmaf(sA[rg * 5 + ii][k], b, acc[ii]);
        }
        __syncthreads();
    }
    #pragma unroll
    for (int ii = 0; ii < 5; ii++) {
        int row = rg * 5 + ii;
        if (row < 38)
            g_Wg2[(size_t)(H + p0 + row) * H + col0 + c] = acc[ii];
    }
}

// ----------------------------------------------------------------------------
// Sequential recurrence. One warp per (e,b); lanes 0..15 = r.
// ----------------------------------------------------------------------------
__global__ void recur_kernel(const float* __restrict__ lam_r,
                             const float* __restrict__ lam_i)
{
    const int eb = blockIdx.x;
    const int e = eb >> 2;
    const int b = eb & 3;
    const int lane = threadIdx.x;
    if (lane >= R) return;

    const float lr = (1.f - ETA) * lam_r[e * R + lane];
    const float li = (1.f - ETA) * lam_i[e * R + lane];

    const float* up = g_U + (size_t)b * T * 128 + e * 32 + lane;
    float* gp = g_G + (size_t)b * T * GDIM + e * 76;

    float hr = 0.f, hi = 0.f, acc = 0.f;
    const unsigned mask = 0xFFFFu;

    float u_r = up[0];
    float u_i = up[16];

    for (int t = 0; t < T; t++) {
        int tn = (t + 1 < T) ? (t + 1) : t;
        float nu_r = up[(size_t)tn * 128];
        float nu_i = up[(size_t)tn * 128 + 16];

        float nhr = lr * hr - li * hi + ETA * u_r;
        float nhi = lr * hi + li * hr + ETA * u_i;
        float m2 = nhr * nhr + nhi * nhi;

        float s = m2, mx = m2;
        #pragma unroll
        for (int off = 8; off >= 1; off >>= 1) {
            s += __shfl_xor_sync(mask, s, off, 16);
            mx = fmaxf(mx, __shfl_xor_sync(mask, mx, off, 16));
        }
        float m_mean = s * (1.f / 16.f);
        acc = 0.99f * acc + 0.01f * m_mean;
        float inv = rsqrtf(m_mean + EPS);
        float hnr = nhr * inv, hni = nhi * inv;

        float sr = hnr, si = hni;
        #pragma unroll
        for (int off = 8; off >= 1; off >>= 1) {
            sr += __shfl_xor_sync(mask, sr, off, 16);
            si += __shfl_xor_sync(mask, si, off, 16);
        }
        float mr = sr * (1.f / 16.f);
        float mi = si * (1.f / 16.f);

        float* g_t = gp + (size_t)t * GDIM;
        g_t[6 + lane]           = hnr;
        g_t[6 + R + lane]       = hni;
        g_t[38 + 6 + lane]      = hni;
        g_t[38 + 6 + R + lane]  = -hnr;
        if (lane == 0) {
            g_t[0] = mr;
            g_t[1] = mi;
            g_t[2] = sqrtf(m_mean + EPS);
            g_t[3] = sqrtf(mx + EPS);
            g_t[4] = acc;
            g_t[5] = log1pf(acc);
            g_t[38 + 0] = mi;
            g_t[38 + 1] = -mr;
            g_t[38 + 2] = 0.f; g_t[38 + 3] = 0.f; g_t[38 + 4] = 0.f; g_t[38 + 5] = 0.f;
        }
        hr = nhr; hi = nhi;
        u_r = nu_r; u_i = nu_i;
    }
}

// ----------------------------------------------------------------------------
// Gate concat CC2 = [x | G | mag]. grid M_TOT, block 256.
// ----------------------------------------------------------------------------
__global__ void concat2_kernel(const float* __restrict__ x)
{
    const int row = blockIdx.x;
    float* dst = g_CC2 + (size_t)row * CCW;
    const float* xr = x + (size_t)row * H;
    const float* gr = g_G + (size_t)row * GDIM;
    const float* fr = g_FRF + (size_t)row * 2048;
    for (int c = threadIdx.x; c < CCW; c += 256) {
        float v;
        if (c < H) v = xr[c];
        else if (c < H + GDIM) v = gr[c - H];
        else {
            int h = c - H - GDIM;
            float a = fr[h], b = fr[1024 + h];
            v = sqrtf(a * a + b * b + EPS);
        }
        dst[c] = v;
    }
}

// ----------------------------------------------------------------------------
// Launch
// ----------------------------------------------------------------------------
extern "C" void kernel_launch(void* const* d_in, const int* in_sizes, int n_in,
                              void* d_out, int out_size)
{
    const float* x      = (const float*)d_in[0];
    const float* sig_Wr = (const float*)d_in[1];
    const float* sig_Wi = (const float*)d_in[2];
    const float* sig_br = (const float*)d_in[3];
    const float* sig_bi = (const float*)d_in[4];
    const float* A_r    = (const float*)d_in[5];
    const float* A_i    = (const float*)d_in[6];
    const float* lam_r  = (const float*)d_in[7];
    const float* lam_i  = (const float*)d_in[8];
    const float* eh_Wr  = (const float*)d_in[9];
    const float* eh_Wi  = (const float*)d_in[10];
    const float* eh_br  = (const float*)d_in[11];
    const float* eh_bi  = (const float*)d_in[12];
    const float* fu_Wr  = (const float*)d_in[13];
    const float* fu_Wi  = (const float*)d_in[14];
    const float* fu_br  = (const float*)d_in[15];
    const float* fu_bi  = (const float*)d_in[16];
    const float* gW     = (const float*)d_in[17];
    const float* gb     = (const float*)d_in[18];
    float* out = (float*)d_out;

    float *Bc, *ubias, *U, *G, *WF, *CB, *FRF, *Wg2, *cgate, *CC2;
    cudaGetSymbolAddress((void**)&Bc,    g_Bc);
    cudaGetSymbolAddress((void**)&ubias, g_ubias);
    cudaGetSymbolAddress((void**)&U,     g_U);
    cudaGetSymbolAddress((void**)&G,     g_G);
    cudaGetSymbolAddress((void**)&WF,    g_WF);
    cudaGetSymbolAddress((void**)&CB,    g_CB);
    cudaGetSymbolAddress((void**)&FRF,   g_FRF);
    cudaGetSymbolAddress((void**)&Wg2,   g_Wg2);
    cudaGetSymbolAddress((void**)&cgate, g_cgate);
    cudaGetSymbolAddress((void**)&CC2,   g_CC2);

    // --- precompute (weight composition) ---
    combine_proj_kernel<<<dim3(64, E), 256>>>(sig_Wr, sig_Wi, A_r, A_i);
    ubias_kernel<<<1, 128>>>(sig_br, sig_bi, A_r, A_i);
    pquv_kernel<<<dim3(32, E), 256>>>(eh_Wr, eh_Wi, fu_Wr, fu_Wi);
    crci_part_kernel<<<dim3(8, 32), 128>>>(eh_br, eh_bi, fu_Wr, fu_Wi);
    crci_reduce_kernel<<<8, 256>>>(fu_br, fu_bi);
    wg2copy_kernel<<<(H * H + 255) / 256, 256>>>(gW);
    gcg_kernel<<<dim3(32, 8), 256>>>(gW);
    cgate_part_kernel<<<dim3(8, 8), 128>>>(gW);
    cgate_reduce_kernel<<<4, 256>>>(gb);

    // --- main path ---
    // U = x @ Bc + ubias         [8192,1024]@[1024,128]
    sgemm_k<0><<<dim3(1, M_TOT / 128), 256>>>(x, Bc, U, M_TOT, 128, H, ubias,
                                              nullptr, 0, nullptr, 0);
    // recurrence -> G
    recur_kernel<<<E * BSZ, 32>>>(lam_r, lam_i);
    // FRF = G @ WF + [cr|ci]     [8192,304]@[304,2048]
    sgemm_k<0><<<dim3(2048 / 128, M_TOT / 128), 256>>>(G, WF, FRF, M_TOT, 2048, GDIM, CB,
                                                       nullptr, 0, nullptr, 0);
    // CC2 = [x | G | mag]
    concat2_kernel<<<M_TOT, 256>>>(x);
    // gate: v = CC2 @ Wg2 + cgate ; out = sig(v)*frf + (1-sig(v))*x
    sgemm_k<1><<<dim3(H / 128, M_TOT / 128), 256>>>(CC2, Wg2, out, M_TOT, H, CCW, cgate,
                                                    FRF, 2048, x, H);
}

// round 6
// speedup vs baseline: 4.1086x; 1.0404x over previous
#include <cuda_runtime.h>
#include <math.h>
#include <stdint.h>

#define BSZ 4
#define T 2048
#define H 1024
#define S 512
#define R 16
#define E 4
#define FDIM 38             // 6 + 2*R
#define M_TOT (BSZ*T)       // 8192
#define GDIM (E*2*FDIM)     // 304   feature width [fr|fi] per engine
#define CCW (H + GDIM + H)  // 2352  gate concat width  (147*16)
#define ETA 0.1f
#define EPS 1e-6f

// ----------------------------------------------------------------------------
// Scratch (static device globals)
// ----------------------------------------------------------------------------
__device__ float g_Bc[H * 128];
__device__ float g_ubias[128];
__device__ float g_U[M_TOT * 128];
__device__ float g_G[(size_t)M_TOT * GDIM];
__device__ float g_WF[(size_t)GDIM * 2048];
__device__ float g_CB[2048];
__device__ float g_CBpart[32][2048];
__device__ float g_cgpart[8][1024];
__device__ float g_FRF[(size_t)M_TOT * 2048];
__device__ float g_Wg2[(size_t)CCW * H];
__device__ float g_cgate[H];
__device__ float g_CC2[(size_t)M_TOT * CCW];

// ----------------------------------------------------------------------------
// tf32 2-term split helper: v = hi + lo (hi, lo both tf32 bit-patterns in u32)
// ----------------------------------------------------------------------------
__device__ __forceinline__ void split_tf32(float v, uint32_t& hi, uint32_t& lo)
{
    uint32_t h;
    asm("cvt.rna.tf32.f32 %0, %1;" : "=r"(h) : "f"(v));
    float lf = v - __uint_as_float(h);
    uint32_t l;
    asm("cvt.rna.tf32.f32 %0, %1;" : "=r"(l) : "f"(lf));
    hi = h; lo = l;
}

__device__ __forceinline__ void mma_tf32(float* d, const uint32_t* a, const uint32_t* b)
{
    asm volatile(
        "mma.sync.aligned.m16n8k8.row.col.f32.tf32.tf32.f32 "
        "{%0,%1,%2,%3}, {%4,%5,%6,%7}, {%8,%9}, {%0,%1,%2,%3};"
        : "+f"(d[0]), "+f"(d[1]), "+f"(d[2]), "+f"(d[3])
        : "r"(a[0]), "r"(a[1]), "r"(a[2]), "r"(a[3]), "r"(b[0]), "r"(b[1]));
}

// ----------------------------------------------------------------------------
// Tensor-core GEMM (tf32 2-term split ≈ fp32 accuracy):
// C[M,N] = A[M,K] @ B[K,N] + bias[N].  CTA tile 128x128, KT=16, 8 warps (64x32).
// Requires M%128==0, N%128==0, K%16==0.
// EPI==1: g = sigmoid(v); C = g*e1 + (1-g)*e2 (own row strides)
// ----------------------------------------------------------------------------
#define MLDA 136
template<int EPI>
__global__ __launch_bounds__(256)
void mma_gemm(const float* __restrict__ A, const float* __restrict__ B,
              float* __restrict__ C, int M, int N, int K,
              const float* __restrict__ bias,
              const float* __restrict__ e1, int ld1,
              const float* __restrict__ e2, int ld2)
{
    __shared__ float As[16][MLDA];   // [k][m]
    __shared__ float Bs[16][MLDA];   // [k][n]
    const int tid = threadIdx.x;
    const int bx = blockIdx.x, by = blockIdx.y;
    const int wid = tid >> 5, lane = tid & 31;
    const int wm = wid & 1, wn = wid >> 1;        // 2 x 4 warps
    const int grp = lane >> 2, tig = lane & 3;

    // global load indexing
    const int aRow = tid >> 2, aCol = (tid & 3) * 4;     // A: 2 rows per thread (aRow, aRow+64)
    const int bRow = tid >> 5, bCol = (tid & 31) * 4;    // B: rows bRow, bRow+8

    const float* Ap0 = A + (size_t)(by * 128 + aRow) * K + aCol;
    const float* Ap1 = A + (size_t)(by * 128 + 64 + aRow) * K + aCol;
    const float* Bp0 = B + (size_t)bRow * N + bx * 128 + bCol;
    const float* Bp1 = B + (size_t)(bRow + 8) * N + bx * 128 + bCol;

    float acc[4][4][4];
    #pragma unroll
    for (int i = 0; i < 4; i++)
        #pragma unroll
        for (int j = 0; j < 4; j++)
            #pragma unroll
            for (int q = 0; q < 4; q++) acc[i][j][q] = 0.f;

    float4 pa0 = *(const float4*)(Ap0);
    float4 pa1 = *(const float4*)(Ap1);
    float4 pb0 = *(const float4*)(Bp0);
    float4 pb1 = *(const float4*)(Bp1);

    for (int k0 = 0; k0 < K; k0 += 16) {
        As[aCol + 0][aRow] = pa0.x;  As[aCol + 1][aRow] = pa0.y;
        As[aCol + 2][aRow] = pa0.z;  As[aCol + 3][aRow] = pa0.w;
        As[aCol + 0][aRow + 64] = pa1.x;  As[aCol + 1][aRow + 64] = pa1.y;
        As[aCol + 2][aRow + 64] = pa1.z;  As[aCol + 3][aRow + 64] = pa1.w;
        *(float4*)&Bs[bRow][bCol]     = pb0;
        *(float4*)&Bs[bRow + 8][bCol] = pb1;
        __syncthreads();

        if (k0 + 16 < K) {
            pa0 = *(const float4*)(Ap0 + k0 + 16);
            pa1 = *(const float4*)(Ap1 + k0 + 16);
            pb0 = *(const float4*)(Bp0 + (size_t)(k0 + 16) * N);
            pb1 = *(const float4*)(Bp1 + (size_t)(k0 + 16) * N);
        }

        #pragma unroll
        for (int kk = 0; kk < 2; kk++) {
            const int kb = kk * 8;
            uint32_t ah[4][4], al[4][4], bh[4][2], bl[4][2];
            #pragma unroll
            for (int i = 0; i < 4; i++) {
                int m = wm * 64 + i * 16 + grp;
                split_tf32(As[kb + tig][m],         ah[i][0], al[i][0]);
                split_tf32(As[kb + tig][m + 8],     ah[i][1], al[i][1]);
                split_tf32(As[kb + tig + 4][m],     ah[i][2], al[i][2]);
                split_tf32(As[kb + tig + 4][m + 8], ah[i][3], al[i][3]);
            }
            #pragma unroll
            for (int j = 0; j < 4; j++) {
                int n = wn * 32 + j * 8 + grp;
                split_tf32(Bs[kb + tig][n],     bh[j][0], bl[j][0]);
                split_tf32(Bs[kb + tig + 4][n], bh[j][1], bl[j][1]);
            }
            #pragma unroll
            for (int i = 0; i < 4; i++)
                #pragma unroll
                for (int j = 0; j < 4; j++) {
                    mma_tf32(acc[i][j], ah[i], bh[j]);
                    mma_tf32(acc[i][j], ah[i], bl[j]);
                    mma_tf32(acc[i][j], al[i], bh[j]);
                }
        }
        __syncthreads();
    }

    #pragma unroll
    for (int i = 0; i < 4; i++) {
        #pragma unroll
        for (int j = 0; j < 4; j++) {
            int row0 = by * 128 + wm * 64 + i * 16 + grp;
            int col0 = bx * 128 + wn * 32 + j * 8 + tig * 2;
            #pragma unroll
            for (int q = 0; q < 4; q++) {
                int row = row0 + (q >> 1) * 8;
                int col = col0 + (q & 1);
                float v = acc[i][j][q] + bias[col];
                if (EPI == 0) {
                    C[(size_t)row * N + col] = v;
                } else {
                    float g = 1.f / (1.f + expf(-v));
                    C[(size_t)row * N + col] =
                        g * e1[(size_t)row * ld1 + col] + (1.f - g) * e2[(size_t)row * ld2 + col];
                }
            }
        }
    }
}

// ----------------------------------------------------------------------------
// SIMT SGEMM (kept for U projection): 128x128x8 tile, 256 thr, 8x8/thread.
// ----------------------------------------------------------------------------
__global__ __launch_bounds__(256)
void sgemm_k(const float* __restrict__ A, const float* __restrict__ B,
             float* __restrict__ C, int M, int N, int K,
             const float* __restrict__ bias)
{
    __shared__ float As[8][128];
    __shared__ float Bs[8][128];
    const int tid = threadIdx.x;
    const int bx = blockIdx.x, by = blockIdx.y;
    const int tx = tid & 15, ty = tid >> 4;
    const int aRow = tid >> 1, aCol = (tid & 1) * 4;
    const int bRow = tid >> 5, bCol = (tid & 31) * 4;
    const float* Ap = A + (size_t)(by * 128 + aRow) * K + aCol;
    const float* Bp = B + (size_t)bRow * N + bx * 128 + bCol;

    float acc[8][8];
    #pragma unroll
    for (int i = 0; i < 8; i++)
        #pragma unroll
        for (int j = 0; j < 8; j++) acc[i][j] = 0.f;

    float4 a4 = *(const float4*)(Ap);
    float4 b4 = *(const float4*)(Bp);

    for (int k0 = 0; k0 < K; k0 += 8) {
        As[aCol + 0][aRow] = a4.x;
        As[aCol + 1][aRow] = a4.y;
        As[aCol + 2][aRow] = a4.z;
        As[aCol + 3][aRow] = a4.w;
        *(float4*)&Bs[bRow][bCol] = b4;
        __syncthreads();

        if (k0 + 8 < K) {
            a4 = *(const float4*)(Ap + k0 + 8);
            b4 = *(const float4*)(Bp + (size_t)(k0 + 8) * N);
        }

        #pragma unroll
        for (int kk = 0; kk < 8; kk++) {
            float4 a0 = *(const float4*)&As[kk][ty * 8];
            float4 a1 = *(const float4*)&As[kk][ty * 8 + 4];
            float4 b0 = *(const float4*)&Bs[kk][tx * 8];
            float4 b1 = *(const float4*)&Bs[kk][tx * 8 + 4];
            float ar[8] = {a0.x, a0.y, a0.z, a0.w, a1.x, a1.y, a1.z, a1.w};
            float br[8] = {b0.x, b0.y, b0.z, b0.w, b1.x, b1.y, b1.z, b1.w};
            #pragma unroll
            for (int i = 0; i < 8; i++)
                #pragma unroll
                for (int j = 0; j < 8; j++)
                    acc[i][j] = fmaf(ar[i], br[j], acc[i][j]);
        }
        __syncthreads();
    }

    #pragma unroll
    for (int i = 0; i < 8; i++) {
        int row = by * 128 + ty * 8 + i;
        #pragma unroll
        for (int j = 0; j < 8; j++) {
            int col = bx * 128 + tx * 8 + j;
            C[(size_t)row * N + col] = acc[i][j] + bias[col];
        }
    }
}

// ----------------------------------------------------------------------------
// Precompute Bc (combined input proj)
// ----------------------------------------------------------------------------
__global__ __launch_bounds__(256)
void combine_proj_kernel(const float* __restrict__ sig_Wr, const float* __restrict__ sig_Wi,
                         const float* __restrict__ A_r, const float* __restrict__ A_i)
{
    __shared__ float sAr[128][16], sAi[128][16];
    __shared__ float sWr[16][128], sWi[16][128];
    const int e = blockIdx.y;
    const int h0 = blockIdx.x * 16;
    const int tid = threadIdx.x;
    const int h_loc = tid >> 4, r = tid & 15;
    float aur = 0.f, aui = 0.f;

    for (int s0 = 0; s0 < S; s0 += 128) {
        for (int i = tid; i < 128 * 16; i += 256) {
            int s = i >> 4, rr = i & 15;
            sAr[s][rr] = A_r[((size_t)e * S + s0 + s) * R + rr];
            sAi[s][rr] = A_i[((size_t)e * S + s0 + s) * R + rr];
        }
        for (int i = tid; i < 16 * 128; i += 256) {
            int hh = i >> 7, ss = i & 127;
            sWr[hh][ss] = sig_Wr[(size_t)(h0 + hh) * S + s0 + ss];
            sWi[hh][ss] = sig_Wi[(size_t)(h0 + hh) * S + s0 + ss];
        }
        __syncthreads();
        #pragma unroll 4
        for (int s = 0; s < 128; s++) {
            float wr = sWr[h_loc][s], wi = sWi[h_loc][s];
            float ar = sAr[s][r],     ai = sAi[s][r];
            aur = fmaf(wr, ar, aur);
            aur = fmaf(-wi, ai, aur);
            aui = fmaf(wr, ai, aui);
            aui = fmaf(wi, ar, aui);
        }
        __syncthreads();
    }
    g_Bc[(size_t)(h0 + h_loc) * 128 + e * 32 + r]      = aur;
    g_Bc[(size_t)(h0 + h_loc) * 128 + e * 32 + 16 + r] = aui;
}

__global__ void ubias_kernel(const float* __restrict__ sig_br, const float* __restrict__ sig_bi,
                             const float* __restrict__ A_r, const float* __restrict__ A_i)
{
    int j = threadIdx.x;
    int e = j >> 5, half = (j >> 4) & 1, r = j & 15;
    float acc = 0.f;
    for (int s = 0; s < S; s++) {
        float ar = A_r[((size_t)e * S + s) * R + r];
        float ai = A_i[((size_t)e * S + s) * R + r];
        float br = sig_br[s], bi = sig_bi[s];
        acc += half ? (br * ai + bi * ar) : (br * ar - bi * ai);
    }
    g_ubias[j] = acc;
}

// ----------------------------------------------------------------------------
// pquv (widened): per engine, WF rows from wc1 = P-Q, wc2 = U+V directly.
// grid (H/64, E), block 256 = 64 cols x 4 row-groups (10,10,10,8 rows of 38).
// ----------------------------------------------------------------------------
__global__ __launch_bounds__(256)
void pquv_kernel(const float* __restrict__ eh_Wr, const float* __restrict__ eh_Wi,
                 const float* __restrict__ fu_Wr, const float* __restrict__ fu_Wi)
{
    __shared__ float2 sA[40][32];   // (ar, ai) [f][k]
    __shared__ float2 sB[32][64];   // (br, bi) [k][c]
    const int e = blockIdx.y;
    const int col0 = blockIdx.x * 64;
    const int tid = threadIdx.x;
    const int c = tid & 63, rg = tid >> 6;
    const int row0 = rg * 10;
    const int nrows = (rg == 3) ? 8 : 10;

    float wc1[10], wc2[10];
    #pragma unroll
    for (int i = 0; i < 10; i++) { wc1[i] = 0.f; wc2[i] = 0.f; }

    for (int k0 = 0; k0 < H; k0 += 32) {
        for (int i = tid; i < FDIM * 32; i += 256) {
            int f = i >> 5, k = i & 31;
            size_t off = ((size_t)e * FDIM + f) * H + k0 + k;
            sA[f][k] = make_float2(eh_Wr[off], eh_Wi[off]);
        }
        for (int i = tid; i < 32 * 64; i += 256) {
            int k = i >> 6, cc = i & 63;
            size_t off = ((size_t)e * H + k0 + k) * H + col0 + cc;
            sB[k][cc] = make_float2(fu_Wr[off], fu_Wi[off]);
        }
        __syncthreads();
        for (int k = 0; k < 32; k++) {
            float2 b = sB[k][c];
            #pragma unroll
            for (int i = 0; i < 10; i++) {
                if (i < nrows) {
                    float2 a = sA[row0 + i][k];
                    wc1[i] = fmaf(a.x, b.x, wc1[i]);
                    wc1[i] = fmaf(-a.y, b.y, wc1[i]);
                    wc2[i] = fmaf(a.x, b.y, wc2[i]);
                    wc2[i] = fmaf(a.y, b.x, wc2[i]);
                }
            }
        }
        __syncthreads();
    }
    #pragma unroll
    for (int i = 0; i < 10; i++) {
        if (i < nrows) {
            int row = row0 + i;
            size_t b1 = (size_t)(e * 76 + row) * 2048;
            size_t b2 = (size_t)(e * 76 + 38 + row) * 2048;
            int cg = col0 + c;
            g_WF[b1 + cg]        = wc1[i];
            g_WF[b1 + 1024 + cg] = wc2[i];
            g_WF[b2 + cg]        = -wc2[i];
            g_WF[b2 + 1024 + cg] = wc1[i];
        }
    }
}

// ----------------------------------------------------------------------------
// crci / cgate (parallel partials, deterministic reduce)
// ----------------------------------------------------------------------------
__global__ void crci_part_kernel(const float* __restrict__ eh_br, const float* __restrict__ eh_bi,
                                 const float* __restrict__ fu_Wr, const float* __restrict__ fu_Wi)
{
    const int o = blockIdx.x * 128 + threadIdx.x;
    const int eh0 = blockIdx.y * 128;
    float cr = 0.f, ci = 0.f;
    #pragma unroll 4
    for (int k = 0; k < 128; k++) {
        int eh = eh0 + k;
        float br = eh_br[eh], bi = eh_bi[eh];
        float wr = fu_Wr[(size_t)eh * H + o], wi = fu_Wi[(size_t)eh * H + o];
        cr = fmaf(br, wr, cr); cr = fmaf(-bi, wi, cr);
        ci = fmaf(br, wi, ci); ci = fmaf(bi, wr, ci);
    }
    g_CBpart[blockIdx.y][o]        = cr;
    g_CBpart[blockIdx.y][1024 + o] = ci;
}

__global__ void crci_reduce_kernel(const float* __restrict__ fu_br, const float* __restrict__ fu_bi)
{
    int o = blockIdx.x * 256 + threadIdx.x;
    float acc = (o < 1024) ? fu_br[o] : fu_bi[o - 1024];
    #pragma unroll
    for (int j = 0; j < 32; j++) acc += g_CBpart[j][o];
    g_CB[o] = acc;
}

__global__ void cgate_part_kernel(const float* __restrict__ g_W)
{
    const int o = blockIdx.x * 128 + threadIdx.x;
    const int h0 = blockIdx.y * 128;
    float acc = 0.f;
    #pragma unroll 4
    for (int k = 0; k < 128; k++) {
        int h = h0 + k;
        acc = fmaf(g_CB[h],        g_W[(size_t)(H + h) * H + o],     acc);
        acc = fmaf(g_CB[1024 + h], g_W[(size_t)(2 * H + h) * H + o], acc);
    }
    g_cgpart[blockIdx.y][o] = acc;
}

__global__ void cgate_reduce_kernel(const float* __restrict__ g_b)
{
    int o = blockIdx.x * 256 + threadIdx.x;
    float acc = g_b[o];
    #pragma unroll
    for (int j = 0; j < 8; j++) acc += g_cgpart[j][o];
    g_cgate[o] = acc;
}

__global__ void wg2copy_kernel(const float* __restrict__ g_W)
{
    int idx = blockIdx.x * 256 + threadIdx.x;
    if (idx >= H * H) return;
    g_Wg2[idx] = g_W[idx];
    g_Wg2[(size_t)(H + GDIM) * H + idx] = g_W[(size_t)3 * H * H + idx];
}

// ----------------------------------------------------------------------------
// gcg (widened): Wg2[H + p, col] = sum_k WF[p,k] * gW[H+k, col]
// grid (H/64, 8 row-blocks of 38), block 256 = 64 cols x 4 row-groups.
// ----------------------------------------------------------------------------
__global__ __launch_bounds__(256)
void gcg_kernel(const float* __restrict__ g_W)
{
    __shared__ float sA[40][32];
    __shared__ float sB[32][64];
    const int p0 = blockIdx.y * 38;
    const int col0 = blockIdx.x * 64;
    const int tid = threadIdx.x;
    const int c = tid & 63, rg = tid >> 6;
    const int row0 = rg * 10;
    const int nrows = (rg == 3) ? 8 : 10;

    float acc[10];
    #pragma unroll
    for (int i = 0; i < 10; i++) acc[i] = 0.f;

    for (int k0 = 0; k0 < 2048; k0 += 32) {
        for (int i = tid; i < 38 * 32; i += 256) {
            int pp = i >> 5, k = i & 31;
            sA[pp][k] = g_WF[(size_t)(p0 + pp) * 2048 + k0 + k];
        }
        for (int i = tid; i < 32 * 64; i += 256) {
            int k = i >> 6, cc = i & 63;
            sB[k][cc] = g_W[(size_t)(H + k0 + k) * H + col0 + cc];
        }
        __syncthreads();
        for (int k = 0; k < 32; k++) {
            float b = sB[k][c];
            #pragma unroll
            for (int i = 0; i < 10; i++)
                if (i < nrows)
                    acc[i] = fmaf(sA[row0 + i][k], b, acc[i]);
        }
        __syncthreads();
    }
    #pragma unroll
    for (int i = 0; i < 10; i++)
        if (i < nrows)
            g_Wg2[(size_t)(H + p0 + row0 + i) * H + col0 + c] = acc[i];
}

// ----------------------------------------------------------------------------
// Sequential recurrence. One warp per (e,b); lanes 0..15 = r.
// ----------------------------------------------------------------------------
__global__ void recur_kernel(const float* __restrict__ lam_r,
                             const float* __restrict__ lam_i)
{
    const int eb = blockIdx.x;
    const int e = eb >> 2;
    const int b = eb & 3;
    const int lane = threadIdx.x;
    if (lane >= R) return;

    const float lr = (1.f - ETA) * lam_r[e * R + lane];
    const float li = (1.f - ETA) * lam_i[e * R + lane];

    const float* up = g_U + (size_t)b * T * 128 + e * 32 + lane;
    float* gp = g_G + (size_t)b * T * GDIM + e * 76;

    float hr = 0.f, hi = 0.f, acc = 0.f;
    const unsigned mask = 0xFFFFu;

    float u_r = up[0];
    float u_i = up[16];

    for (int t = 0; t < T; t++) {
        int tn = (t + 1 < T) ? (t + 1) : t;
        float nu_r = up[(size_t)tn * 128];
        float nu_i = up[(size_t)tn * 128 + 16];

        float nhr = lr * hr - li * hi + ETA * u_r;
        float nhi = lr * hi + li * hr + ETA * u_i;
        float m2 = nhr * nhr + nhi * nhi;

        float s = m2, mx = m2;
        #pragma unroll
        for (int off = 8; off >= 1; off >>= 1) {
            s += __shfl_xor_sync(mask, s, off, 16);
            mx = fmaxf(mx, __shfl_xor_sync(mask, mx, off, 16));
        }
        float m_mean = s * (1.f / 16.f);
        acc = 0.99f * acc + 0.01f * m_mean;
        float inv = rsqrtf(m_mean + EPS);
        float hnr = nhr * inv, hni = nhi * inv;

        float sr = hnr, si = hni;
        #pragma unroll
        for (int off = 8; off >= 1; off >>= 1) {
            sr += __shfl_xor_sync(mask, sr, off, 16);
            si += __shfl_xor_sync(mask, si, off, 16);
        }
        float mr = sr * (1.f / 16.f);
        float mi = si * (1.f / 16.f);

        float* g_t = gp + (size_t)t * GDIM;
        g_t[6 + lane]           = hnr;
        g_t[6 + R + lane]       = hni;
        g_t[38 + 6 + lane]      = hni;
        g_t[38 + 6 + R + lane]  = -hnr;
        if (lane == 0) {
            g_t[0] = mr;
            g_t[1] = mi;
            g_t[2] = sqrtf(m_mean + EPS);
            g_t[3] = sqrtf(mx + EPS);
            g_t[4] = acc;
            g_t[5] = log1pf(acc);
            g_t[38 + 0] = mi;
            g_t[38 + 1] = -mr;
            g_t[38 + 2] = 0.f; g_t[38 + 3] = 0.f; g_t[38 + 4] = 0.f; g_t[38 + 5] = 0.f;
        }
        hr = nhr; hi = nhi;
        u_r = nu_r; u_i = nu_i;
    }
}

// ----------------------------------------------------------------------------
// Gate concat CC2 = [x | G | mag]
// ----------------------------------------------------------------------------
__global__ void concat2_kernel(const float* __restrict__ x)
{
    const int row = blockIdx.x;
    float* dst = g_CC2 + (size_t)row * CCW;
    const float* xr = x + (size_t)row * H;
    const float* gr = g_G + (size_t)row * GDIM;
    const float* fr = g_FRF + (size_t)row * 2048;
    for (int c = threadIdx.x; c < CCW; c += 256) {
        float v;
        if (c < H) v = xr[c];
        else if (c < H + GDIM) v = gr[c - H];
        else {
            int h = c - H - GDIM;
            float a = fr[h], b = fr[1024 + h];
            v = sqrtf(a * a + b * b + EPS);
        }
        dst[c] = v;
    }
}

// ----------------------------------------------------------------------------
// Launch
// ----------------------------------------------------------------------------
extern "C" void kernel_launch(void* const* d_in, const int* in_sizes, int n_in,
                              void* d_out, int out_size)
{
    const float* x      = (const float*)d_in[0];
    const float* sig_Wr = (const float*)d_in[1];
    const float* sig_Wi = (const float*)d_in[2];
    const float* sig_br = (const float*)d_in[3];
    const float* sig_bi = (const float*)d_in[4];
    const float* A_r    = (const float*)d_in[5];
    const float* A_i    = (const float*)d_in[6];
    const float* lam_r  = (const float*)d_in[7];
    const float* lam_i  = (const float*)d_in[8];
    const float* eh_Wr  = (const float*)d_in[9];
    const float* eh_Wi  = (const float*)d_in[10];
    const float* eh_br  = (const float*)d_in[11];
    const float* eh_bi  = (const float*)d_in[12];
    const float* fu_Wr  = (const float*)d_in[13];
    const float* fu_Wi  = (const float*)d_in[14];
    const float* fu_br  = (const float*)d_in[15];
    const float* fu_bi  = (const float*)d_in[16];
    const float* gW     = (const float*)d_in[17];
    const float* gb     = (const float*)d_in[18];
    float* out = (float*)d_out;

    float *Bc, *ubias, *U, *G, *WF, *CB, *FRF, *Wg2, *cgate, *CC2;
    cudaGetSymbolAddress((void**)&Bc,    g_Bc);
    cudaGetSymbolAddress((void**)&ubias, g_ubias);
    cudaGetSymbolAddress((void**)&U,     g_U);
    cudaGetSymbolAddress((void**)&G,     g_G);
    cudaGetSymbolAddress((void**)&WF,    g_WF);
    cudaGetSymbolAddress((void**)&CB,    g_CB);
    cudaGetSymbolAddress((void**)&FRF,   g_FRF);
    cudaGetSymbolAddress((void**)&Wg2,   g_Wg2);
    cudaGetSymbolAddress((void**)&cgate, g_cgate);
    cudaGetSymbolAddress((void**)&CC2,   g_CC2);

    // --- precompute (weight composition) ---
    combine_proj_kernel<<<dim3(64, E), 256>>>(sig_Wr, sig_Wi, A_r, A_i);
    ubias_kernel<<<1, 128>>>(sig_br, sig_bi, A_r, A_i);
    pquv_kernel<<<dim3(H / 64, E), 256>>>(eh_Wr, eh_Wi, fu_Wr, fu_Wi);
    crci_part_kernel<<<dim3(8, 32), 128>>>(eh_br, eh_bi, fu_Wr, fu_Wi);
    crci_reduce_kernel<<<8, 256>>>(fu_br, fu_bi);
    wg2copy_kernel<<<(H * H + 255) / 256, 256>>>(gW);
    gcg_kernel<<<dim3(H / 64, 8), 256>>>(gW);
    cgate_part_kernel<<<dim3(8, 8), 128>>>(gW);
    cgate_reduce_kernel<<<4, 256>>>(gb);

    // --- main path ---
    // U = x @ Bc + ubias         [8192,1024]@[1024,128]
    sgemm_k<<<dim3(1, M_TOT / 128), 256>>>(x, Bc, U, M_TOT, 128, H, ubias);
    // recurrence -> G
    recur_kernel<<<E * BSZ, 32>>>(lam_r, lam_i);
    // FRF = G @ WF + [cr|ci]     [8192,304]@[304,2048]   (tensor cores)
    mma_gemm<0><<<dim3(2048 / 128, M_TOT / 128), 256>>>(G, WF, FRF, M_TOT, 2048, GDIM, CB,
                                                        nullptr, 0, nullptr, 0);
    // CC2 = [x | G | mag]
    concat2_kernel<<<M_TOT, 256>>>(x);
    // gate: v = CC2 @ Wg2 + cgate ; out = sig(v)*frf + (1-sig(v))*x   (tensor cores)
    mma_gemm<1><<<dim3(H / 128, M_TOT / 128), 256>>>(CC2, Wg2, out, M_TOT, H, CCW, cgate,
                                                     FRF, 2048, x, H);
}

// round 7
// speedup vs baseline: 7.1635x; 1.7435x over previous
#include <cuda_runtime.h>
#include <cuda_bf16.h>
#include <math.h>
#include <stdint.h>

#define BSZ 4
#define T 2048
#define H 1024
#define S 512
#define R 16
#define E 4
#define FDIM 38             // 6 + 2*R
#define M_TOT (BSZ*T)       // 8192
#define GDIM (E*2*FDIM)     // 304
#define CCW (H + GDIM + H)  // 2352
#define KPG 160             // padded k-pairs for G (304/2=152 -> 160)
#define KPC 1184            // padded k-pairs for CC (2352/2=1176 -> 1184)
#define NCH 32              // recurrence chunks
#define LCH 64              // steps per chunk
#define ETA 0.1f
#define EPS 1e-6f

// ----------------------------------------------------------------------------
// Scratch
// ----------------------------------------------------------------------------
__device__ float g_Bc[H * 128];
__device__ float g_ubias[128];
__device__ float g_Upart[4][M_TOT * 128];
__device__ float g_U[M_TOT * 128];
__device__ float g_G[(size_t)M_TOT * GDIM];
__device__ float g_WF[(size_t)GDIM * 2048];
__device__ float g_CB[2048];
__device__ float g_CBpart[32][2048];
__device__ float g_cgpart[8][1024];
__device__ float g_FRF[(size_t)M_TOT * 2048];
__device__ float g_Wg2[(size_t)CCW * H];
__device__ float g_cgate[H];
// packed bf16x2 hi/lo operands
__device__ uint32_t g_Gh[(size_t)M_TOT * KPG];
__device__ uint32_t g_Gl[(size_t)M_TOT * KPG];
__device__ uint32_t g_WFh[(size_t)KPG * 2048];
__device__ uint32_t g_WFl[(size_t)KPG * 2048];
__device__ uint32_t g_CCh[(size_t)M_TOT * KPC];
__device__ uint32_t g_CCl[(size_t)M_TOT * KPC];
__device__ uint32_t g_W2h[(size_t)KPC * H];
__device__ uint32_t g_W2l[(size_t)KPC * H];
// recurrence scan state
__device__ float2 g_hloc[16][NCH][16];
__device__ float2 g_hinit[16][NCH][16];
__device__ float g_lacc[16][T];
__device__ float g_accend[16][NCH];
__device__ float g_accinit[16][NCH];

// ----------------------------------------------------------------------------
// bf16 split-pack helper: (v0,v1) -> hi pair, lo pair (v = hi + lo)
// ----------------------------------------------------------------------------
__device__ __forceinline__ void split2(float v0, float v1, uint32_t& ph, uint32_t& pl)
{
    __nv_bfloat162 h2 = __floats2bfloat162_rn(v0, v1);
    float r0 = v0 - __bfloat162float(h2.x);
    float r1 = v1 - __bfloat162float(h2.y);
    __nv_bfloat162 l2 = __floats2bfloat162_rn(r0, r1);
    ph = *reinterpret_cast<uint32_t*>(&h2);
    pl = *reinterpret_cast<uint32_t*>(&l2);
}

__device__ __forceinline__ void mma_bf(float* d, const uint32_t* a, const uint32_t* b)
{
    asm volatile(
        "mma.sync.aligned.m16n8k16.row.col.f32.bf16.bf16.f32 "
        "{%0,%1,%2,%3}, {%4,%5,%6,%7}, {%8,%9}, {%0,%1,%2,%3};"
        : "+f"(d[0]), "+f"(d[1]), "+f"(d[2]), "+f"(d[3])
        : "r"(a[0]), "r"(a[1]), "r"(a[2]), "r"(a[3]), "r"(b[0]), "r"(b[1]));
}

// ----------------------------------------------------------------------------
// bf16 2-term-split tensor GEMM. A (hi/lo) [M][KP] u32 pairs, B [KP][N].
// CTA 128x128, 16 k-pairs (=32 k) per iteration, 8 warps (64x32 each).
// EPI==1: g = sigmoid(v); C = g*e1 + (1-g)*e2
// ----------------------------------------------------------------------------
template<int EPI>
__global__ __launch_bounds__(256)
void mma_bf16(const uint32_t* __restrict__ Ah, const uint32_t* __restrict__ Al,
              const uint32_t* __restrict__ Bh, const uint32_t* __restrict__ Bl,
              float* __restrict__ C, int M, int N, int KP,
              const float* __restrict__ bias,
              const float* __restrict__ e1, int ld1,
              const float* __restrict__ e2, int ld2)
{
    __shared__ uint32_t sAh[128][20], sAl[128][20];
    __shared__ uint32_t sBh[16][136], sBl[16][136];
    const int tid = threadIdx.x;
    const int bx = blockIdx.x, by = blockIdx.y;
    const int wid = tid >> 5, lane = tid & 31;
    const int wm = wid & 1, wn = wid >> 1;
    const int grp = lane >> 2, tig = lane & 3;

    const int aRow = tid >> 1, aCol = (tid & 1) * 8;
    const int bRow = tid >> 4, bCol = (tid & 15) * 8;

    const uint32_t* ApH = Ah + (size_t)(by * 128 + aRow) * KP + aCol;
    const uint32_t* ApL = Al + (size_t)(by * 128 + aRow) * KP + aCol;
    const uint32_t* BpH = Bh + (size_t)bRow * N + bx * 128 + bCol;
    const uint32_t* BpL = Bl + (size_t)bRow * N + bx * 128 + bCol;

    float acc[4][4][4];
    #pragma unroll
    for (int i = 0; i < 4; i++)
        #pragma unroll
        for (int j = 0; j < 4; j++)
            #pragma unroll
            for (int q = 0; q < 4; q++) acc[i][j][q] = 0.f;

    uint4 pah0 = *(const uint4*)(ApH),     pah1 = *(const uint4*)(ApH + 4);
    uint4 pal0 = *(const uint4*)(ApL),     pal1 = *(const uint4*)(ApL + 4);
    uint4 pbh0 = *(const uint4*)(BpH),     pbh1 = *(const uint4*)(BpH + 4);
    uint4 pbl0 = *(const uint4*)(BpL),     pbl1 = *(const uint4*)(BpL + 4);

    for (int kp0 = 0; kp0 < KP; kp0 += 16) {
        *(uint4*)&sAh[aRow][aCol]     = pah0;  *(uint4*)&sAh[aRow][aCol + 4] = pah1;
        *(uint4*)&sAl[aRow][aCol]     = pal0;  *(uint4*)&sAl[aRow][aCol + 4] = pal1;
        *(uint4*)&sBh[bRow][bCol]     = pbh0;  *(uint4*)&sBh[bRow][bCol + 4] = pbh1;
        *(uint4*)&sBl[bRow][bCol]     = pbl0;  *(uint4*)&sBl[bRow][bCol + 4] = pbl1;
        __syncthreads();

        if (kp0 + 16 < KP) {
            pah0 = *(const uint4*)(ApH + kp0 + 16); pah1 = *(const uint4*)(ApH + kp0 + 20);
            pal0 = *(const uint4*)(ApL + kp0 + 16); pal1 = *(const uint4*)(ApL + kp0 + 20);
            pbh0 = *(const uint4*)(BpH + (size_t)(kp0 + 16) * N);
            pbh1 = *(const uint4*)(BpH + (size_t)(kp0 + 16) * N + 4);
            pbl0 = *(const uint4*)(BpL + (size_t)(kp0 + 16) * N);
            pbl1 = *(const uint4*)(BpL + (size_t)(kp0 + 16) * N + 4);
        }

        #pragma unroll
        for (int kc = 0; kc < 2; kc++) {
            const int kb = kc * 8;
            uint32_t ah[4][4], al[4][4], bh[4][2], bl[4][2];
            #pragma unroll
            for (int i = 0; i < 4; i++) {
                int m0 = wm * 64 + i * 16 + grp;
                ah[i][0] = sAh[m0][kb + tig];       ah[i][1] = sAh[m0 + 8][kb + tig];
                ah[i][2] = sAh[m0][kb + tig + 4];   ah[i][3] = sAh[m0 + 8][kb + tig + 4];
                al[i][0] = sAl[m0][kb + tig];       al[i][1] = sAl[m0 + 8][kb + tig];
                al[i][2] = sAl[m0][kb + tig + 4];   al[i][3] = sAl[m0 + 8][kb + tig + 4];
            }
            #pragma unroll
            for (int j = 0; j < 4; j++) {
                int n = wn * 32 + j * 8 + grp;
                bh[j][0] = sBh[kb + tig][n];  bh[j][1] = sBh[kb + tig + 4][n];
                bl[j][0] = sBl[kb + tig][n];  bl[j][1] = sBl[kb + tig + 4][n];
            }
            #pragma unroll
            for (int i = 0; i < 4; i++)
                #pragma unroll
                for (int j = 0; j < 4; j++) {
                    mma_bf(acc[i][j], ah[i], bh[j]);
                    mma_bf(acc[i][j], ah[i], bl[j]);
                    mma_bf(acc[i][j], al[i], bh[j]);
                }
        }
        __syncthreads();
    }

    #pragma unroll
    for (int i = 0; i < 4; i++) {
        #pragma unroll
        for (int j = 0; j < 4; j++) {
            int row0 = by * 128 + wm * 64 + i * 16 + grp;
            int col0 = bx * 128 + wn * 32 + j * 8 + tig * 2;
            #pragma unroll
            for (int q = 0; q < 4; q++) {
                int row = row0 + (q >> 1) * 8;
                int col = col0 + (q & 1);
                float v = acc[i][j][q] + bias[col];
                if (EPI == 0) {
                    C[(size_t)row * N + col] = v;
                } else {
                    float g = 1.f / (1.f + expf(-v));
                    C[(size_t)row * N + col] =
                        g * e1[(size_t)row * ld1 + col] + (1.f - g) * e2[(size_t)row * ld2 + col];
                }
            }
        }
    }
}

// ----------------------------------------------------------------------------
// SIMT split-K SGEMM for U projection: 4 z-slices of K=256 each, partials.
// ----------------------------------------------------------------------------
__global__ __launch_bounds__(256)
void sgemm_splitk(const float* __restrict__ A, int lda,
                  const float* __restrict__ B, int M, int N)
{
    const int z = blockIdx.z;
    const float* Az = A + z * 256;
    const float* Bz = B + (size_t)(z * 256) * N;
    float* Cz = g_Upart[z];

    __shared__ float As[8][128];
    __shared__ float Bs[8][128];
    const int tid = threadIdx.x;
    const int by = blockIdx.y;
    const int tx = tid & 15, ty = tid >> 4;
    const int aRow = tid >> 1, aCol = (tid & 1) * 4;
    const int bRow = tid >> 5, bCol = (tid & 31) * 4;
    const float* Ap = Az + (size_t)(by * 128 + aRow) * lda + aCol;
    const float* Bp = Bz + (size_t)bRow * N + bCol;

    float acc[8][8];
    #pragma unroll
    for (int i = 0; i < 8; i++)
        #pragma unroll
        for (int j = 0; j < 8; j++) acc[i][j] = 0.f;

    float4 a4 = *(const float4*)(Ap);
    float4 b4 = *(const float4*)(Bp);

    for (int k0 = 0; k0 < 256; k0 += 8) {
        As[aCol + 0][aRow] = a4.x;
        As[aCol + 1][aRow] = a4.y;
        As[aCol + 2][aRow] = a4.z;
        As[aCol + 3][aRow] = a4.w;
        *(float4*)&Bs[bRow][bCol] = b4;
        __syncthreads();
        if (k0 + 8 < 256) {
            a4 = *(const float4*)(Ap + k0 + 8);
            b4 = *(const float4*)(Bp + (size_t)(k0 + 8) * N);
        }
        #pragma unroll
        for (int kk = 0; kk < 8; kk++) {
            float4 a0 = *(const float4*)&As[kk][ty * 8];
            float4 a1 = *(const float4*)&As[kk][ty * 8 + 4];
            float4 b0 = *(const float4*)&Bs[kk][tx * 8];
            float4 b1 = *(const float4*)&Bs[kk][tx * 8 + 4];
            float ar[8] = {a0.x, a0.y, a0.z, a0.w, a1.x, a1.y, a1.z, a1.w};
            float br[8] = {b0.x, b0.y, b0.z, b0.w, b1.x, b1.y, b1.z, b1.w};
            #pragma unroll
            for (int i = 0; i < 8; i++)
                #pragma unroll
                for (int j = 0; j < 8; j++)
                    acc[i][j] = fmaf(ar[i], br[j], acc[i][j]);
        }
        __syncthreads();
    }
    #pragma unroll
    for (int i = 0; i < 8; i++) {
        int row = by * 128 + ty * 8 + i;
        #pragma unroll
        for (int j = 0; j < 8; j++)
            Cz[(size_t)row * N + tx * 8 + j] = acc[i][j];
    }
}

__global__ void ureduce_kernel()
{
    int gid = blockIdx.x * 256 + threadIdx.x;
    if (gid >= M_TOT * 128) return;
    int col = gid & 127;
    g_U[gid] = g_Upart[0][gid] + g_Upart[1][gid] + g_Upart[2][gid] + g_Upart[3][gid]
             + g_ubias[col];
}

// ----------------------------------------------------------------------------
// Precompute Bc (combined input proj) + ubias
// ----------------------------------------------------------------------------
__global__ __launch_bounds__(256)
void combine_proj_kernel(const float* __restrict__ sig_Wr, const float* __restrict__ sig_Wi,
                         const float* __restrict__ A_r, const float* __restrict__ A_i)
{
    __shared__ float sAr[128][16], sAi[128][16];
    __shared__ float sWr[16][128], sWi[16][128];
    const int e = blockIdx.y;
    const int h0 = blockIdx.x * 16;
    const int tid = threadIdx.x;
    const int h_loc = tid >> 4, r = tid & 15;
    float aur = 0.f, aui = 0.f;

    for (int s0 = 0; s0 < S; s0 += 128) {
        for (int i = tid; i < 128 * 16; i += 256) {
            int s = i >> 4, rr = i & 15;
            sAr[s][rr] = A_r[((size_t)e * S + s0 + s) * R + rr];
            sAi[s][rr] = A_i[((size_t)e * S + s0 + s) * R + rr];
        }
        for (int i = tid; i < 16 * 128; i += 256) {
            int hh = i >> 7, ss = i & 127;
            sWr[hh][ss] = sig_Wr[(size_t)(h0 + hh) * S + s0 + ss];
            sWi[hh][ss] = sig_Wi[(size_t)(h0 + hh) * S + s0 + ss];
        }
        __syncthreads();
        #pragma unroll 4
        for (int s = 0; s < 128; s++) {
            float wr = sWr[h_loc][s], wi = sWi[h_loc][s];
            float ar = sAr[s][r],     ai = sAi[s][r];
            aur = fmaf(wr, ar, aur);
            aur = fmaf(-wi, ai, aur);
            aui = fmaf(wr, ai, aui);
            aui = fmaf(wi, ar, aui);
        }
        __syncthreads();
    }
    g_Bc[(size_t)(h0 + h_loc) * 128 + e * 32 + r]      = aur;
    g_Bc[(size_t)(h0 + h_loc) * 128 + e * 32 + 16 + r] = aui;
}

__global__ void ubias_kernel(const float* __restrict__ sig_br, const float* __restrict__ sig_bi,
                             const float* __restrict__ A_r, const float* __restrict__ A_i)
{
    int j = threadIdx.x;
    int e = j >> 5, half = (j >> 4) & 1, r = j & 15;
    float acc = 0.f;
    for (int s = 0; s < S; s++) {
        float ar = A_r[((size_t)e * S + s) * R + r];
        float ai = A_i[((size_t)e * S + s) * R + r];
        float br = sig_br[s], bi = sig_bi[s];
        acc += half ? (br * ai + bi * ar) : (br * ar - bi * ai);
    }
    g_ubias[j] = acc;
}

// ----------------------------------------------------------------------------
// pquv -> WF; crci -> CB; gcg/wg2copy/cgate  (unchanged from round 6)
// ----------------------------------------------------------------------------
__global__ __launch_bounds__(256)
void pquv_kernel(const float* __restrict__ eh_Wr, const float* __restrict__ eh_Wi,
                 const float* __restrict__ fu_Wr, const float* __restrict__ fu_Wi)
{
    __shared__ float2 sA[40][32];
    __shared__ float2 sB[32][64];
    const int e = blockIdx.y;
    const int col0 = blockIdx.x * 64;
    const int tid = threadIdx.x;
    const int c = tid & 63, rg = tid >> 6;
    const int row0 = rg * 10;
    const int nrows = (rg == 3) ? 8 : 10;

    float wc1[10], wc2[10];
    #pragma unroll
    for (int i = 0; i < 10; i++) { wc1[i] = 0.f; wc2[i] = 0.f; }

    for (int k0 = 0; k0 < H; k0 += 32) {
        for (int i = tid; i < FDIM * 32; i += 256) {
            int f = i >> 5, k = i & 31;
            size_t off = ((size_t)e * FDIM + f) * H + k0 + k;
            sA[f][k] = make_float2(eh_Wr[off], eh_Wi[off]);
        }
        for (int i = tid; i < 32 * 64; i += 256) {
            int k = i >> 6, cc = i & 63;
            size_t off = ((size_t)e * H + k0 + k) * H + col0 + cc;
            sB[k][cc] = make_float2(fu_Wr[off], fu_Wi[off]);
        }
        __syncthreads();
        for (int k = 0; k < 32; k++) {
            float2 b = sB[k][c];
            #pragma unroll
            for (int i = 0; i < 10; i++) {
                if (i < nrows) {
                    float2 a = sA[row0 + i][k];
                    wc1[i] = fmaf(a.x, b.x, wc1[i]);
                    wc1[i] = fmaf(-a.y, b.y, wc1[i]);
                    wc2[i] = fmaf(a.x, b.y, wc2[i]);
                    wc2[i] = fmaf(a.y, b.x, wc2[i]);
                }
            }
        }
        __syncthreads();
    }
    #pragma unroll
    for (int i = 0; i < 10; i++) {
        if (i < nrows) {
            int row = row0 + i;
            size_t b1 = (size_t)(e * 76 + row) * 2048;
            size_t b2 = (size_t)(e * 76 + 38 + row) * 2048;
            int cg = col0 + c;
            g_WF[b1 + cg]        = wc1[i];
            g_WF[b1 + 1024 + cg] = wc2[i];
            g_WF[b2 + cg]        = -wc2[i];
            g_WF[b2 + 1024 + cg] = wc1[i];
        }
    }
}

__global__ void crci_part_kernel(const float* __restrict__ eh_br, const float* __restrict__ eh_bi,
                                 const float* __restrict__ fu_Wr, const float* __restrict__ fu_Wi)
{
    const int o = blockIdx.x * 128 + threadIdx.x;
    const int eh0 = blockIdx.y * 128;
    float cr = 0.f, ci = 0.f;
    #pragma unroll 4
    for (int k = 0; k < 128; k++) {
        int eh = eh0 + k;
        float br = eh_br[eh], bi = eh_bi[eh];
        float wr = fu_Wr[(size_t)eh * H + o], wi = fu_Wi[(size_t)eh * H + o];
        cr = fmaf(br, wr, cr); cr = fmaf(-bi, wi, cr);
        ci = fmaf(br, wi, ci); ci = fmaf(bi, wr, ci);
    }
    g_CBpart[blockIdx.y][o]        = cr;
    g_CBpart[blockIdx.y][1024 + o] = ci;
}

__global__ void crci_reduce_kernel(const float* __restrict__ fu_br, const float* __restrict__ fu_bi)
{
    int o = blockIdx.x * 256 + threadIdx.x;
    float acc = (o < 1024) ? fu_br[o] : fu_bi[o - 1024];
    #pragma unroll
    for (int j = 0; j < 32; j++) acc += g_CBpart[j][o];
    g_CB[o] = acc;
}

__global__ void cgate_part_kernel(const float* __restrict__ g_W)
{
    const int o = blockIdx.x * 128 + threadIdx.x;
    const int h0 = blockIdx.y * 128;
    float acc = 0.f;
    #pragma unroll 4
    for (int k = 0; k < 128; k++) {
        int h = h0 + k;
        acc = fmaf(g_CB[h],        g_W[(size_t)(H + h) * H + o],     acc);
        acc = fmaf(g_CB[1024 + h], g_W[(size_t)(2 * H + h) * H + o], acc);
    }
    g_cgpart[blockIdx.y][o] = acc;
}

__global__ void cgate_reduce_kernel(const float* __restrict__ g_b)
{
    int o = blockIdx.x * 256 + threadIdx.x;
    float acc = g_b[o];
    #pragma unroll
    for (int j = 0; j < 8; j++) acc += g_cgpart[j][o];
    g_cgate[o] = acc;
}

__global__ void wg2copy_kernel(const float* __restrict__ g_W)
{
    int idx = blockIdx.x * 256 + threadIdx.x;
    if (idx >= H * H) return;
    g_Wg2[idx] = g_W[idx];
    g_Wg2[(size_t)(H + GDIM) * H + idx] = g_W[(size_t)3 * H * H + idx];
}

__global__ __launch_bounds__(256)
void gcg_kernel(const float* __restrict__ g_W)
{
    __shared__ float sA[40][32];
    __shared__ float sB[32][64];
    const int p0 = blockIdx.y * 38;
    const int col0 = blockIdx.x * 64;
    const int tid = threadIdx.x;
    const int c = tid & 63, rg = tid >> 6;
    const int row0 = rg * 10;
    const int nrows = (rg == 3) ? 8 : 10;

    float acc[10];
    #pragma unroll
    for (int i = 0; i < 10; i++) acc[i] = 0.f;

    for (int k0 = 0; k0 < 2048; k0 += 32) {
        for (int i = tid; i < 38 * 32; i += 256) {
            int pp = i >> 5, k = i & 31;
            sA[pp][k] = g_WF[(size_t)(p0 + pp) * 2048 + k0 + k];
        }
        for (int i = tid; i < 32 * 64; i += 256) {
            int k = i >> 6, cc = i & 63;
            sB[k][cc] = g_W[(size_t)(H + k0 + k) * H + col0 + cc];
        }
        __syncthreads();
        for (int k = 0; k < 32; k++) {
            float b = sB[k][c];
            #pragma unroll
            for (int i = 0; i < 10; i++)
                if (i < nrows)
                    acc[i] = fmaf(sA[row0 + i][k], b, acc[i]);
        }
        __syncthreads();
    }
    #pragma unroll
    for (int i = 0; i < 10; i++)
        if (i < nrows)
            g_Wg2[(size_t)(H + p0 + row0 + i) * H + col0 + c] = acc[i];
}

// ----------------------------------------------------------------------------
// Weight / feature packing to split bf16x2
// ----------------------------------------------------------------------------
__global__ void pack_WF_kernel()
{
    int gid = blockIdx.x * 256 + threadIdx.x;
    if (gid >= KPG * 2048) return;
    int kp = gid / 2048, n = gid % 2048;
    float v0 = 0.f, v1 = 0.f;
    if (kp < GDIM / 2) {
        v0 = g_WF[(size_t)(2 * kp) * 2048 + n];
        v1 = g_WF[(size_t)(2 * kp + 1) * 2048 + n];
    }
    split2(v0, v1, g_WFh[gid], g_WFl[gid]);
}

__global__ void pack_W2_kernel()
{
    int gid = blockIdx.x * 256 + threadIdx.x;
    if (gid >= KPC * H) return;
    int kp = gid / H, n = gid % H;
    float v0 = 0.f, v1 = 0.f;
    if (kp < CCW / 2) {
        v0 = g_Wg2[(size_t)(2 * kp) * H + n];
        v1 = g_Wg2[(size_t)(2 * kp + 1) * H + n];
    }
    split2(v0, v1, g_W2h[gid], g_W2l[gid]);
}

__global__ void pack_G_kernel()
{
    int gid = blockIdx.x * 256 + threadIdx.x;
    if (gid >= M_TOT * KPG) return;
    int m = gid / KPG, kp = gid % KPG;
    float v0 = 0.f, v1 = 0.f;
    if (kp < GDIM / 2) {
        v0 = g_G[(size_t)m * GDIM + 2 * kp];
        v1 = g_G[(size_t)m * GDIM + 2 * kp + 1];
    }
    split2(v0, v1, g_Gh[gid], g_Gl[gid]);
}

// ----------------------------------------------------------------------------
// Recurrence as chunked parallel scan.
// ----------------------------------------------------------------------------
__global__ void recur_p1(const float* __restrict__ lam_r, const float* __restrict__ lam_i)
{
    const int bid = blockIdx.x;
    const int seq = bid >> 5, c = bid & 31;
    const int e = seq >> 2, b = seq & 3;
    const int lane = threadIdx.x;
    if (lane >= R) return;
    const float lr = 0.9f * lam_r[e * R + lane];
    const float li = 0.9f * lam_i[e * R + lane];
    const float* up = g_U + ((size_t)b * T + c * LCH) * 128 + e * 32 + lane;
    float hr = 0.f, hi = 0.f;
    #pragma unroll 4
    for (int s = 0; s < LCH; s++) {
        float ur = up[(size_t)s * 128];
        float ui = up[(size_t)s * 128 + 16];
        float nhr = fmaf(lr, hr, fmaf(-li, hi, ETA * ur));
        float nhi = fmaf(lr, hi, fmaf(li, hr, ETA * ui));
        hr = nhr; hi = nhi;
    }
    g_hloc[seq][c][lane] = make_float2(hr, hi);
}

__global__ void recur_combine(const float* __restrict__ lam_r, const float* __restrict__ lam_i)
{
    int tid = threadIdx.x;          // 256 = 16 seq x 16 lanes
    int seq = tid >> 4, lane = tid & 15;
    int e = seq >> 2;
    float lr = 0.9f * lam_r[e * R + lane];
    float li = 0.9f * lam_i[e * R + lane];
    float pr = 1.f, pi = 0.f;
    for (int k = 0; k < LCH; k++) {
        float nr = pr * lr - pi * li;
        pi = pr * li + pi * lr;
        pr = nr;
    }
    float cr = 0.f, ci = 0.f;
    for (int c = 0; c < NCH; c++) {
        g_hinit[seq][c][lane] = make_float2(cr, ci);
        float2 hl = g_hloc[seq][c][lane];
        float nr = pr * cr - pi * ci + hl.x;
        ci = pr * ci + pi * cr + hl.y;
        cr = nr;
    }
}

__global__ void recur_p2(const float* __restrict__ lam_r, const float* __restrict__ lam_i)
{
    const int bid = blockIdx.x;
    const int seq = bid >> 5, c = bid & 31;
    const int e = seq >> 2, b = seq & 3;
    const int lane = threadIdx.x;
    if (lane >= R) return;

    const float lr = 0.9f * lam_r[e * R + lane];
    const float li = 0.9f * lam_i[e * R + lane];
    const int t0 = c * LCH;
    const float* up = g_U + ((size_t)b * T + t0) * 128 + e * 32 + lane;
    float* gp = g_G + ((size_t)b * T + t0) * GDIM + e * 76;

    float2 h0 = g_hinit[seq][c][lane];
    float hr = h0.x, hi = h0.y, acc = 0.f;
    const unsigned mask = 0xFFFFu;

    float u_r = up[0];
    float u_i = up[16];

    for (int s = 0; s < LCH; s++) {
        int sn = (t0 + s + 1 < T) ? (s + 1) : s;
        float nu_r = up[(size_t)sn * 128];
        float nu_i = up[(size_t)sn * 128 + 16];

        float nhr = lr * hr - li * hi + ETA * u_r;
        float nhi = lr * hi + li * hr + ETA * u_i;
        float m2 = nhr * nhr + nhi * nhi;

        float sm = m2, mx = m2;
        #pragma unroll
        for (int off = 8; off >= 1; off >>= 1) {
            sm += __shfl_xor_sync(mask, sm, off, 16);
            mx = fmaxf(mx, __shfl_xor_sync(mask, mx, off, 16));
        }
        float m_mean = sm * (1.f / 16.f);
        acc = 0.99f * acc + 0.01f * m_mean;
        float inv = rsqrtf(m_mean + EPS);
        float hnr = nhr * inv, hni = nhi * inv;

        float sr = hnr, si = hni;
        #pragma unroll
        for (int off = 8; off >= 1; off >>= 1) {
            sr += __shfl_xor_sync(mask, sr, off, 16);
            si += __shfl_xor_sync(mask, si, off, 16);
        }
        float mr = sr * (1.f / 16.f);
        float mi = si * (1.f / 16.f);

        float* g_t = gp + (size_t)s * GDIM;
        g_t[6 + lane]           = hnr;
        g_t[6 + R + lane]       = hni;
        g_t[38 + 6 + lane]      = hni;
        g_t[38 + 6 + R + lane]  = -hnr;
        if (lane == 0) {
            g_t[0] = mr;
            g_t[1] = mi;
            g_t[2] = sqrtf(m_mean + EPS);
            g_t[3] = sqrtf(mx + EPS);
            // slots 4,5 filled by acc_fix
            g_t[38 + 0] = mi;
            g_t[38 + 1] = -mr;
            g_t[38 + 2] = 0.f; g_t[38 + 3] = 0.f; g_t[38 + 4] = 0.f; g_t[38 + 5] = 0.f;
            g_lacc[seq][t0 + s] = acc;
        }
        hr = nhr; hi = nhi;
        u_r = nu_r; u_i = nu_i;
    }
    if (lane == 0) g_accend[seq][c] = acc;
}

__global__ void acc_combine_kernel()
{
    int seq = threadIdx.x;   // 16
    if (seq >= 16) return;
    float p = 1.f;
    for (int k = 0; k < LCH; k++) p *= 0.99f;
    float A = 0.f;
    for (int c = 0; c < NCH; c++) {
        g_accinit[seq][c] = A;
        A = p * A + g_accend[seq][c];
    }
}

__global__ void acc_fix_kernel()
{
    int gid = blockIdx.x * 256 + threadIdx.x;   // 16 * 2048
    if (gid >= 16 * T) return;
    int seq = gid >> 11;
    int t = gid & (T - 1);
    int c = t >> 6;
    int k = (t & (LCH - 1)) + 1;
    float acc = __powf(0.99f, (float)k) * g_accinit[seq][c] + g_lacc[seq][t];
    int e = seq >> 2, b = seq & 3;
    float* g_t = g_G + ((size_t)b * T + t) * GDIM + e * 76;
    g_t[4] = acc;
    g_t[5] = log1pf(acc);
}

// ----------------------------------------------------------------------------
// Gate concat, written directly as split bf16x2 pairs.
// ----------------------------------------------------------------------------
__global__ void concat2_kernel(const float* __restrict__ x)
{
    const int row = blockIdx.x;
    const float* xr = x + (size_t)row * H;
    const float* gr = g_G + (size_t)row * GDIM;
    const float* fr = g_FRF + (size_t)row * 2048;
    uint32_t* dh = g_CCh + (size_t)row * KPC;
    uint32_t* dl = g_CCl + (size_t)row * KPC;

    for (int kp = threadIdx.x; kp < KPC; kp += 256) {
        float v0, v1;
        if (kp < 512) {                       // x: c in [0,1024)
            v0 = xr[2 * kp]; v1 = xr[2 * kp + 1];
        } else if (kp < 664) {                // G: c in [1024,1328)
            int cg = 2 * kp - 1024;
            v0 = gr[cg]; v1 = gr[cg + 1];
        } else if (kp < 1176) {               // mag: c in [1328,2352)
            int h = 2 * kp - 1328;
            float a0 = fr[h],     b0 = fr[1024 + h];
            float a1 = fr[h + 1], b1 = fr[1024 + h + 1];
            v0 = sqrtf(a0 * a0 + b0 * b0 + EPS);
            v1 = sqrtf(a1 * a1 + b1 * b1 + EPS);
        } else {                              // pad
            v0 = 0.f; v1 = 0.f;
        }
        split2(v0, v1, dh[kp], dl[kp]);
    }
}

// ----------------------------------------------------------------------------
// Launch
// ----------------------------------------------------------------------------
extern "C" void kernel_launch(void* const* d_in, const int* in_sizes, int n_in,
                              void* d_out, int out_size)
{
    const float* x      = (const float*)d_in[0];
    const float* sig_Wr = (const float*)d_in[1];
    const float* sig_Wi = (const float*)d_in[2];
    const float* sig_br = (const float*)d_in[3];
    const float* sig_bi = (const float*)d_in[4];
    const float* A_r    = (const float*)d_in[5];
    const float* A_i    = (const float*)d_in[6];
    const float* lam_r  = (const float*)d_in[7];
    const float* lam_i  = (const float*)d_in[8];
    const float* eh_Wr  = (const float*)d_in[9];
    const float* eh_Wi  = (const float*)d_in[10];
    const float* eh_br  = (const float*)d_in[11];
    const float* eh_bi  = (const float*)d_in[12];
    const float* fu_Wr  = (const float*)d_in[13];
    const float* fu_Wi  = (const float*)d_in[14];
    const float* fu_br  = (const float*)d_in[15];
    const float* fu_bi  = (const float*)d_in[16];
    const float* gW     = (const float*)d_in[17];
    const float* gb     = (const float*)d_in[18];
    float* out = (float*)d_out;

    float *Bc, *FRF, *CB, *cgate;
    uint32_t *Gh, *Gl, *WFh, *WFl, *CCh, *CCl, *W2h, *W2l;
    cudaGetSymbolAddress((void**)&Bc,    g_Bc);
    cudaGetSymbolAddress((void**)&FRF,   g_FRF);
    cudaGetSymbolAddress((void**)&CB,    g_CB);
    cudaGetSymbolAddress((void**)&cgate, g_cgate);
    cudaGetSymbolAddress((void**)&Gh,    g_Gh);
    cudaGetSymbolAddress((void**)&Gl,    g_Gl);
    cudaGetSymbolAddress((void**)&WFh,   g_WFh);
    cudaGetSymbolAddress((void**)&WFl,   g_WFl);
    cudaGetSymbolAddress((void**)&CCh,   g_CCh);
    cudaGetSymbolAddress((void**)&CCl,   g_CCl);
    cudaGetSymbolAddress((void**)&W2h,   g_W2h);
    cudaGetSymbolAddress((void**)&W2l,   g_W2l);

    // --- precompute (weight composition) ---
    combine_proj_kernel<<<dim3(64, E), 256>>>(sig_Wr, sig_Wi, A_r, A_i);
    ubias_kernel<<<1, 128>>>(sig_br, sig_bi, A_r, A_i);
    pquv_kernel<<<dim3(H / 64, E), 256>>>(eh_Wr, eh_Wi, fu_Wr, fu_Wi);
    crci_part_kernel<<<dim3(8, 32), 128>>>(eh_br, eh_bi, fu_Wr, fu_Wi);
    crci_reduce_kernel<<<8, 256>>>(fu_br, fu_bi);
    pack_WF_kernel<<<(KPG * 2048 + 255) / 256, 256>>>();
    wg2copy_kernel<<<(H * H + 255) / 256, 256>>>(gW);
    gcg_kernel<<<dim3(H / 64, 8), 256>>>(gW);
    pack_W2_kernel<<<(KPC * H + 255) / 256, 256>>>();
    cgate_part_kernel<<<dim3(8, 8), 128>>>(gW);
    cgate_reduce_kernel<<<4, 256>>>(gb);

    // --- main path ---
    // U = x @ Bc + ubias (split-K)
    sgemm_splitk<<<dim3(1, M_TOT / 128, 4), 256>>>(x, H, Bc, M_TOT, 128);
    ureduce_kernel<<<(M_TOT * 128 + 255) / 256, 256>>>();
    // recurrence scan -> G
    recur_p1<<<16 * NCH, 32>>>(lam_r, lam_i);
    recur_combine<<<1, 256>>>(lam_r, lam_i);
    recur_p2<<<16 * NCH, 32>>>(lam_r, lam_i);
    acc_combine_kernel<<<1, 16>>>();
    acc_fix_kernel<<<(16 * T + 255) / 256, 256>>>();
    // pack G and run FRF GEMM: FRF = G @ WF + CB
    pack_G_kernel<<<(M_TOT * KPG + 255) / 256, 256>>>();
    mma_bf16<0><<<dim3(2048 / 128, M_TOT / 128), 256>>>(Gh, Gl, WFh, WFl, FRF,
                                                        M_TOT, 2048, KPG, CB,
                                                        nullptr, 0, nullptr, 0);
    // concat (packed) and gate GEMM -> out
    concat2_kernel<<<M_TOT, 256>>>(x);
    mma_bf16<1><<<dim3(H / 128, M_TOT / 128), 256>>>(CCh, CCl, W2h, W2l, out,
                                                     M_TOT, H, KPC, cgate,
                                                     FRF, 2048, x, H);
}

// round 10
// speedup vs baseline: 7.4400x; 1.0386x over previous
#include <cuda_runtime.h>
#include <cuda_bf16.h>
#include <math.h>
#include <stdint.h>

#define BSZ 4
#define T 2048
#define H 1024
#define S 512
#define R 16
#define E 4
#define FDIM 38             // 6 + 2*R
#define M_TOT (BSZ*T)       // 8192
#define GDIM (E*2*FDIM)     // 304
#define CCW (H + GDIM + H)  // 2352
#define KEG 320             // padded K for FRF GEMM
#define KEC 2368            // padded K for gate GEMM
#define KPG (KEG/2)
#define KPC (KEC/2)
#define NCH 32
#define LCH 64
#define ETA 0.1f
#define EPS 1e-6f

// ----------------------------------------------------------------------------
// Scratch
// ----------------------------------------------------------------------------
__device__ float g_Bc[H * 128];
__device__ float g_ubias[128];
__device__ float g_Upart[4][M_TOT * 128];
__device__ float g_U[M_TOT * 128];
__device__ float g_G[(size_t)M_TOT * GDIM];
__device__ float g_WF[(size_t)GDIM * 2048];
__device__ float g_CB[2048];
__device__ float g_CBpart[32][2048];
__device__ float g_cgpart[8][1024];
__device__ float g_FRF[(size_t)M_TOT * 2048];
__device__ float g_Wg2[(size_t)CCW * H];
__device__ float g_cgate[H];
// split bf16 operands, K-contiguous rows (u32 = 2 adjacent-K bf16)
__device__ uint32_t g_Gh[(size_t)M_TOT * KPG];     // A for FRF  [M][KPG]
__device__ uint32_t g_Gl[(size_t)M_TOT * KPG];
__device__ uint32_t g_WFh[(size_t)2048 * KPG];     // B for FRF  [N][KPG]
__device__ uint32_t g_WFl[(size_t)2048 * KPG];
__device__ uint32_t g_CCh[(size_t)M_TOT * KPC];    // A for gate [M][KPC]
__device__ uint32_t g_CCl[(size_t)M_TOT * KPC];
__device__ uint32_t g_W2h[(size_t)1024 * KPC];     // B for gate [N][KPC]
__device__ uint32_t g_W2l[(size_t)1024 * KPC];
// recurrence scan state
__device__ float2 g_hloc[16][NCH][16];
__device__ float2 g_hinit[16][NCH][16];
__device__ float g_lacc[16][T];
__device__ float g_accend[16][NCH];
__device__ float g_accinit[16][NCH];

// ----------------------------------------------------------------------------
// helpers
// ----------------------------------------------------------------------------
__device__ __forceinline__ void split2(float v0, float v1, uint32_t& ph, uint32_t& pl)
{
    __nv_bfloat162 h2 = __floats2bfloat162_rn(v0, v1);
    float r0 = v0 - __bfloat162float(h2.x);
    float r1 = v1 - __bfloat162float(h2.y);
    __nv_bfloat162 l2 = __floats2bfloat162_rn(r0, r1);
    ph = *reinterpret_cast<uint32_t*>(&h2);
    pl = *reinterpret_cast<uint32_t*>(&l2);
}

__device__ __forceinline__ uint32_t smem_u32_of(const void* p)
{
    uint32_t a;
    asm("{ .reg .u64 t; cvta.to.shared.u64 t, %1; cvt.u32.u64 %0, t; }" : "=r"(a) : "l"(p));
    return a;
}

__device__ __forceinline__ void mma_bf(float* d, const uint32_t* a, const uint32_t* b)
{
    asm volatile(
        "mma.sync.aligned.m16n8k16.row.col.f32.bf16.bf16.f32 "
        "{%0,%1,%2,%3}, {%4,%5,%6,%7}, {%8,%9}, {%0,%1,%2,%3};"
        : "+f"(d[0]), "+f"(d[1]), "+f"(d[2]), "+f"(d[3])
        : "r"(a[0]), "r"(a[1]), "r"(a[2]), "r"(a[3]), "r"(b[0]), "r"(b[1]));
}

// pipelined-GEMM smem geometry
#define NSTG 3
#define ROWU 12                      // u32 per smem row: 8 data + 4 pad (48B, 16B-aligned)
#define TILE_U (128 * ROWU)          // 1536 u32 = 6 KB
#define STG_U (4 * TILE_U)           // 6144 u32 = 24 KB
#define SMEMT (NSTG * STG_U * 4)     // 73728 B

// ----------------------------------------------------------------------------
// Pipelined bf16 split GEMM (legacy mma.sync, cp.async 3-stage):
// C[M,N] = A[M,KE] @ Bt[N,KE]^T + bias.
// A/Bt as split bf16 hi/lo u32 arrays, K-contiguous rows, KE mult of 16.
// grid (N/128, M/128), 256 thr, warps 2x4 (64m x 32n each).
// EPI==1: g = sigmoid(v); C = g*e1 + (1-g)*e2
// ----------------------------------------------------------------------------
template<int EPI>
__global__ __launch_bounds__(256)
void tc_gemm(const uint32_t* __restrict__ Ah, const uint32_t* __restrict__ Al,
             const uint32_t* __restrict__ Bh, const uint32_t* __restrict__ Bl,
             float* __restrict__ C, int M, int N, int KE,
             const float* __restrict__ bias,
             const float* __restrict__ e1, int ld1,
             const float* __restrict__ e2, int ld2)
{
    extern __shared__ uint32_t sm[];
    const uint32_t smem_base = smem_u32_of(sm);
    const int tid = threadIdx.x;
    const int wid = tid >> 5, lane = tid & 31;
    const int wm = wid & 1, wn = wid >> 1;
    const int grp = lane >> 2, tig = lane & 3;
    const int bx = blockIdx.x, by = blockIdx.y;
    const int KP = KE >> 1;
    const int NC = KE >> 4;          // 16-elem (8 u32) chunks

    // cp.async assignment: each thread copies one 16B unit per tile per chunk
    const int crow = tid >> 1, c16 = tid & 1;
    const uint32_t* gsrc0 = Ah + (size_t)(by * 128 + crow) * KP + c16 * 4;
    const uint32_t* gsrc1 = Al + (size_t)(by * 128 + crow) * KP + c16 * 4;
    const uint32_t* gsrc2 = Bh + (size_t)(bx * 128 + crow) * KP + c16 * 4;
    const uint32_t* gsrc3 = Bl + (size_t)(bx * 128 + crow) * KP + c16 * 4;
    const uint32_t dst0 = smem_base + (crow * ROWU + c16 * 4) * 4;

    float acc[4][4][4];
    #pragma unroll
    for (int i = 0; i < 4; i++)
        #pragma unroll
        for (int j = 0; j < 4; j++)
            #pragma unroll
            for (int q = 0; q < 4; q++) acc[i][j][q] = 0.f;

#define ISSUE(chunk) do { \
        uint32_t db_ = dst0 + ((chunk) % NSTG) * (STG_U * 4); \
        const uint32_t* s0_ = gsrc0 + (chunk) * 8; \
        const uint32_t* s1_ = gsrc1 + (chunk) * 8; \
        const uint32_t* s2_ = gsrc2 + (chunk) * 8; \
        const uint32_t* s3_ = gsrc3 + (chunk) * 8; \
        asm volatile("cp.async.cg.shared.global [%0], [%1], 16;" :: "r"(db_),                  "l"(s0_)); \
        asm volatile("cp.async.cg.shared.global [%0], [%1], 16;" :: "r"(db_ + TILE_U * 4),     "l"(s1_)); \
        asm volatile("cp.async.cg.shared.global [%0], [%1], 16;" :: "r"(db_ + 2 * TILE_U * 4), "l"(s2_)); \
        asm volatile("cp.async.cg.shared.global [%0], [%1], 16;" :: "r"(db_ + 3 * TILE_U * 4), "l"(s3_)); \
        asm volatile("cp.async.commit_group;"); \
    } while (0)

    ISSUE(0);
    ISSUE(1);

    for (int i = 0; i < NC; i++) {
        // chunk i must be complete before reading. While more chunks remain in
        // flight (i+1 committed), one group may stay pending; on the FINAL
        // iteration the only pending group is chunk i itself -> wait_group 0.
        if (i + 1 < NC) asm volatile("cp.async.wait_group 1;");
        else            asm volatile("cp.async.wait_group 0;");
        __syncthreads();
        if (i + 2 < NC) ISSUE(i + 2);

        const uint32_t stu = (i % NSTG) * STG_U;
        const uint32_t tAh = stu, tAl = stu + TILE_U;
        const uint32_t tBh = stu + 2 * TILE_U, tBl = stu + 3 * TILE_U;

        // B fragments for all 4 j-tiles
        uint32_t bh[4][2], bl[4][2];
        #pragma unroll
        for (int j = 0; j < 4; j++) {
            int rn = (wn * 32 + j * 8 + grp) * ROWU;
            bh[j][0] = sm[tBh + rn + tig];
            bh[j][1] = sm[tBh + rn + tig + 4];
            bl[j][0] = sm[tBl + rn + tig];
            bl[j][1] = sm[tBl + rn + tig + 4];
        }
        #pragma unroll
        for (int ii = 0; ii < 4; ii++) {
            int ra = (wm * 64 + ii * 16 + grp) * ROWU;
            int rb = ra + 8 * ROWU;
            uint32_t ah[4], al[4];
            ah[0] = sm[tAh + ra + tig];
            ah[1] = sm[tAh + rb + tig];
            ah[2] = sm[tAh + ra + tig + 4];
            ah[3] = sm[tAh + rb + tig + 4];
            al[0] = sm[tAl + ra + tig];
            al[1] = sm[tAl + rb + tig];
            al[2] = sm[tAl + ra + tig + 4];
            al[3] = sm[tAl + rb + tig + 4];
            #pragma unroll
            for (int j = 0; j < 4; j++) {
                mma_bf(acc[ii][j], ah, bh[j]);
                mma_bf(acc[ii][j], ah, bl[j]);
                mma_bf(acc[ii][j], al, bh[j]);
            }
        }
    }
#undef ISSUE

    #pragma unroll
    for (int i = 0; i < 4; i++) {
        #pragma unroll
        for (int j = 0; j < 4; j++) {
            int row0 = by * 128 + wm * 64 + i * 16 + grp;
            int col0 = bx * 128 + wn * 32 + j * 8 + tig * 2;
            #pragma unroll
            for (int q = 0; q < 4; q++) {
                int row = row0 + (q >> 1) * 8;
                int col = col0 + (q & 1);
                float v = acc[i][j][q] + bias[col];
                if (EPI == 0) {
                    C[(size_t)row * N + col] = v;
                } else {
                    float g = 1.f / (1.f + expf(-v));
                    C[(size_t)row * N + col] =
                        g * e1[(size_t)row * ld1 + col] + (1.f - g) * e2[(size_t)row * ld2 + col];
                }
            }
        }
    }
}

// ----------------------------------------------------------------------------
// transpose-pack: src fp32 [K][N] -> dst bf16 hi/lo [N][KP2] u32 pairs
// ----------------------------------------------------------------------------
__global__ void tpack_kernel(const float* __restrict__ src, int K, int N, int KP2,
                             uint32_t* __restrict__ dh, uint32_t* __restrict__ dl)
{
    __shared__ float tile[32][33];
    const int n0 = blockIdx.x * 32;
    const int k0 = blockIdx.y * 32;
    const int tx = threadIdx.x, ty = threadIdx.y;
    #pragma unroll
    for (int j = 0; j < 32; j += 8) {
        int k = k0 + ty + j;
        tile[ty + j][tx] = (k < K) ? src[(size_t)k * N + n0 + tx] : 0.f;
    }
    __syncthreads();
    int t = ty * 32 + tx;
    #pragma unroll
    for (int s = 0; s < 2; s++) {
        int idx = t + s * 256;
        int n = idx >> 4;
        int kp = idx & 15;
        float v0 = tile[2 * kp][n], v1 = tile[2 * kp + 1][n];
        uint32_t h, l;
        split2(v0, v1, h, l);
        size_t o = (size_t)(n0 + n) * KP2 + (k0 >> 1) + kp;
        dh[o] = h;
        dl[o] = l;
    }
}

// ----------------------------------------------------------------------------
// SIMT split-K SGEMM for U projection
// ----------------------------------------------------------------------------
__global__ __launch_bounds__(256)
void sgemm_splitk(const float* __restrict__ A, int lda,
                  const float* __restrict__ B, int M, int N)
{
    const int z = blockIdx.z;
    const float* Az = A + z * 256;
    const float* Bz = B + (size_t)(z * 256) * N;
    float* Cz = g_Upart[z];

    __shared__ float As[8][128];
    __shared__ float Bs[8][128];
    const int tid = threadIdx.x;
    const int by = blockIdx.y;
    const int tx = tid & 15, ty = tid >> 4;
    const int aRow = tid >> 1, aCol = (tid & 1) * 4;
    const int bRow = tid >> 5, bCol = (tid & 31) * 4;
    const float* Ap = Az + (size_t)(by * 128 + aRow) * lda + aCol;
    const float* Bp = Bz + (size_t)bRow * N + bCol;

    float acc[8][8];
    #pragma unroll
    for (int i = 0; i < 8; i++)
        #pragma unroll
        for (int j = 0; j < 8; j++) acc[i][j] = 0.f;

    float4 a4 = *(const float4*)(Ap);
    float4 b4 = *(const float4*)(Bp);

    for (int k0 = 0; k0 < 256; k0 += 8) {
        As[aCol + 0][aRow] = a4.x;
        As[aCol + 1][aRow] = a4.y;
        As[aCol + 2][aRow] = a4.z;
        As[aCol + 3][aRow] = a4.w;
        *(float4*)&Bs[bRow][bCol] = b4;
        __syncthreads();
        if (k0 + 8 < 256) {
            a4 = *(const float4*)(Ap + k0 + 8);
            b4 = *(const float4*)(Bp + (size_t)(k0 + 8) * N);
        }
        #pragma unroll
        for (int kk = 0; kk < 8; kk++) {
            float4 a0 = *(const float4*)&As[kk][ty * 8];
            float4 a1 = *(const float4*)&As[kk][ty * 8 + 4];
            float4 b0 = *(const float4*)&Bs[kk][tx * 8];
            float4 b1 = *(const float4*)&Bs[kk][tx * 8 + 4];
            float ar[8] = {a0.x, a0.y, a0.z, a0.w, a1.x, a1.y, a1.z, a1.w};
            float br[8] = {b0.x, b0.y, b0.z, b0.w, b1.x, b1.y, b1.z, b1.w};
            #pragma unroll
            for (int i = 0; i < 8; i++)
                #pragma unroll
                for (int j = 0; j < 8; j++)
                    acc[i][j] = fmaf(ar[i], br[j], acc[i][j]);
        }
        __syncthreads();
    }
    #pragma unroll
    for (int i = 0; i < 8; i++) {
        int row = by * 128 + ty * 8 + i;
        #pragma unroll
        for (int j = 0; j < 8; j++)
            Cz[(size_t)row * N + tx * 8 + j] = acc[i][j];
    }
}

__global__ void ureduce_kernel()
{
    int gid = blockIdx.x * 256 + threadIdx.x;
    if (gid >= M_TOT * 128) return;
    int col = gid & 127;
    g_U[gid] = g_Upart[0][gid] + g_Upart[1][gid] + g_Upart[2][gid] + g_Upart[3][gid]
             + g_ubias[col];
}

// ----------------------------------------------------------------------------
// Precompute Bc + ubias
// ----------------------------------------------------------------------------
__global__ __launch_bounds__(256)
void combine_proj_kernel(const float* __restrict__ sig_Wr, const float* __restrict__ sig_Wi,
                         const float* __restrict__ A_r, const float* __restrict__ A_i)
{
    __shared__ float sAr[128][16], sAi[128][16];
    __shared__ float sWr[16][128], sWi[16][128];
    const int e = blockIdx.y;
    const int h0 = blockIdx.x * 16;
    const int tid = threadIdx.x;
    const int h_loc = tid >> 4, r = tid & 15;
    float aur = 0.f, aui = 0.f;

    for (int s0 = 0; s0 < S; s0 += 128) {
        for (int i = tid; i < 128 * 16; i += 256) {
            int s = i >> 4, rr = i & 15;
            sAr[s][rr] = A_r[((size_t)e * S + s0 + s) * R + rr];
            sAi[s][rr] = A_i[((size_t)e * S + s0 + s) * R + rr];
        }
        for (int i = tid; i < 16 * 128; i += 256) {
            int hh = i >> 7, ss = i & 127;
            sWr[hh][ss] = sig_Wr[(size_t)(h0 + hh) * S + s0 + ss];
            sWi[hh][ss] = sig_Wi[(size_t)(h0 + hh) * S + s0 + ss];
        }
        __syncthreads();
        #pragma unroll 4
        for (int s = 0; s < 128; s++) {
            float wr = sWr[h_loc][s], wi = sWi[h_loc][s];
            float ar = sAr[s][r],     ai = sAi[s][r];
            aur = fmaf(wr, ar, aur);
            aur = fmaf(-wi, ai, aur);
            aui = fmaf(wr, ai, aui);
            aui = fmaf(wi, ar, aui);
        }
        __syncthreads();
    }
    g_Bc[(size_t)(h0 + h_loc) * 128 + e * 32 + r]      = aur;
    g_Bc[(size_t)(h0 + h_loc) * 128 + e * 32 + 16 + r] = aui;
}

__global__ void ubias_kernel(const float* __restrict__ sig_br, const float* __restrict__ sig_bi,
                             const float* __restrict__ A_r, const float* __restrict__ A_i)
{
    int j = threadIdx.x;
    int e = j >> 5, half = (j >> 4) & 1, r = j & 15;
    float acc = 0.f;
    for (int s = 0; s < S; s++) {
        float ar = A_r[((size_t)e * S + s) * R + r];
        float ai = A_i[((size_t)e * S + s) * R + r];
        float br = sig_br[s], bi = sig_bi[s];
        acc += half ? (br * ai + bi * ar) : (br * ar - bi * ai);
    }
    g_ubias[j] = acc;
}

// ----------------------------------------------------------------------------
// pquv / crci / cgate / wg2copy / gcg
// ----------------------------------------------------------------------------
__global__ __launch_bounds__(256)
void pquv_kernel(const float* __restrict__ eh_Wr, const float* __restrict__ eh_Wi,
                 const float* __restrict__ fu_Wr, const float* __restrict__ fu_Wi)
{
    __shared__ float2 sA[40][32];
    __shared__ float2 sB[32][64];
    const int e = blockIdx.y;
    const int col0 = blockIdx.x * 64;
    const int tid = threadIdx.x;
    const int c = tid & 63, rg = tid >> 6;
    const int row0 = rg * 10;
    const int nrows = (rg == 3) ? 8 : 10;

    float wc1[10], wc2[10];
    #pragma unroll
    for (int i = 0; i < 10; i++) { wc1[i] = 0.f; wc2[i] = 0.f; }

    for (int k0 = 0; k0 < H; k0 += 32) {
        for (int i = tid; i < FDIM * 32; i += 256) {
            int f = i >> 5, k = i & 31;
            size_t off = ((size_t)e * FDIM + f) * H + k0 + k;
            sA[f][k] = make_float2(eh_Wr[off], eh_Wi[off]);
        }
        for (int i = tid; i < 32 * 64; i += 256) {
            int k = i >> 6, cc = i & 63;
            size_t off = ((size_t)e * H + k0 + k) * H + col0 + cc;
            sB[k][cc] = make_float2(fu_Wr[off], fu_Wi[off]);
        }
        __syncthreads();
        for (int k = 0; k < 32; k++) {
            float2 b = sB[k][c];
            #pragma unroll
            for (int i = 0; i < 10; i++) {
                if (i < nrows) {
                    float2 a = sA[row0 + i][k];
                    wc1[i] = fmaf(a.x, b.x, wc1[i]);
                    wc1[i] = fmaf(-a.y, b.y, wc1[i]);
                    wc2[i] = fmaf(a.x, b.y, wc2[i]);
                    wc2[i] = fmaf(a.y, b.x, wc2[i]);
                }
            }
        }
        __syncthreads();
    }
    #pragma unroll
    for (int i = 0; i < 10; i++) {
        if (i < nrows) {
            int row = row0 + i;
            size_t b1 = (size_t)(e * 76 + row) * 2048;
            size_t b2 = (size_t)(e * 76 + 38 + row) * 2048;
            int cg = col0 + c;
            g_WF[b1 + cg]        = wc1[i];
            g_WF[b1 + 1024 + cg] = wc2[i];
            g_WF[b2 + cg]        = -wc2[i];
            g_WF[b2 + 1024 + cg] = wc1[i];
        }
    }
}

__global__ void crci_part_kernel(const float* __restrict__ eh_br, const float* __restrict__ eh_bi,
                                 const float* __restrict__ fu_Wr, const float* __restrict__ fu_Wi)
{
    const int o = blockIdx.x * 128 + threadIdx.x;
    const int eh0 = blockIdx.y * 128;
    float cr = 0.f, ci = 0.f;
    #pragma unroll 4
    for (int k = 0; k < 128; k++) {
        int eh = eh0 + k;
        float br = eh_br[eh], bi = eh_bi[eh];
        float wr = fu_Wr[(size_t)eh * H + o], wi = fu_Wi[(size_t)eh * H + o];
        cr = fmaf(br, wr, cr); cr = fmaf(-bi, wi, cr);
        ci = fmaf(br, wi, ci); ci = fmaf(bi, wr, ci);
    }
    g_CBpart[blockIdx.y][o]        = cr;
    g_CBpart[blockIdx.y][1024 + o] = ci;
}

__global__ void crci_reduce_kernel(const float* __restrict__ fu_br, const float* __restrict__ fu_bi)
{
    int o = blockIdx.x * 256 + threadIdx.x;
    float acc = (o < 1024) ? fu_br[o] : fu_bi[o - 1024];
    #pragma unroll
    for (int j = 0; j < 32; j++) acc += g_CBpart[j][o];
    g_CB[o] = acc;
}

__global__ void cgate_part_kernel(const float* __restrict__ g_W)
{
    const int o = blockIdx.x * 128 + threadIdx.x;
    const int h0 = blockIdx.y * 128;
    float acc = 0.f;
    #pragma unroll 4
    for (int k = 0; k < 128; k++) {
        int h = h0 + k;
        acc = fmaf(g_CB[h],        g_W[(size_t)(H + h) * H + o],     acc);
        acc = fmaf(g_CB[1024 + h], g_W[(size_t)(2 * H + h) * H + o], acc);
    }
    g_cgpart[blockIdx.y][o] = acc;
}

__global__ void cgate_reduce_kernel(const float* __restrict__ g_b)
{
    int o = blockIdx.x * 256 + threadIdx.x;
    float acc = g_b[o];
    #pragma unroll
    for (int j = 0; j < 8; j++) acc += g_cgpart[j][o];
    g_cgate[o] = acc;
}

__global__ void wg2copy_kernel(const float* __restrict__ g_W)
{
    int idx = blockIdx.x * 256 + threadIdx.x;
    if (idx >= H * H) return;
    g_Wg2[idx] = g_W[idx];
    g_Wg2[(size_t)(H + GDIM) * H + idx] = g_W[(size_t)3 * H * H + idx];
}

__global__ __launch_bounds__(256)
void gcg_kernel(const float* __restrict__ g_W)
{
    __shared__ float sA[40][32];
    __shared__ float sB[32][64];
    const int p0 = blockIdx.y * 38;
    const int col0 = blockIdx.x * 64;
    const int tid = threadIdx.x;
    const int c = tid & 63, rg = tid >> 6;
    const int row0 = rg * 10;
    const int nrows = (rg == 3) ? 8 : 10;

    float acc[10];
    #pragma unroll
    for (int i = 0; i < 10; i++) acc[i] = 0.f;

    for (int k0 = 0; k0 < 2048; k0 += 32) {
        for (int i = tid; i < 38 * 32; i += 256) {
            int pp = i >> 5, k = i & 31;
            sA[pp][k] = g_WF[(size_t)(p0 + pp) * 2048 + k0 + k];
        }
        for (int i = tid; i < 32 * 64; i += 256) {
            int k = i >> 6, cc = i & 63;
            sB[k][cc] = g_W[(size_t)(H + k0 + k) * H + col0 + cc];
        }
        __syncthreads();
        for (int k = 0; k < 32; k++) {
            float b = sB[k][c];
            #pragma unroll
            for (int i = 0; i < 10; i++)
                if (i < nrows)
                    acc[i] = fmaf(sA[row0 + i][k], b, acc[i]);
        }
        __syncthreads();
    }
    #pragma unroll
    for (int i = 0; i < 10; i++)
        if (i < nrows)
            g_Wg2[(size_t)(H + p0 + row0 + i) * H + col0 + c] = acc[i];
}

// ----------------------------------------------------------------------------
// A-side packing
// ----------------------------------------------------------------------------
__global__ void pack_G_kernel()
{
    int gid = blockIdx.x * 256 + threadIdx.x;
    if (gid >= M_TOT * KPG) return;
    int m = gid / KPG, kp = gid % KPG;
    float v0 = 0.f, v1 = 0.f;
    if (kp < GDIM / 2) {
        v0 = g_G[(size_t)m * GDIM + 2 * kp];
        v1 = g_G[(size_t)m * GDIM + 2 * kp + 1];
    }
    split2(v0, v1, g_Gh[gid], g_Gl[gid]);
}

__global__ void concat2_kernel(const float* __restrict__ x)
{
    const int row = blockIdx.x;
    const float* xr = x + (size_t)row * H;
    const float* gr = g_G + (size_t)row * GDIM;
    const float* fr = g_FRF + (size_t)row * 2048;
    uint32_t* dh = g_CCh + (size_t)row * KPC;
    uint32_t* dl = g_CCl + (size_t)row * KPC;

    for (int kp = threadIdx.x; kp < KPC; kp += 256) {
        float v0, v1;
        if (kp < 512) {
            v0 = xr[2 * kp]; v1 = xr[2 * kp + 1];
        } else if (kp < 664) {
            int cg = 2 * kp - 1024;
            v0 = gr[cg]; v1 = gr[cg + 1];
        } else if (kp < 1176) {
            int h = 2 * kp - 1328;
            float a0 = fr[h],     b0 = fr[1024 + h];
            float a1 = fr[h + 1], b1 = fr[1024 + h + 1];
            v0 = sqrtf(a0 * a0 + b0 * b0 + EPS);
            v1 = sqrtf(a1 * a1 + b1 * b1 + EPS);
        } else {
            v0 = 0.f; v1 = 0.f;
        }
        split2(v0, v1, dh[kp], dl[kp]);
    }
}

// ----------------------------------------------------------------------------
// Recurrence as chunked parallel scan
// ----------------------------------------------------------------------------
__global__ void recur_p1(const float* __restrict__ lam_r, const float* __restrict__ lam_i)
{
    const int bid = blockIdx.x;
    const int seq = bid >> 5, c = bid & 31;
    const int e = seq >> 2, b = seq & 3;
    const int lane = threadIdx.x;
    if (lane >= R) return;
    const float lr = 0.9f * lam_r[e * R + lane];
    const float li = 0.9f * lam_i[e * R + lane];
    const float* up = g_U + ((size_t)b * T + c * LCH) * 128 + e * 32 + lane;
    float hr = 0.f, hi = 0.f;
    #pragma unroll 4
    for (int s = 0; s < LCH; s++) {
        float ur = up[(size_t)s * 128];
        float ui = up[(size_t)s * 128 + 16];
        float nhr = fmaf(lr, hr, fmaf(-li, hi, ETA * ur));
        float nhi = fmaf(lr, hi, fmaf(li, hr, ETA * ui));
        hr = nhr; hi = nhi;
    }
    g_hloc[seq][c][lane] = make_float2(hr, hi);
}

__global__ void recur_combine(const float* __restrict__ lam_r, const float* __restrict__ lam_i)
{
    int tid = threadIdx.x;
    int seq = tid >> 4, lane = tid & 15;
    int e = seq >> 2;
    float lr = 0.9f * lam_r[e * R + lane];
    float li = 0.9f * lam_i[e * R + lane];
    float pr = 1.f, pi = 0.f;
    for (int k = 0; k < LCH; k++) {
        float nr = pr * lr - pi * li;
        pi = pr * li + pi * lr;
        pr = nr;
    }
    float cr = 0.f, ci = 0.f;
    for (int c = 0; c < NCH; c++) {
        g_hinit[seq][c][lane] = make_float2(cr, ci);
        float2 hl = g_hloc[seq][c][lane];
        float nr = pr * cr - pi * ci + hl.x;
        ci = pr * ci + pi * cr + hl.y;
        cr = nr;
    }
}

__global__ void recur_p2(const float* __restrict__ lam_r, const float* __restrict__ lam_i)
{
    const int bid = blockIdx.x;
    const int seq = bid >> 5, c = bid & 31;
    const int e = seq >> 2, b = seq & 3;
    const int lane = threadIdx.x;
    if (lane >= R) return;

    const float lr = 0.9f * lam_r[e * R + lane];
    const float li = 0.9f * lam_i[e * R + lane];
    const int t0 = c * LCH;
    const float* up = g_U + ((size_t)b * T + t0) * 128 + e * 32 + lane;
    float* gp = g_G + ((size_t)b * T + t0) * GDIM + e * 76;

    float2 h0 = g_hinit[seq][c][lane];
    float hr = h0.x, hi = h0.y, acc = 0.f;
    const unsigned mask = 0xFFFFu;

    float u_r = up[0];
    float u_i = up[16];

    for (int s = 0; s < LCH; s++) {
        int sn = (t0 + s + 1 < T) ? (s + 1) : s;
        float nu_r = up[(size_t)sn * 128];
        float nu_i = up[(size_t)sn * 128 + 16];

        float nhr = lr * hr - li * hi + ETA * u_r;
        float nhi = lr * hi + li * hr + ETA * u_i;
        float m2 = nhr * nhr + nhi * nhi;

        float sm = m2, mx = m2;
        #pragma unroll
        for (int off = 8; off >= 1; off >>= 1) {
            sm += __shfl_xor_sync(mask, sm, off, 16);
            mx = fmaxf(mx, __shfl_xor_sync(mask, mx, off, 16));
        }
        float m_mean = sm * (1.f / 16.f);
        acc = 0.99f * acc + 0.01f * m_mean;
        float inv = rsqrtf(m_mean + EPS);
        float hnr = nhr * inv, hni = nhi * inv;

        float sr = hnr, si = hni;
        #pragma unroll
        for (int off = 8; off >= 1; off >>= 1) {
            sr += __shfl_xor_sync(mask, sr, off, 16);
            si += __shfl_xor_sync(mask, si, off, 16);
        }
        float mr = sr * (1.f / 16.f);
        float mi = si * (1.f / 16.f);

        float* g_t = gp + (size_t)s * GDIM;
        g_t[6 + lane]           = hnr;
        g_t[6 + R + lane]       = hni;
        g_t[38 + 6 + lane]      = hni;
        g_t[38 + 6 + R + lane]  = -hnr;
        if (lane == 0) {
            g_t[0] = mr;
            g_t[1] = mi;
            g_t[2] = sqrtf(m_mean + EPS);
            g_t[3] = sqrtf(mx + EPS);
            g_t[38 + 0] = mi;
            g_t[38 + 1] = -mr;
            g_t[38 + 2] = 0.f; g_t[38 + 3] = 0.f; g_t[38 + 4] = 0.f; g_t[38 + 5] = 0.f;
            g_lacc[seq][t0 + s] = acc;
        }
        hr = nhr; hi = nhi;
        u_r = nu_r; u_i = nu_i;
    }
    if (lane == 0) g_accend[seq][c] = acc;
}

__global__ void acc_combine_kernel()
{
    int seq = threadIdx.x;
    if (seq >= 16) return;
    float p = 1.f;
    for (int k = 0; k < LCH; k++) p *= 0.99f;
    float A = 0.f;
    for (int c = 0; c < NCH; c++) {
        g_accinit[seq][c] = A;
        A = p * A + g_accend[seq][c];
    }
}

__global__ void acc_fix_kernel()
{
    int gid = blockIdx.x * 256 + threadIdx.x;
    if (gid >= 16 * T) return;
    int seq = gid >> 11;
    int t = gid & (T - 1);
    int c = t >> 6;
    int k = (t & (LCH - 1)) + 1;
    float acc = __powf(0.99f, (float)k) * g_accinit[seq][c] + g_lacc[seq][t];
    int e = seq >> 2, b = seq & 3;
    float* g_t = g_G + ((size_t)b * T + t) * GDIM + e * 76;
    g_t[4] = acc;
    g_t[5] = log1pf(acc);
}

// ----------------------------------------------------------------------------
// Launch
// ----------------------------------------------------------------------------
extern "C" void kernel_launch(void* const* d_in, const int* in_sizes, int n_in,
                              void* d_out, int out_size)
{
    const float* x      = (const float*)d_in[0];
    const float* sig_Wr = (const float*)d_in[1];
    const float* sig_Wi = (const float*)d_in[2];
    const float* sig_br = (const float*)d_in[3];
    const float* sig_bi = (const float*)d_in[4];
    const float* A_r    = (const float*)d_in[5];
    const float* A_i    = (const float*)d_in[6];
    const float* lam_r  = (const float*)d_in[7];
    const float* lam_i  = (const float*)d_in[8];
    const float* eh_Wr  = (const float*)d_in[9];
    const float* eh_Wi  = (const float*)d_in[10];
    const float* eh_br  = (const float*)d_in[11];
    const float* eh_bi  = (const float*)d_in[12];
    const float* fu_Wr  = (const float*)d_in[13];
    const float* fu_Wi  = (const float*)d_in[14];
    const float* fu_br  = (const float*)d_in[15];
    const float* fu_bi  = (const float*)d_in[16];
    const float* gW     = (const float*)d_in[17];
    const float* gb     = (const float*)d_in[18];
    float* out = (float*)d_out;

    float *Bc, *FRF, *CB, *cgate, *WF, *Wg2;
    uint32_t *Gh, *Gl, *WFh, *WFl, *CCh, *CCl, *W2h, *W2l;
    cudaGetSymbolAddress((void**)&Bc,    g_Bc);
    cudaGetSymbolAddress((void**)&FRF,   g_FRF);
    cudaGetSymbolAddress((void**)&CB,    g_CB);
    cudaGetSymbolAddress((void**)&cgate, g_cgate);
    cudaGetSymbolAddress((void**)&WF,    g_WF);
    cudaGetSymbolAddress((void**)&Wg2,   g_Wg2);
    cudaGetSymbolAddress((void**)&Gh,    g_Gh);
    cudaGetSymbolAddress((void**)&Gl,    g_Gl);
    cudaGetSymbolAddress((void**)&WFh,   g_WFh);
    cudaGetSymbolAddress((void**)&WFl,   g_WFl);
    cudaGetSymbolAddress((void**)&CCh,   g_CCh);
    cudaGetSymbolAddress((void**)&CCl,   g_CCl);
    cudaGetSymbolAddress((void**)&W2h,   g_W2h);
    cudaGetSymbolAddress((void**)&W2l,   g_W2l);

    cudaFuncSetAttribute(tc_gemm<0>, cudaFuncAttributeMaxDynamicSharedMemorySize, SMEMT);
    cudaFuncSetAttribute(tc_gemm<1>, cudaFuncAttributeMaxDynamicSharedMemorySize, SMEMT);

    // --- precompute (weight composition) ---
    combine_proj_kernel<<<dim3(64, E), 256>>>(sig_Wr, sig_Wi, A_r, A_i);
    ubias_kernel<<<1, 128>>>(sig_br, sig_bi, A_r, A_i);
    pquv_kernel<<<dim3(H / 64, E), 256>>>(eh_Wr, eh_Wi, fu_Wr, fu_Wi);
    crci_part_kernel<<<dim3(8, 32), 128>>>(eh_br, eh_bi, fu_Wr, fu_Wi);
    crci_reduce_kernel<<<8, 256>>>(fu_br, fu_bi);
    tpack_kernel<<<dim3(2048 / 32, KEG / 32), dim3(32, 8)>>>(WF, GDIM, 2048, KPG, WFh, WFl);
    wg2copy_kernel<<<(H * H + 255) / 256, 256>>>(gW);
    gcg_kernel<<<dim3(H / 64, 8), 256>>>(gW);
    tpack_kernel<<<dim3(H / 32, KEC / 32), dim3(32, 8)>>>(Wg2, CCW, H, KPC, W2h, W2l);
    cgate_part_kernel<<<dim3(8, 8), 128>>>(gW);
    cgate_reduce_kernel<<<4, 256>>>(gb);

    // --- main path ---
    sgemm_splitk<<<dim3(1, M_TOT / 128, 4), 256>>>(x, H, Bc, M_TOT, 128);
    ureduce_kernel<<<(M_TOT * 128 + 255) / 256, 256>>>();
    recur_p1<<<16 * NCH, 32>>>(lam_r, lam_i);
    recur_combine<<<1, 256>>>(lam_r, lam_i);
    recur_p2<<<16 * NCH, 32>>>(lam_r, lam_i);
    acc_combine_kernel<<<1, 16>>>();
    acc_fix_kernel<<<(16 * T + 255) / 256, 256>>>();
    pack_G_kernel<<<(M_TOT * KPG + 255) / 256, 256>>>();
    // FRF = G @ WF + CB
    tc_gemm<0><<<dim3(2048 / 128, M_TOT / 128), 256, SMEMT>>>(
        Gh, Gl, WFh, WFl, FRF, M_TOT, 2048, KEG, CB, nullptr, 0, nullptr, 0);
    concat2_kernel<<<M_TOT, 256>>>(x);
    // gate GEMM + fused epilogue
    tc_gemm<1><<<dim3(H / 128, M_TOT / 128), 256, SMEMT>>>(
        CCh, CCl, W2h, W2l, out, M_TOT, H, KEC, cgate, FRF, 2048, x, H);
}

// round 12
// speedup vs baseline: 10.7239x; 1.4414x over previous
#include <cuda_runtime.h>
#include <cuda_bf16.h>
#include <cuda_fp16.h>
#include <math.h>
#include <stdint.h>

#define BSZ 4
#define T 2048
#define H 1024
#define S 512
#define R 16
#define E 4
#define FDIM 38             // 6 + 2*R
#define M_TOT (BSZ*T)       // 8192
#define GDIM (E*2*FDIM)     // 304
#define CCW (H + GDIM + H)  // 2352
#define KEG 320             // padded K for FRF GEMM
#define KEC 2368            // padded K for gate GEMM
#define KPG (KEG/2)
#define KPC (KEC/2)
#define NCH 32
#define LCH 64
#define ETA 0.1f
#define EPS 1e-6f

// ----------------------------------------------------------------------------
// Scratch
// ----------------------------------------------------------------------------
__device__ float g_Bc[H * 128];
__device__ float g_ubias[128];
__device__ float g_Upart[4][M_TOT * 128];
__device__ float g_U[M_TOT * 128];
__device__ float g_G[(size_t)M_TOT * GDIM];
__device__ float g_WF[(size_t)GDIM * 2048];
__device__ float g_CB[2048];
__device__ float g_CBpart[32][2048];
__device__ float g_cgpart[8][1024];
__device__ float g_FRF[(size_t)M_TOT * 2048];
__device__ float g_cgate[H];
// pquv / gcg split-K partials
__device__ float g_pqp[4][E][FDIM][1024];
__device__ float g_uvp[4][E][FDIM][1024];
__device__ float g_gcgp[4][GDIM][1024];
__device__ float g_GcG[(size_t)GDIM * 1024];
// FRF operands: split bf16 (u32 = 2 adjacent-K bf16)
__device__ uint32_t g_Gh[(size_t)M_TOT * KPG];     // A hi [M][KPG]
__device__ uint32_t g_Gl[(size_t)M_TOT * KPG];
__device__ uint32_t g_WFh[(size_t)2048 * KPG];     // B hi [N][KPG]
__device__ uint32_t g_WFl[(size_t)2048 * KPG];
// gate operands: fp16 (A split 2-term, B single)
__device__ uint32_t g_CCh[(size_t)M_TOT * KPC];    // A hi [M][KPC]
__device__ uint32_t g_CCl[(size_t)M_TOT * KPC];    // A lo
__device__ uint32_t g_W2h[(size_t)1024 * KPC];     // B    [N][KPC]
// recurrence scan state
__device__ float2 g_hloc[16][NCH][16];
__device__ float2 g_hinit[16][NCH][16];
__device__ float g_lacc[16][T];
__device__ float g_accend[16][NCH];
__device__ float g_accinit[16][NCH];

// ----------------------------------------------------------------------------
// helpers
// ----------------------------------------------------------------------------
__device__ __forceinline__ void split2(float v0, float v1, uint32_t& ph, uint32_t& pl)
{
    __nv_bfloat162 h2 = __floats2bfloat162_rn(v0, v1);
    float r0 = v0 - __bfloat162float(h2.x);
    float r1 = v1 - __bfloat162float(h2.y);
    __nv_bfloat162 l2 = __floats2bfloat162_rn(r0, r1);
    ph = *reinterpret_cast<uint32_t*>(&h2);
    pl = *reinterpret_cast<uint32_t*>(&l2);
}

__device__ __forceinline__ void split2h(float v0, float v1, uint32_t& ph, uint32_t& pl)
{
    __half2 h2 = __floats2half2_rn(v0, v1);
    float r0 = v0 - __half2float(__low2half(h2));
    float r1 = v1 - __half2float(__high2half(h2));
    __half2 l2 = __floats2half2_rn(r0, r1);
    ph = *reinterpret_cast<uint32_t*>(&h2);
    pl = *reinterpret_cast<uint32_t*>(&l2);
}

__device__ __forceinline__ uint32_t pack2h(float v0, float v1)
{
    __half2 h2 = __floats2half2_rn(v0, v1);
    return *reinterpret_cast<uint32_t*>(&h2);
}

__device__ __forceinline__ uint32_t smem_u32_of(const void* p)
{
    uint32_t a;
    asm("{ .reg .u64 t; cvta.to.shared.u64 t, %1; cvt.u32.u64 %0, t; }" : "=r"(a) : "l"(p));
    return a;
}

__device__ __forceinline__ void mma_bf(float* d, const uint32_t* a, const uint32_t* b)
{
    asm volatile(
        "mma.sync.aligned.m16n8k16.row.col.f32.bf16.bf16.f32 "
        "{%0,%1,%2,%3}, {%4,%5,%6,%7}, {%8,%9}, {%0,%1,%2,%3};"
        : "+f"(d[0]), "+f"(d[1]), "+f"(d[2]), "+f"(d[3])
        : "r"(a[0]), "r"(a[1]), "r"(a[2]), "r"(a[3]), "r"(b[0]), "r"(b[1]));
}

__device__ __forceinline__ void mma_f16(float* d, const uint32_t* a, const uint32_t* b)
{
    asm volatile(
        "mma.sync.aligned.m16n8k16.row.col.f32.f16.f16.f32 "
        "{%0,%1,%2,%3}, {%4,%5,%6,%7}, {%8,%9}, {%0,%1,%2,%3};"
        : "+f"(d[0]), "+f"(d[1]), "+f"(d[2]), "+f"(d[3])
        : "r"(a[0]), "r"(a[1]), "r"(a[2]), "r"(a[3]), "r"(b[0]), "r"(b[1]));
}

// pipelined-GEMM smem geometry
#define NSTG 3
#define ROWU 12                      // u32 per smem row: 8 data + 4 pad
#define TILE_U (128 * ROWU)          // 1536 u32 = 6 KB
#define STG4_U (4 * TILE_U)          // 4-tile stage (bf16 3-term)
#define SMEM4 (NSTG * STG4_U * 4)    // 73728 B
#define STG3_U (3 * TILE_U)          // 3-tile stage (fp16 2-term)
#define SMEM3 (NSTG * STG3_U * 4)    // 55296 B

// ----------------------------------------------------------------------------
// bf16 3-term pipelined GEMM (FRF): C = A @ Bt^T + bias
// ----------------------------------------------------------------------------
__global__ __launch_bounds__(256)
void gemm_bf3(const uint32_t* __restrict__ Ah, const uint32_t* __restrict__ Al,
              const uint32_t* __restrict__ Bh, const uint32_t* __restrict__ Bl,
              float* __restrict__ C, int M, int N, int KE,
              const float* __restrict__ bias)
{
    extern __shared__ uint32_t sm[];
    const uint32_t smem_base = smem_u32_of(sm);
    const int tid = threadIdx.x;
    const int wid = tid >> 5, lane = tid & 31;
    const int wm = wid & 1, wn = wid >> 1;
    const int grp = lane >> 2, tig = lane & 3;
    const int bx = blockIdx.x, by = blockIdx.y;
    const int KP = KE >> 1;
    const int NC = KE >> 4;

    const int crow = tid >> 1, c16 = tid & 1;
    const uint32_t* gsrc0 = Ah + (size_t)(by * 128 + crow) * KP + c16 * 4;
    const uint32_t* gsrc1 = Al + (size_t)(by * 128 + crow) * KP + c16 * 4;
    const uint32_t* gsrc2 = Bh + (size_t)(bx * 128 + crow) * KP + c16 * 4;
    const uint32_t* gsrc3 = Bl + (size_t)(bx * 128 + crow) * KP + c16 * 4;
    const uint32_t dst0 = smem_base + (crow * ROWU + c16 * 4) * 4;

    float acc[4][4][4];
    #pragma unroll
    for (int i = 0; i < 4; i++)
        #pragma unroll
        for (int j = 0; j < 4; j++)
            #pragma unroll
            for (int q = 0; q < 4; q++) acc[i][j][q] = 0.f;

#define ISSUE4(chunk) do { \
        uint32_t db_ = dst0 + ((chunk) % NSTG) * (STG4_U * 4); \
        asm volatile("cp.async.cg.shared.global [%0], [%1], 16;" :: "r"(db_),                  "l"(gsrc0 + (chunk) * 8)); \
        asm volatile("cp.async.cg.shared.global [%0], [%1], 16;" :: "r"(db_ + TILE_U * 4),     "l"(gsrc1 + (chunk) * 8)); \
        asm volatile("cp.async.cg.shared.global [%0], [%1], 16;" :: "r"(db_ + 2 * TILE_U * 4), "l"(gsrc2 + (chunk) * 8)); \
        asm volatile("cp.async.cg.shared.global [%0], [%1], 16;" :: "r"(db_ + 3 * TILE_U * 4), "l"(gsrc3 + (chunk) * 8)); \
        asm volatile("cp.async.commit_group;"); \
    } while (0)

    ISSUE4(0);
    ISSUE4(1);

    for (int i = 0; i < NC; i++) {
        if (i + 1 < NC) asm volatile("cp.async.wait_group 1;");
        else            asm volatile("cp.async.wait_group 0;");
        __syncthreads();
        if (i + 2 < NC) ISSUE4(i + 2);

        const uint32_t stu = (i % NSTG) * STG4_U;
        const uint32_t tAh = stu, tAl = stu + TILE_U;
        const uint32_t tBh = stu + 2 * TILE_U, tBl = stu + 3 * TILE_U;

        uint32_t bh[4][2], bl[4][2];
        #pragma unroll
        for (int j = 0; j < 4; j++) {
            int rn = (wn * 32 + j * 8 + grp) * ROWU;
            bh[j][0] = sm[tBh + rn + tig];
            bh[j][1] = sm[tBh + rn + tig + 4];
            bl[j][0] = sm[tBl + rn + tig];
            bl[j][1] = sm[tBl + rn + tig + 4];
        }
        #pragma unroll
        for (int ii = 0; ii < 4; ii++) {
            int ra = (wm * 64 + ii * 16 + grp) * ROWU;
            int rb = ra + 8 * ROWU;
            uint32_t ah[4], al[4];
            ah[0] = sm[tAh + ra + tig];
            ah[1] = sm[tAh + rb + tig];
            ah[2] = sm[tAh + ra + tig + 4];
            ah[3] = sm[tAh + rb + tig + 4];
            al[0] = sm[tAl + ra + tig];
            al[1] = sm[tAl + rb + tig];
            al[2] = sm[tAl + ra + tig + 4];
            al[3] = sm[tAl + rb + tig + 4];
            #pragma unroll
            for (int j = 0; j < 4; j++) {
                mma_bf(acc[ii][j], ah, bh[j]);
                mma_bf(acc[ii][j], ah, bl[j]);
                mma_bf(acc[ii][j], al, bh[j]);
            }
        }
    }
#undef ISSUE4

    #pragma unroll
    for (int i = 0; i < 4; i++) {
        #pragma unroll
        for (int j = 0; j < 4; j++) {
            int row0 = by * 128 + wm * 64 + i * 16 + grp;
            int col0 = bx * 128 + wn * 32 + j * 8 + tig * 2;
            #pragma unroll
            for (int q = 0; q < 4; q++) {
                int row = row0 + (q >> 1) * 8;
                int col = col0 + (q & 1);
                C[(size_t)row * N + col] = acc[i][j][q] + bias[col];
            }
        }
    }
}

// ----------------------------------------------------------------------------
// fp16 2-term pipelined GEMM (gate): A split (Ah+Al), B single fp16.
// Fused epilogue: g = sigmoid(v); C = g*e1 + (1-g)*e2
// ----------------------------------------------------------------------------
__global__ __launch_bounds__(256)
void gemm_f16gate(const uint32_t* __restrict__ Ah, const uint32_t* __restrict__ Al,
                  const uint32_t* __restrict__ B,
                  float* __restrict__ C, int M, int N, int KE,
                  const float* __restrict__ bias,
                  const float* __restrict__ e1, int ld1,
                  const float* __restrict__ e2, int ld2)
{
    extern __shared__ uint32_t sm[];
    const uint32_t smem_base = smem_u32_of(sm);
    const int tid = threadIdx.x;
    const int wid = tid >> 5, lane = tid & 31;
    const int wm = wid & 1, wn = wid >> 1;
    const int grp = lane >> 2, tig = lane & 3;
    const int bx = blockIdx.x, by = blockIdx.y;
    const int KP = KE >> 1;
    const int NC = KE >> 4;

    const int crow = tid >> 1, c16 = tid & 1;
    const uint32_t* gsrc0 = Ah + (size_t)(by * 128 + crow) * KP + c16 * 4;
    const uint32_t* gsrc1 = Al + (size_t)(by * 128 + crow) * KP + c16 * 4;
    const uint32_t* gsrc2 = B  + (size_t)(bx * 128 + crow) * KP + c16 * 4;
    const uint32_t dst0 = smem_base + (crow * ROWU + c16 * 4) * 4;

    float acc[4][4][4];
    #pragma unroll
    for (int i = 0; i < 4; i++)
        #pragma unroll
        for (int j = 0; j < 4; j++)
            #pragma unroll
            for (int q = 0; q < 4; q++) acc[i][j][q] = 0.f;

#define ISSUE3(chunk) do { \
        uint32_t db_ = dst0 + ((chunk) % NSTG) * (STG3_U * 4); \
        asm volatile("cp.async.cg.shared.global [%0], [%1], 16;" :: "r"(db_),                  "l"(gsrc0 + (chunk) * 8)); \
        asm volatile("cp.async.cg.shared.global [%0], [%1], 16;" :: "r"(db_ + TILE_U * 4),     "l"(gsrc1 + (chunk) * 8)); \
        asm volatile("cp.async.cg.shared.global [%0], [%1], 16;" :: "r"(db_ + 2 * TILE_U * 4), "l"(gsrc2 + (chunk) * 8)); \
        asm volatile("cp.async.commit_group;"); \
    } while (0)

    ISSUE3(0);
    ISSUE3(1);

    for (int i = 0; i < NC; i++) {
        if (i + 1 < NC) asm volatile("cp.async.wait_group 1;");
        else            asm volatile("cp.async.wait_group 0;");
        __syncthreads();
        if (i + 2 < NC) ISSUE3(i + 2);

        const uint32_t stu = (i % NSTG) * STG3_U;
        const uint32_t tAh = stu, tAl = stu + TILE_U;
        const uint32_t tB = stu + 2 * TILE_U;

        uint32_t bfr[4][2];
        #pragma unroll
        for (int j = 0; j < 4; j++) {
            int rn = (wn * 32 + j * 8 + grp) * ROWU;
            bfr[j][0] = sm[tB + rn + tig];
            bfr[j][1] = sm[tB + rn + tig + 4];
        }
        #pragma unroll
        for (int ii = 0; ii < 4; ii++) {
            int ra = (wm * 64 + ii * 16 + grp) * ROWU;
            int rb = ra + 8 * ROWU;
            uint32_t ah[4], al[4];
            ah[0] = sm[tAh + ra + tig];
            ah[1] = sm[tAh + rb + tig];
            ah[2] = sm[tAh + ra + tig + 4];
            ah[3] = sm[tAh + rb + tig + 4];
            al[0] = sm[tAl + ra + tig];
            al[1] = sm[tAl + rb + tig];
            al[2] = sm[tAl + ra + tig + 4];
            al[3] = sm[tAl + rb + tig + 4];
            #pragma unroll
            for (int j = 0; j < 4; j++) {
                mma_f16(acc[ii][j], ah, bfr[j]);
                mma_f16(acc[ii][j], al, bfr[j]);
            }
        }
    }
#undef ISSUE3

    #pragma unroll
    for (int i = 0; i < 4; i++) {
        #pragma unroll
        for (int j = 0; j < 4; j++) {
            int row0 = by * 128 + wm * 64 + i * 16 + grp;
            int col0 = bx * 128 + wn * 32 + j * 8 + tig * 2;
            #pragma unroll
            for (int q = 0; q < 4; q++) {
                int row = row0 + (q >> 1) * 8;
                int col = col0 + (q & 1);
                float v = acc[i][j][q] + bias[col];
                float g = 1.f / (1.f + expf(-v));
                C[(size_t)row * N + col] =
                    g * e1[(size_t)row * ld1 + col] + (1.f - g) * e2[(size_t)row * ld2 + col];
            }
        }
    }
}

// ----------------------------------------------------------------------------
// transpose-pack (bf16 split) for WF
// ----------------------------------------------------------------------------
__global__ void tpack_kernel(const float* __restrict__ src, int K, int N, int KP2,
                             uint32_t* __restrict__ dh, uint32_t* __restrict__ dl)
{
    __shared__ float tile[32][33];
    const int n0 = blockIdx.x * 32;
    const int k0 = blockIdx.y * 32;
    const int tx = threadIdx.x, ty = threadIdx.y;
    #pragma unroll
    for (int j = 0; j < 32; j += 8) {
        int k = k0 + ty + j;
        tile[ty + j][tx] = (k < K) ? src[(size_t)k * N + n0 + tx] : 0.f;
    }
    __syncthreads();
    int t = ty * 32 + tx;
    #pragma unroll
    for (int s = 0; s < 2; s++) {
        int idx = t + s * 256;
        int n = idx >> 4;
        int kp = idx & 15;
        float v0 = tile[2 * kp][n], v1 = tile[2 * kp + 1][n];
        uint32_t h, l;
        split2(v0, v1, h, l);
        size_t o = (size_t)(n0 + n) * KP2 + (k0 >> 1) + kp;
        dh[o] = h;
        dl[o] = l;
    }
}

// ----------------------------------------------------------------------------
// gate weight pack (fp16 single), sourced from gW rows + GcG
// grid (1024/32, 2368/32), block (32,8)
// ----------------------------------------------------------------------------
__global__ void gate_wpack_kernel(const float* __restrict__ g_W)
{
    __shared__ float tile[32][33];
    const int n0 = blockIdx.x * 32;
    const int k0 = blockIdx.y * 32;
    const int tx = threadIdx.x, ty = threadIdx.y;
    #pragma unroll
    for (int j = 0; j < 32; j += 8) {
        int k = k0 + ty + j;
        float v;
        if (k < 1024)       v = g_W[(size_t)k * H + n0 + tx];
        else if (k < 1328)  v = g_GcG[(size_t)(k - 1024) * 1024 + n0 + tx];
        else if (k < 2352)  v = g_W[(size_t)(3 * 1024 + (k - 1328)) * H + n0 + tx];
        else                v = 0.f;
        tile[ty + j][tx] = v;
    }
    __syncthreads();
    int t = ty * 32 + tx;
    #pragma unroll
    for (int s = 0; s < 2; s++) {
        int idx = t + s * 256;
        int n = idx >> 4;
        int kp = idx & 15;
        g_W2h[(size_t)(n0 + n) * KPC + (k0 >> 1) + kp] =
            pack2h(tile[2 * kp][n], tile[2 * kp + 1][n]);
    }
}

// ----------------------------------------------------------------------------
// SIMT split-K SGEMM for U projection
// ----------------------------------------------------------------------------
__global__ __launch_bounds__(256)
void sgemm_splitk(const float* __restrict__ A, int lda,
                  const float* __restrict__ B, int M, int N)
{
    const int z = blockIdx.z;
    const float* Az = A + z * 256;
    const float* Bz = B + (size_t)(z * 256) * N;
    float* Cz = g_Upart[z];

    __shared__ float As[8][128];
    __shared__ float Bs[8][128];
    const int tid = threadIdx.x;
    const int by = blockIdx.y;
    const int tx = tid & 15, ty = tid >> 4;
    const int aRow = tid >> 1, aCol = (tid & 1) * 4;
    const int bRow = tid >> 5, bCol = (tid & 31) * 4;
    const float* Ap = Az + (size_t)(by * 128 + aRow) * lda + aCol;
    const float* Bp = Bz + (size_t)bRow * N + bCol;

    float acc[8][8];
    #pragma unroll
    for (int i = 0; i < 8; i++)
        #pragma unroll
        for (int j = 0; j < 8; j++) acc[i][j] = 0.f;

    float4 a4 = *(const float4*)(Ap);
    float4 b4 = *(const float4*)(Bp);

    for (int k0 = 0; k0 < 256; k0 += 8) {
        As[aCol + 0][aRow] = a4.x;
        As[aCol + 1][aRow] = a4.y;
        As[aCol + 2][aRow] = a4.z;
        As[aCol + 3][aRow] = a4.w;
        *(float4*)&Bs[bRow][bCol] = b4;
        __syncthreads();
        if (k0 + 8 < 256) {
            a4 = *(const float4*)(Ap + k0 + 8);
            b4 = *(const float4*)(Bp + (size_t)(k0 + 8) * N);
        }
        #pragma unroll
        for (int kk = 0; kk < 8; kk++) {
            float4 a0 = *(const float4*)&As[kk][ty * 8];
            float4 a1 = *(const float4*)&As[kk][ty * 8 + 4];
            float4 b0 = *(const float4*)&Bs[kk][tx * 8];
            float4 b1 = *(const float4*)&Bs[kk][tx * 8 + 4];
            float ar[8] = {a0.x, a0.y, a0.z, a0.w, a1.x, a1.y, a1.z, a1.w};
            float br[8] = {b0.x, b0.y, b0.z, b0.w, b1.x, b1.y, b1.z, b1.w};
            #pragma unroll
            for (int i = 0; i < 8; i++)
                #pragma unroll
                for (int j = 0; j < 8; j++)
                    acc[i][j] = fmaf(ar[i], br[j], acc[i][j]);
        }
        __syncthreads();
    }
    #pragma unroll
    for (int i = 0; i < 8; i++) {
        int row = by * 128 + ty * 8 + i;
        #pragma unroll
        for (int j = 0; j < 8; j++)
            Cz[(size_t)row * N + tx * 8 + j] = acc[i][j];
    }
}

__global__ void ureduce_kernel()
{
    int gid = blockIdx.x * 256 + threadIdx.x;
    if (gid >= M_TOT * 128) return;
    int col = gid & 127;
    g_U[gid] = g_Upart[0][gid] + g_Upart[1][gid] + g_Upart[2][gid] + g_Upart[3][gid]
             + g_ubias[col];
}

// ----------------------------------------------------------------------------
// Precompute Bc + ubias
// ----------------------------------------------------------------------------
__global__ __launch_bounds__(256)
void combine_proj_kernel(const float* __restrict__ sig_Wr, const float* __restrict__ sig_Wi,
                         const float* __restrict__ A_r, const float* __restrict__ A_i)
{
    __shared__ float sAr[128][16], sAi[128][16];
    __shared__ float sWr[16][128], sWi[16][128];
    const int e = blockIdx.y;
    const int h0 = blockIdx.x * 16;
    const int tid = threadIdx.x;
    const int h_loc = tid >> 4, r = tid & 15;
    float aur = 0.f, aui = 0.f;

    for (int s0 = 0; s0 < S; s0 += 128) {
        for (int i = tid; i < 128 * 16; i += 256) {
            int s = i >> 4, rr = i & 15;
            sAr[s][rr] = A_r[((size_t)e * S + s0 + s) * R + rr];
            sAi[s][rr] = A_i[((size_t)e * S + s0 + s) * R + rr];
        }
        for (int i = tid; i < 16 * 128; i += 256) {
            int hh = i >> 7, ss = i & 127;
            sWr[hh][ss] = sig_Wr[(size_t)(h0 + hh) * S + s0 + ss];
            sWi[hh][ss] = sig_Wi[(size_t)(h0 + hh) * S + s0 + ss];
        }
        __syncthreads();
        #pragma unroll 4
        for (int s = 0; s < 128; s++) {
            float wr = sWr[h_loc][s], wi = sWi[h_loc][s];
            float ar = sAr[s][r],     ai = sAi[s][r];
            aur = fmaf(wr, ar, aur);
            aur = fmaf(-wi, ai, aur);
            aui = fmaf(wr, ai, aui);
            aui = fmaf(wi, ar, aui);
        }
        __syncthreads();
    }
    g_Bc[(size_t)(h0 + h_loc) * 128 + e * 32 + r]      = aur;
    g_Bc[(size_t)(h0 + h_loc) * 128 + e * 32 + 16 + r] = aui;
}

__global__ void ubias_kernel(const float* __restrict__ sig_br, const float* __restrict__ sig_bi,
                             const float* __restrict__ A_r, const float* __restrict__ A_i)
{
    int j = threadIdx.x;
    int e = j >> 5, half = (j >> 4) & 1, r = j & 15;
    float acc = 0.f;
    for (int s = 0; s < S; s++) {
        float ar = A_r[((size_t)e * S + s) * R + r];
        float ai = A_i[((size_t)e * S + s) * R + r];
        float br = sig_br[s], bi = sig_bi[s];
        acc += half ? (br * ai + bi * ar) : (br * ar - bi * ai);
    }
    g_ubias[j] = acc;
}

// ----------------------------------------------------------------------------
// pquv split-K: grid (H/64, E, 4), each z handles K chunk of 256.
// ----------------------------------------------------------------------------
__global__ __launch_bounds__(256)
void pquv_part_kernel(const float* __restrict__ eh_Wr, const float* __restrict__ eh_Wi,
                      const float* __restrict__ fu_Wr, const float* __restrict__ fu_Wi)
{
    __shared__ float2 sA[40][32];
    __shared__ float2 sB[32][64];
    const int e = blockIdx.y;
    const int z = blockIdx.z;
    const int col0 = blockIdx.x * 64;
    const int tid = threadIdx.x;
    const int c = tid & 63, rg = tid >> 6;
    const int row0 = rg * 10;
    const int nrows = (rg == 3) ? 8 : 10;

    float wc1[10], wc2[10];
    #pragma unroll
    for (int i = 0; i < 10; i++) { wc1[i] = 0.f; wc2[i] = 0.f; }

    for (int kc = 0; kc < 8; kc++) {
        int k0 = z * 256 + kc * 32;
        for (int i = tid; i < FDIM * 32; i += 256) {
            int f = i >> 5, k = i & 31;
            size_t off = ((size_t)e * FDIM + f) * H + k0 + k;
            sA[f][k] = make_float2(eh_Wr[off], eh_Wi[off]);
        }
        for (int i = tid; i < 32 * 64; i += 256) {
            int k = i >> 6, cc = i & 63;
            size_t off = ((size_t)e * H + k0 + k) * H + col0 + cc;
            sB[k][cc] = make_float2(fu_Wr[off], fu_Wi[off]);
        }
        __syncthreads();
        for (int k = 0; k < 32; k++) {
            float2 b = sB[k][c];
            #pragma unroll
            for (int i = 0; i < 10; i++) {
                if (i < nrows) {
                    float2 a = sA[row0 + i][k];
                    wc1[i] = fmaf(a.x, b.x, wc1[i]);
                    wc1[i] = fmaf(-a.y, b.y, wc1[i]);
                    wc2[i] = fmaf(a.x, b.y, wc2[i]);
                    wc2[i] = fmaf(a.y, b.x, wc2[i]);
                }
            }
        }
        __syncthreads();
    }
    #pragma unroll
    for (int i = 0; i < 10; i++) {
        if (i < nrows) {
            g_pqp[z][e][row0 + i][col0 + c] = wc1[i];
            g_uvp[z][e][row0 + i][col0 + c] = wc2[i];
        }
    }
}

// reduce partials and scatter into WF [304][2048]
__global__ void wf_reduce_kernel()
{
    int gid = blockIdx.x * 256 + threadIdx.x;       // E*FDIM*1024
    if (gid >= E * FDIM * 1024) return;
    int cg = gid & 1023;
    int rem = gid >> 10;
    int row = rem % FDIM;
    int e = rem / FDIM;
    float wc1 = 0.f, wc2 = 0.f;
    #pragma unroll
    for (int z = 0; z < 4; z++) {
        wc1 += g_pqp[z][e][row][cg];
        wc2 += g_uvp[z][e][row][cg];
    }
    size_t b1 = (size_t)(e * 76 + row) * 2048;
    size_t b2 = (size_t)(e * 76 + 38 + row) * 2048;
    g_WF[b1 + cg]        = wc1;
    g_WF[b1 + 1024 + cg] = wc2;
    g_WF[b2 + cg]        = -wc2;
    g_WF[b2 + 1024 + cg] = wc1;
}

// ----------------------------------------------------------------------------
// crci / cgate
// ----------------------------------------------------------------------------
__global__ void crci_part_kernel(const float* __restrict__ eh_br, const float* __restrict__ eh_bi,
                                 const float* __restrict__ fu_Wr, const float* __restrict__ fu_Wi)
{
    const int o = blockIdx.x * 128 + threadIdx.x;
    const int eh0 = blockIdx.y * 128;
    float cr = 0.f, ci = 0.f;
    #pragma unroll 4
    for (int k = 0; k < 128; k++) {
        int eh = eh0 + k;
        float br = eh_br[eh], bi = eh_bi[eh];
        float wr = fu_Wr[(size_t)eh * H + o], wi = fu_Wi[(size_t)eh * H + o];
        cr = fmaf(br, wr, cr); cr = fmaf(-bi, wi, cr);
        ci = fmaf(br, wi, ci); ci = fmaf(bi, wr, ci);
    }
    g_CBpart[blockIdx.y][o]        = cr;
    g_CBpart[blockIdx.y][1024 + o] = ci;
}

__global__ void crci_reduce_kernel(const float* __restrict__ fu_br, const float* __restrict__ fu_bi)
{
    int o = blockIdx.x * 256 + threadIdx.x;
    float acc = (o < 1024) ? fu_br[o] : fu_bi[o - 1024];
    #pragma unroll
    for (int j = 0; j < 32; j++) acc += g_CBpart[j][o];
    g_CB[o] = acc;
}

__global__ void cgate_part_kernel(const float* __restrict__ g_W)
{
    const int o = blockIdx.x * 128 + threadIdx.x;
    const int h0 = blockIdx.y * 128;
    float acc = 0.f;
    #pragma unroll 4
    for (int k = 0; k < 128; k++) {
        int h = h0 + k;
        acc = fmaf(g_CB[h],        g_W[(size_t)(H + h) * H + o],     acc);
        acc = fmaf(g_CB[1024 + h], g_W[(size_t)(2 * H + h) * H + o], acc);
    }
    g_cgpart[blockIdx.y][o] = acc;
}

__global__ void cgate_reduce_kernel(const float* __restrict__ g_b)
{
    int o = blockIdx.x * 256 + threadIdx.x;
    float acc = g_b[o];
    #pragma unroll
    for (int j = 0; j < 8; j++) acc += g_cgpart[j][o];
    g_cgate[o] = acc;
}

// ----------------------------------------------------------------------------
// gcg split-K: grid (H/64, 8, 4); z handles K chunk of 512.
// ----------------------------------------------------------------------------
__global__ __launch_bounds__(256)
void gcg_part_kernel(const float* __restrict__ g_W)
{
    __shared__ float sA[40][32];
    __shared__ float sB[32][64];
    const int p0 = blockIdx.y * 38;
    const int z = blockIdx.z;
    const int col0 = blockIdx.x * 64;
    const int tid = threadIdx.x;
    const int c = tid & 63, rg = tid >> 6;
    const int row0 = rg * 10;
    const int nrows = (rg == 3) ? 8 : 10;

    float acc[10];
    #pragma unroll
    for (int i = 0; i < 10; i++) acc[i] = 0.f;

    for (int kc = 0; kc < 16; kc++) {
        int k0 = z * 512 + kc * 32;
        for (int i = tid; i < 38 * 32; i += 256) {
            int pp = i >> 5, k = i & 31;
            sA[pp][k] = g_WF[(size_t)(p0 + pp) * 2048 + k0 + k];
        }
        for (int i = tid; i < 32 * 64; i += 256) {
            int k = i >> 6, cc = i & 63;
            sB[k][cc] = g_W[(size_t)(H + k0 + k) * H + col0 + cc];
        }
        __syncthreads();
        for (int k = 0; k < 32; k++) {
            float b = sB[k][c];
            #pragma unroll
            for (int i = 0; i < 10; i++)
                if (i < nrows)
                    acc[i] = fmaf(sA[row0 + i][k], b, acc[i]);
        }
        __syncthreads();
    }
    #pragma unroll
    for (int i = 0; i < 10; i++)
        if (i < nrows)
            g_gcgp[z][p0 + row0 + i][col0 + c] = acc[i];
}

__global__ void gcg_reduce_kernel()
{
    int gid = blockIdx.x * 256 + threadIdx.x;    // GDIM*1024
    if (gid >= GDIM * 1024) return;
    int col = gid & 1023;
    int p = gid >> 10;
    float acc = 0.f;
    #pragma unroll
    for (int z = 0; z < 4; z++) acc += g_gcgp[z][p][col];
    g_GcG[(size_t)p * 1024 + col] = acc;
}

// ----------------------------------------------------------------------------
// A-side packing
// ----------------------------------------------------------------------------
__global__ void pack_G_kernel()
{
    int gid = blockIdx.x * 256 + threadIdx.x;
    if (gid >= M_TOT * KPG) return;
    int m = gid / KPG, kp = gid % KPG;
    float v0 = 0.f, v1 = 0.f;
    if (kp < GDIM / 2) {
        v0 = g_G[(size_t)m * GDIM + 2 * kp];
        v1 = g_G[(size_t)m * GDIM + 2 * kp + 1];
    }
    split2(v0, v1, g_Gh[gid], g_Gl[gid]);
}

__global__ void concat2_kernel(const float* __restrict__ x)
{
    const int row = blockIdx.x;
    const float* xr = x + (size_t)row * H;
    const float* gr = g_G + (size_t)row * GDIM;
    const float* fr = g_FRF + (size_t)row * 2048;
    uint32_t* dh = g_CCh + (size_t)row * KPC;
    uint32_t* dl = g_CCl + (size_t)row * KPC;

    for (int kp = threadIdx.x; kp < KPC; kp += 256) {
        float v0, v1;
        if (kp < 512) {
            v0 = xr[2 * kp]; v1 = xr[2 * kp + 1];
        } else if (kp < 664) {
            int cg = 2 * kp - 1024;
            v0 = gr[cg]; v1 = gr[cg + 1];
        } else if (kp < 1176) {
            int h = 2 * kp - 1328;
            float a0 = fr[h],     b0 = fr[1024 + h];
            float a1 = fr[h + 1], b1 = fr[1024 + h + 1];
            v0 = sqrtf(a0 * a0 + b0 * b0 + EPS);
            v1 = sqrtf(a1 * a1 + b1 * b1 + EPS);
        } else {
            v0 = 0.f; v1 = 0.f;
        }
        split2h(v0, v1, dh[kp], dl[kp]);
    }
}

// ----------------------------------------------------------------------------
// Recurrence as chunked parallel scan
// ----------------------------------------------------------------------------
__global__ void recur_p1(const float* __restrict__ lam_r, const float* __restrict__ lam_i)
{
    const int bid = blockIdx.x;
    const int seq = bid >> 5, c = bid & 31;
    const int e = seq >> 2, b = seq & 3;
    const int lane = threadIdx.x;
    if (lane >= R) return;
    const float lr = 0.9f * lam_r[e * R + lane];
    const float li = 0.9f * lam_i[e * R + lane];
    const float* up = g_U + ((size_t)b * T + c * LCH) * 128 + e * 32 + lane;
    float hr = 0.f, hi = 0.f;
    #pragma unroll 4
    for (int s = 0; s < LCH; s++) {
        float ur = up[(size_t)s * 128];
        float ui = up[(size_t)s * 128 + 16];
        float nhr = fmaf(lr, hr, fmaf(-li, hi, ETA * ur));
        float nhi = fmaf(lr, hi, fmaf(li, hr, ETA * ui));
        hr = nhr; hi = nhi;
    }
    g_hloc[seq][c][lane] = make_float2(hr, hi);
}

__global__ void recur_combine(const float* __restrict__ lam_r, const float* __restrict__ lam_i)
{
    int tid = threadIdx.x;
    int seq = tid >> 4, lane = tid & 15;
    int e = seq >> 2;
    float lr = 0.9f * lam_r[e * R + lane];
    float li = 0.9f * lam_i[e * R + lane];
    float pr = 1.f, pi = 0.f;
    for (int k = 0; k < LCH; k++) {
        float nr = pr * lr - pi * li;
        pi = pr * li + pi * lr;
        pr = nr;
    }
    float cr = 0.f, ci = 0.f;
    for (int c = 0; c < NCH; c++) {
        g_hinit[seq][c][lane] = make_float2(cr, ci);
        float2 hl = g_hloc[seq][c][lane];
        float nr = pr * cr - pi * ci + hl.x;
        ci = pr * ci + pi * cr + hl.y;
        cr = nr;
    }
}

__global__ void recur_p2(const float* __restrict__ lam_r, const float* __restrict__ lam_i)
{
    const int bid = blockIdx.x;
    const int seq = bid >> 5, c = bid & 31;
    const int e = seq >> 2, b = seq & 3;
    const int lane = threadIdx.x;
    if (lane >= R) return;

    const float lr = 0.9f * lam_r[e * R + lane];
    const float li = 0.9f * lam_i[e * R + lane];
    const int t0 = c * LCH;
    const float* up = g_U + ((size_t)b * T + t0) * 128 + e * 32 + lane;
    float* gp = g_G + ((size_t)b * T + t0) * GDIM + e * 76;

    float2 h0 = g_hinit[seq][c][lane];
    float hr = h0.x, hi = h0.y, acc = 0.f;
    const unsigned mask = 0xFFFFu;

    float u_r = up[0];
    float u_i = up[16];

    for (int s = 0; s < LCH; s++) {
        int sn = (t0 + s + 1 < T) ? (s + 1) : s;
        float nu_r = up[(size_t)sn * 128];
        float nu_i = up[(size_t)sn * 128 + 16];

        float nhr = lr * hr - li * hi + ETA * u_r;
        float nhi = lr * hi + li * hr + ETA * u_i;
        float m2 = nhr * nhr + nhi * nhi;

        float sm = m2, mx = m2;
        #pragma unroll
        for (int off = 8; off >= 1; off >>= 1) {
            sm += __shfl_xor_sync(mask, sm, off, 16);
            mx = fmaxf(mx, __shfl_xor_sync(mask, mx, off, 16));
        }
        float m_mean = sm * (1.f / 16.f);
        acc = 0.99f * acc + 0.01f * m_mean;
        float inv = rsqrtf(m_mean + EPS);
        float hnr = nhr * inv, hni = nhi * inv;

        float sr = hnr, si = hni;
        #pragma unroll
        for (int off = 8; off >= 1; off >>= 1) {
            sr += __shfl_xor_sync(mask, sr, off, 16);
            si += __shfl_xor_sync(mask, si, off, 16);
        }
        float mr = sr * (1.f / 16.f);
        float mi = si * (1.f / 16.f);

        float* g_t = gp + (size_t)s * GDIM;
        g_t[6 + lane]           = hnr;
        g_t[6 + R + lane]       = hni;
        g_t[38 + 6 + lane]      = hni;
        g_t[38 + 6 + R + lane]  = -hnr;
        if (lane == 0) {
            g_t[0] = mr;
            g_t[1] = mi;
            g_t[2] = sqrtf(m_mean + EPS);
            g_t[3] = sqrtf(mx + EPS);
            g_t[38 + 0] = mi;
            g_t[38 + 1] = -mr;
            g_t[38 + 2] = 0.f; g_t[38 + 3] = 0.f; g_t[38 + 4] = 0.f; g_t[38 + 5] = 0.f;
            g_lacc[seq][t0 + s] = acc;
        }
        hr = nhr; hi = nhi;
        u_r = nu_r; u_i = nu_i;
    }
    if (lane == 0) g_accend[seq][c] = acc;
}

__global__ void acc_combine_kernel()
{
    int seq = threadIdx.x;
    if (seq >= 16) return;
    float p = 1.f;
    for (int k = 0; k < LCH; k++) p *= 0.99f;
    float A = 0.f;
    for (int c = 0; c < NCH; c++) {
        g_accinit[seq][c] = A;
        A = p * A + g_accend[seq][c];
    }
}

__global__ void acc_fix_kernel()
{
    int gid = blockIdx.x * 256 + threadIdx.x;
    if (gid >= 16 * T) return;
    int seq = gid >> 11;
    int t = gid & (T - 1);
    int c = t >> 6;
    int k = (t & (LCH - 1)) + 1;
    float acc = __powf(0.99f, (float)k) * g_accinit[seq][c] + g_lacc[seq][t];
    int e = seq >> 2, b = seq & 3;
    float* g_t = g_G + ((size_t)b * T + t) * GDIM + e * 76;
    g_t[4] = acc;
    g_t[5] = log1pf(acc);
}

// ----------------------------------------------------------------------------
// Launch
// ----------------------------------------------------------------------------
extern "C" void kernel_launch(void* const* d_in, const int* in_sizes, int n_in,
                              void* d_out, int out_size)
{
    const float* x      = (const float*)d_in[0];
    const float* sig_Wr = (const float*)d_in[1];
    const float* sig_Wi = (const float*)d_in[2];
    const float* sig_br = (const float*)d_in[3];
    const float* sig_bi = (const float*)d_in[4];
    const float* A_r    = (const float*)d_in[5];
    const float* A_i    = (const float*)d_in[6];
    const float* lam_r  = (const float*)d_in[7];
    const float* lam_i  = (const float*)d_in[8];
    const float* eh_Wr  = (const float*)d_in[9];
    const float* eh_Wi  = (const float*)d_in[10];
    const float* eh_br  = (const float*)d_in[11];
    const float* eh_bi  = (const float*)d_in[12];
    const float* fu_Wr  = (const float*)d_in[13];
    const float* fu_Wi  = (const float*)d_in[14];
    const float* fu_br  = (const float*)d_in[15];
    const float* fu_bi  = (const float*)d_in[16];
    const float* gW     = (const float*)d_in[17];
    const float* gb     = (const float*)d_in[18];
    float* out = (float*)d_out;

    float *Bc, *FRF, *CB, *cgate, *WF;
    uint32_t *Gh, *Gl, *WFh, *WFl, *CCh, *CCl, *W2h;
    cudaGetSymbolAddress((void**)&Bc,    g_Bc);
    cudaGetSymbolAddress((void**)&FRF,   g_FRF);
    cudaGetSymbolAddress((void**)&CB,    g_CB);
    cudaGetSymbolAddress((void**)&cgate, g_cgate);
    cudaGetSymbolAddress((void**)&WF,    g_WF);
    cudaGetSymbolAddress((void**)&Gh,    g_Gh);
    cudaGetSymbolAddress((void**)&Gl,    g_Gl);
    cudaGetSymbolAddress((void**)&WFh,   g_WFh);
    cudaGetSymbolAddress((void**)&WFl,   g_WFl);
    cudaGetSymbolAddress((void**)&CCh,   g_CCh);
    cudaGetSymbolAddress((void**)&CCl,   g_CCl);
    cudaGetSymbolAddress((void**)&W2h,   g_W2h);

    cudaFuncSetAttribute(gemm_bf3, cudaFuncAttributeMaxDynamicSharedMemorySize, SMEM4);
    cudaFuncSetAttribute(gemm_f16gate, cudaFuncAttributeMaxDynamicSharedMemorySize, SMEM3);

    // --- precompute (weight composition) ---
    combine_proj_kernel<<<dim3(64, E), 256>>>(sig_Wr, sig_Wi, A_r, A_i);
    ubias_kernel<<<1, 128>>>(sig_br, sig_bi, A_r, A_i);
    pquv_part_kernel<<<dim3(H / 64, E, 4), 256>>>(eh_Wr, eh_Wi, fu_Wr, fu_Wi);
    wf_reduce_kernel<<<(E * FDIM * 1024 + 255) / 256, 256>>>();
    crci_part_kernel<<<dim3(8, 32), 128>>>(eh_br, eh_bi, fu_Wr, fu_Wi);
    crci_reduce_kernel<<<8, 256>>>(fu_br, fu_bi);
    tpack_kernel<<<dim3(2048 / 32, KEG / 32), dim3(32, 8)>>>(WF, GDIM, 2048, KPG, WFh, WFl);
    gcg_part_kernel<<<dim3(H / 64, 8, 4), 256>>>(gW);
    gcg_reduce_kernel<<<(GDIM * 1024 + 255) / 256, 256>>>();
    gate_wpack_kernel<<<dim3(1024 / 32, KEC / 32), dim3(32, 8)>>>(gW);
    cgate_part_kernel<<<dim3(8, 8), 128>>>(gW);
    cgate_reduce_kernel<<<4, 256>>>(gb);

    // --- main path ---
    sgemm_splitk<<<dim3(1, M_TOT / 128, 4), 256>>>(x, H, Bc, M_TOT, 128);
    ureduce_kernel<<<(M_TOT * 128 + 255) / 256, 256>>>();
    recur_p1<<<16 * NCH, 32>>>(lam_r, lam_i);
    recur_combine<<<1, 256>>>(lam_r, lam_i);
    recur_p2<<<16 * NCH, 32>>>(lam_r, lam_i);
    acc_combine_kernel<<<1, 16>>>();
    acc_fix_kernel<<<(16 * T + 255) / 256, 256>>>();
    pack_G_kernel<<<(M_TOT * KPG + 255) / 256, 256>>>();
    // FRF = G @ WF + CB  (bf16 3-term)
    gemm_bf3<<<dim3(2048 / 128, M_TOT / 128), 256, SMEM4>>>(
        Gh, Gl, WFh, WFl, FRF, M_TOT, 2048, KEG, CB);
    concat2_kernel<<<M_TOT, 256>>>(x);
    // gate GEMM (fp16 2-term) + fused epilogue
    gemm_f16gate<<<dim3(H / 128, M_TOT / 128), 256, SMEM3>>>(
        CCh, CCl, W2h, out, M_TOT, H, KEC, cgate, FRF, 2048, x, H);
}

// round 14
// speedup vs baseline: 11.4674x; 1.0693x over previous
#include <cuda_runtime.h>
#include <cuda_bf16.h>
#include <cuda_fp16.h>
#include <math.h>
#include <stdint.h>

#define BSZ 4
#define T 2048
#define H 1024
#define S 512
#define R 16
#define E 4
#define FDIM 38             // 6 + 2*R
#define M_TOT (BSZ*T)       // 8192
#define GDIM (E*2*FDIM)     // 304
#define CCW (H + GDIM + H)  // 2352
#define KEG 320             // padded K for FRF GEMM
#define KEC 2368            // padded K for gate GEMM
#define KPG (KEG/2)
#define KPC (KEC/2)
#define NCH 32
#define LCH 64
#define ETA 0.1f
#define EPS 1e-6f

// ----------------------------------------------------------------------------
// Scratch
// ----------------------------------------------------------------------------
__device__ float g_Bc[H * 128];
__device__ float g_ubias[128];
__device__ float g_Upart[4][M_TOT * 128];
__device__ float g_U[M_TOT * 128];
__device__ float g_G[(size_t)M_TOT * GDIM];
__device__ float g_WF[(size_t)GDIM * 2048];
__device__ float g_CB[2048];
__device__ float g_CBpart[64][2048];
__device__ float g_cgpart[8][1024];
__device__ float g_FRF[(size_t)M_TOT * 2048];
__device__ float g_cgate[H];
// pquv / gcg split-K partials
__device__ float g_pqp[4][E][FDIM][1024];
__device__ float g_uvp[4][E][FDIM][1024];
__device__ float g_gcgp[4][GDIM][1024];
__device__ float g_GcG[(size_t)GDIM * 1024];
// FRF operands: split bf16 (u32 = 2 adjacent-K bf16)
__device__ uint32_t g_Gh[(size_t)M_TOT * KPG];     // A hi [M][KPG]
__device__ uint32_t g_Gl[(size_t)M_TOT * KPG];
__device__ uint32_t g_WFh[(size_t)2048 * KPG];     // B hi [N][KPG]
__device__ uint32_t g_WFl[(size_t)2048 * KPG];
// gate operands: fp16 (A split 2-term, B single)
__device__ uint32_t g_CCh[(size_t)M_TOT * KPC];    // A hi [M][KPC]
__device__ uint32_t g_CCl[(size_t)M_TOT * KPC];    // A lo
__device__ uint32_t g_W2h[(size_t)1024 * KPC];     // B    [N][KPC]
// recurrence scan state
__device__ float2 g_hloc[16][NCH][16];
__device__ float2 g_hinit[16][NCH][16];
__device__ float g_lacc[16][T];
__device__ float g_accend[16][NCH];
__device__ float g_accinit[16][NCH];

// ----------------------------------------------------------------------------
// helpers
// ----------------------------------------------------------------------------
__device__ __forceinline__ void split2(float v0, float v1, uint32_t& ph, uint32_t& pl)
{
    __nv_bfloat162 h2 = __floats2bfloat162_rn(v0, v1);
    float r0 = v0 - __bfloat162float(h2.x);
    float r1 = v1 - __bfloat162float(h2.y);
    __nv_bfloat162 l2 = __floats2bfloat162_rn(r0, r1);
    ph = *reinterpret_cast<uint32_t*>(&h2);
    pl = *reinterpret_cast<uint32_t*>(&l2);
}

__device__ __forceinline__ void split2h(float v0, float v1, uint32_t& ph, uint32_t& pl)
{
    __half2 h2 = __floats2half2_rn(v0, v1);
    float r0 = v0 - __half2float(__low2half(h2));
    float r1 = v1 - __half2float(__high2half(h2));
    __half2 l2 = __floats2half2_rn(r0, r1);
    ph = *reinterpret_cast<uint32_t*>(&h2);
    pl = *reinterpret_cast<uint32_t*>(&l2);
}

__device__ __forceinline__ uint32_t pack2h(float v0, float v1)
{
    __half2 h2 = __floats2half2_rn(v0, v1);
    return *reinterpret_cast<uint32_t*>(&h2);
}

__device__ __forceinline__ uint32_t smem_u32_of(const void* p)
{
    uint32_t a;
    asm("{ .reg .u64 t; cvta.to.shared.u64 t, %1; cvt.u32.u64 %0, t; }" : "=r"(a) : "l"(p));
    return a;
}

__device__ __forceinline__ void mma_bf(float* d, const uint32_t* a, const uint32_t* b)
{
    asm volatile(
        "mma.sync.aligned.m16n8k16.row.col.f32.bf16.bf16.f32 "
        "{%0,%1,%2,%3}, {%4,%5,%6,%7}, {%8,%9}, {%0,%1,%2,%3};"
        : "+f"(d[0]), "+f"(d[1]), "+f"(d[2]), "+f"(d[3])
        : "r"(a[0]), "r"(a[1]), "r"(a[2]), "r"(a[3]), "r"(b[0]), "r"(b[1]));
}

__device__ __forceinline__ void mma_f16(float* d, const uint32_t* a, const uint32_t* b)
{
    asm volatile(
        "mma.sync.aligned.m16n8k16.row.col.f32.f16.f16.f32 "
        "{%0,%1,%2,%3}, {%4,%5,%6,%7}, {%8,%9}, {%0,%1,%2,%3};"
        : "+f"(d[0]), "+f"(d[1]), "+f"(d[2]), "+f"(d[3])
        : "r"(a[0]), "r"(a[1]), "r"(a[2]), "r"(a[3]), "r"(b[0]), "r"(b[1]));
}

// pipelined-GEMM smem geometry
#define NSTG 3
#define ROWU 12                      // u32 per smem row: 8 data + 4 pad
#define TILE_U (128 * ROWU)          // 1536 u32 = 6 KB
#define STG4_U (4 * TILE_U)          // 4-tile stage (bf16 3-term)
#define SMEM4 (NSTG * STG4_U * 4)    // 73728 B
#define STG3_U (3 * TILE_U)          // 3-tile stage (fp16 2-term)
#define SMEM3 (NSTG * STG3_U * 4)    // 55296 B

// ----------------------------------------------------------------------------
// bf16 3-term pipelined GEMM (FRF): C = A @ Bt^T + bias
// ----------------------------------------------------------------------------
__global__ __launch_bounds__(256)
void gemm_bf3(const uint32_t* __restrict__ Ah, const uint32_t* __restrict__ Al,
              const uint32_t* __restrict__ Bh, const uint32_t* __restrict__ Bl,
              float* __restrict__ C, int M, int N, int KE,
              const float* __restrict__ bias)
{
    extern __shared__ uint32_t sm[];
    const uint32_t smem_base = smem_u32_of(sm);
    const int tid = threadIdx.x;
    const int wid = tid >> 5, lane = tid & 31;
    const int wm = wid & 1, wn = wid >> 1;
    const int grp = lane >> 2, tig = lane & 3;
    const int bx = blockIdx.x, by = blockIdx.y;
    const int KP = KE >> 1;
    const int NC = KE >> 4;

    const int crow = tid >> 1, c16 = tid & 1;
    const uint32_t* gsrc0 = Ah + (size_t)(by * 128 + crow) * KP + c16 * 4;
    const uint32_t* gsrc1 = Al + (size_t)(by * 128 + crow) * KP + c16 * 4;
    const uint32_t* gsrc2 = Bh + (size_t)(bx * 128 + crow) * KP + c16 * 4;
    const uint32_t* gsrc3 = Bl + (size_t)(bx * 128 + crow) * KP + c16 * 4;
    const uint32_t dst0 = smem_base + (crow * ROWU + c16 * 4) * 4;

    float acc[4][4][4];
    #pragma unroll
    for (int i = 0; i < 4; i++)
        #pragma unroll
        for (int j = 0; j < 4; j++)
            #pragma unroll
            for (int q = 0; q < 4; q++) acc[i][j][q] = 0.f;

#define ISSUE4(chunk) do { \
        uint32_t db_ = dst0 + ((chunk) % NSTG) * (STG4_U * 4); \
        asm volatile("cp.async.cg.shared.global [%0], [%1], 16;" :: "r"(db_),                  "l"(gsrc0 + (chunk) * 8)); \
        asm volatile("cp.async.cg.shared.global [%0], [%1], 16;" :: "r"(db_ + TILE_U * 4),     "l"(gsrc1 + (chunk) * 8)); \
        asm volatile("cp.async.cg.shared.global [%0], [%1], 16;" :: "r"(db_ + 2 * TILE_U * 4), "l"(gsrc2 + (chunk) * 8)); \
        asm volatile("cp.async.cg.shared.global [%0], [%1], 16;" :: "r"(db_ + 3 * TILE_U * 4), "l"(gsrc3 + (chunk) * 8)); \
        asm volatile("cp.async.commit_group;"); \
    } while (0)

    ISSUE4(0);
    ISSUE4(1);

    for (int i = 0; i < NC; i++) {
        if (i + 1 < NC) asm volatile("cp.async.wait_group 1;");
        else            asm volatile("cp.async.wait_group 0;");
        __syncthreads();
        if (i + 2 < NC) ISSUE4(i + 2);

        const uint32_t stu = (i % NSTG) * STG4_U;
        const uint32_t tAh = stu, tAl = stu + TILE_U;
        const uint32_t tBh = stu + 2 * TILE_U, tBl = stu + 3 * TILE_U;

        uint32_t bh[4][2], bl[4][2];
        #pragma unroll
        for (int j = 0; j < 4; j++) {
            int rn = (wn * 32 + j * 8 + grp) * ROWU;
            bh[j][0] = sm[tBh + rn + tig];
            bh[j][1] = sm[tBh + rn + tig + 4];
            bl[j][0] = sm[tBl + rn + tig];
            bl[j][1] = sm[tBl + rn + tig + 4];
        }
        #pragma unroll
        for (int ii = 0; ii < 4; ii++) {
            int ra = (wm * 64 + ii * 16 + grp) * ROWU;
            int rb = ra + 8 * ROWU;
            uint32_t ah[4], al[4];
            ah[0] = sm[tAh + ra + tig];
            ah[1] = sm[tAh + rb + tig];
            ah[2] = sm[tAh + ra + tig + 4];
            ah[3] = sm[tAh + rb + tig + 4];
            al[0] = sm[tAl + ra + tig];
            al[1] = sm[tAl + rb + tig];
            al[2] = sm[tAl + ra + tig + 4];
            al[3] = sm[tAl + rb + tig + 4];
            #pragma unroll
            for (int j = 0; j < 4; j++) {
                mma_bf(acc[ii][j], ah, bh[j]);
                mma_bf(acc[ii][j], ah, bl[j]);
                mma_bf(acc[ii][j], al, bh[j]);
            }
        }
    }
#undef ISSUE4

    #pragma unroll
    for (int i = 0; i < 4; i++) {
        #pragma unroll
        for (int j = 0; j < 4; j++) {
            int row0 = by * 128 + wm * 64 + i * 16 + grp;
            int col0 = bx * 128 + wn * 32 + j * 8 + tig * 2;
            #pragma unroll
            for (int q = 0; q < 4; q++) {
                int row = row0 + (q >> 1) * 8;
                int col = col0 + (q & 1);
                C[(size_t)row * N + col] = acc[i][j][q] + bias[col];
            }
        }
    }
}

// ----------------------------------------------------------------------------
// fp16 2-term pipelined GEMM (gate): A split (Ah+Al), B single fp16.
// Fused epilogue: g = sigmoid(v); C = g*e1 + (1-g)*e2
// ----------------------------------------------------------------------------
__global__ __launch_bounds__(256)
void gemm_f16gate(const uint32_t* __restrict__ Ah, const uint32_t* __restrict__ Al,
                  const uint32_t* __restrict__ B,
                  float* __restrict__ C, int M, int N, int KE,
                  const float* __restrict__ bias,
                  const float* __restrict__ e1, int ld1,
                  const float* __restrict__ e2, int ld2)
{
    extern __shared__ uint32_t sm[];
    const uint32_t smem_base = smem_u32_of(sm);
    const int tid = threadIdx.x;
    const int wid = tid >> 5, lane = tid & 31;
    const int wm = wid & 1, wn = wid >> 1;
    const int grp = lane >> 2, tig = lane & 3;
    const int bx = blockIdx.x, by = blockIdx.y;
    const int KP = KE >> 1;
    const int NC = KE >> 4;

    const int crow = tid >> 1, c16 = tid & 1;
    const uint32_t* gsrc0 = Ah + (size_t)(by * 128 + crow) * KP + c16 * 4;
    const uint32_t* gsrc1 = Al + (size_t)(by * 128 + crow) * KP + c16 * 4;
    const uint32_t* gsrc2 = B  + (size_t)(bx * 128 + crow) * KP + c16 * 4;
    const uint32_t dst0 = smem_base + (crow * ROWU + c16 * 4) * 4;

    float acc[4][4][4];
    #pragma unroll
    for (int i = 0; i < 4; i++)
        #pragma unroll
        for (int j = 0; j < 4; j++)
            #pragma unroll
            for (int q = 0; q < 4; q++) acc[i][j][q] = 0.f;

#define ISSUE3(chunk) do { \
        uint32_t db_ = dst0 + ((chunk) % NSTG) * (STG3_U * 4); \
        asm volatile("cp.async.cg.shared.global [%0], [%1], 16;" :: "r"(db_),                  "l"(gsrc0 + (chunk) * 8)); \
        asm volatile("cp.async.cg.shared.global [%0], [%1], 16;" :: "r"(db_ + TILE_U * 4),     "l"(gsrc1 + (chunk) * 8)); \
        asm volatile("cp.async.cg.shared.global [%0], [%1], 16;" :: "r"(db_ + 2 * TILE_U * 4), "l"(gsrc2 + (chunk) * 8)); \
        asm volatile("cp.async.commit_group;"); \
    } while (0)

    ISSUE3(0);
    ISSUE3(1);

    for (int i = 0; i < NC; i++) {
        if (i + 1 < NC) asm volatile("cp.async.wait_group 1;");
        else            asm volatile("cp.async.wait_group 0;");
        __syncthreads();
        if (i + 2 < NC) ISSUE3(i + 2);

        const uint32_t stu = (i % NSTG) * STG3_U;
        const uint32_t tAh = stu, tAl = stu + TILE_U;
        const uint32_t tB = stu + 2 * TILE_U;

        uint32_t bfr[4][2];
        #pragma unroll
        for (int j = 0; j < 4; j++) {
            int rn = (wn * 32 + j * 8 + grp) * ROWU;
            bfr[j][0] = sm[tB + rn + tig];
            bfr[j][1] = sm[tB + rn + tig + 4];
        }
        #pragma unroll
        for (int ii = 0; ii < 4; ii++) {
            int ra = (wm * 64 + ii * 16 + grp) * ROWU;
            int rb = ra + 8 * ROWU;
            uint32_t ah[4], al[4];
            ah[0] = sm[tAh + ra + tig];
            ah[1] = sm[tAh + rb + tig];
            ah[2] = sm[tAh + ra + tig + 4];
            ah[3] = sm[tAh + rb + tig + 4];
            al[0] = sm[tAl + ra + tig];
            al[1] = sm[tAl + rb + tig];
            al[2] = sm[tAl + ra + tig + 4];
            al[3] = sm[tAl + rb + tig + 4];
            #pragma unroll
            for (int j = 0; j < 4; j++) {
                mma_f16(acc[ii][j], ah, bfr[j]);
                mma_f16(acc[ii][j], al, bfr[j]);
            }
        }
    }
#undef ISSUE3

    #pragma unroll
    for (int i = 0; i < 4; i++) {
        #pragma unroll
        for (int j = 0; j < 4; j++) {
            int row0 = by * 128 + wm * 64 + i * 16 + grp;
            int col0 = bx * 128 + wn * 32 + j * 8 + tig * 2;
            #pragma unroll
            for (int q = 0; q < 4; q++) {
                int row = row0 + (q >> 1) * 8;
                int col = col0 + (q & 1);
                float v = acc[i][j][q] + bias[col];
                float g = 1.f / (1.f + expf(-v));
                C[(size_t)row * N + col] =
                    g * e1[(size_t)row * ld1 + col] + (1.f - g) * e2[(size_t)row * ld2 + col];
            }
        }
    }
}

// ----------------------------------------------------------------------------
// transpose-pack (bf16 split) for WF
// ----------------------------------------------------------------------------
__global__ void tpack_kernel(const float* __restrict__ src, int K, int N, int KP2,
                             uint32_t* __restrict__ dh, uint32_t* __restrict__ dl)
{
    __shared__ float tile[32][33];
    const int n0 = blockIdx.x * 32;
    const int k0 = blockIdx.y * 32;
    const int tx = threadIdx.x, ty = threadIdx.y;
    #pragma unroll
    for (int j = 0; j < 32; j += 8) {
        int k = k0 + ty + j;
        tile[ty + j][tx] = (k < K) ? src[(size_t)k * N + n0 + tx] : 0.f;
    }
    __syncthreads();
    int t = ty * 32 + tx;
    #pragma unroll
    for (int s = 0; s < 2; s++) {
        int idx = t + s * 256;
        int n = idx >> 4;
        int kp = idx & 15;
        float v0 = tile[2 * kp][n], v1 = tile[2 * kp + 1][n];
        uint32_t h, l;
        split2(v0, v1, h, l);
        size_t o = (size_t)(n0 + n) * KP2 + (k0 >> 1) + kp;
        dh[o] = h;
        dl[o] = l;
    }
}

// ----------------------------------------------------------------------------
// gate weight pack (fp16 single), sourced from gW rows + GcG
// ----------------------------------------------------------------------------
__global__ void gate_wpack_kernel(const float* __restrict__ g_W)
{
    __shared__ float tile[32][33];
    const int n0 = blockIdx.x * 32;
    const int k0 = blockIdx.y * 32;
    const int tx = threadIdx.x, ty = threadIdx.y;
    #pragma unroll
    for (int j = 0; j < 32; j += 8) {
        int k = k0 + ty + j;
        float v;
        if (k < 1024)       v = g_W[(size_t)k * H + n0 + tx];
        else if (k < 1328)  v = g_GcG[(size_t)(k - 1024) * 1024 + n0 + tx];
        else if (k < 2352)  v = g_W[(size_t)(3 * 1024 + (k - 1328)) * H + n0 + tx];
        else                v = 0.f;
        tile[ty + j][tx] = v;
    }
    __syncthreads();
    int t = ty * 32 + tx;
    #pragma unroll
    for (int s = 0; s < 2; s++) {
        int idx = t + s * 256;
        int n = idx >> 4;
        int kp = idx & 15;
        g_W2h[(size_t)(n0 + n) * KPC + (k0 >> 1) + kp] =
            pack2h(tile[2 * kp][n], tile[2 * kp + 1][n]);
    }
}

// ----------------------------------------------------------------------------
// SIMT split-K SGEMM for U projection
// ----------------------------------------------------------------------------
__global__ __launch_bounds__(256)
void sgemm_splitk(const float* __restrict__ A, int lda,
                  const float* __restrict__ B, int M, int N)
{
    const int z = blockIdx.z;
    const float* Az = A + z * 256;
    const float* Bz = B + (size_t)(z * 256) * N;
    float* Cz = g_Upart[z];

    __shared__ float As[8][128];
    __shared__ float Bs[8][128];
    const int tid = threadIdx.x;
    const int by = blockIdx.y;
    const int tx = tid & 15, ty = tid >> 4;
    const int aRow = tid >> 1, aCol = (tid & 1) * 4;
    const int bRow = tid >> 5, bCol = (tid & 31) * 4;
    const float* Ap = Az + (size_t)(by * 128 + aRow) * lda + aCol;
    const float* Bp = Bz + (size_t)bRow * N + bCol;

    float acc[8][8];
    #pragma unroll
    for (int i = 0; i < 8; i++)
        #pragma unroll
        for (int j = 0; j < 8; j++) acc[i][j] = 0.f;

    float4 a4 = *(const float4*)(Ap);
    float4 b4 = *(const float4*)(Bp);

    for (int k0 = 0; k0 < 256; k0 += 8) {
        As[aCol + 0][aRow] = a4.x;
        As[aCol + 1][aRow] = a4.y;
        As[aCol + 2][aRow] = a4.z;
        As[aCol + 3][aRow] = a4.w;
        *(float4*)&Bs[bRow][bCol] = b4;
        __syncthreads();
        if (k0 + 8 < 256) {
            a4 = *(const float4*)(Ap + k0 + 8);
            b4 = *(const float4*)(Bp + (size_t)(k0 + 8) * N);
        }
        #pragma unroll
        for (int kk = 0; kk < 8; kk++) {
            float4 a0 = *(const float4*)&As[kk][ty * 8];
            float4 a1 = *(const float4*)&As[kk][ty * 8 + 4];
            float4 b0 = *(const float4*)&Bs[kk][tx * 8];
            float4 b1 = *(const float4*)&Bs[kk][tx * 8 + 4];
            float ar[8] = {a0.x, a0.y, a0.z, a0.w, a1.x, a1.y, a1.z, a1.w};
            float br[8] = {b0.x, b0.y, b0.z, b0.w, b1.x, b1.y, b1.z, b1.w};
            #pragma unroll
            for (int i = 0; i < 8; i++)
                #pragma unroll
                for (int j = 0; j < 8; j++)
                    acc[i][j] = fmaf(ar[i], br[j], acc[i][j]);
        }
        __syncthreads();
    }
    #pragma unroll
    for (int i = 0; i < 8; i++) {
        int row = by * 128 + ty * 8 + i;
        #pragma unroll
        for (int j = 0; j < 8; j++)
            Cz[(size_t)row * N + tx * 8 + j] = acc[i][j];
    }
}

__global__ void ureduce_kernel()
{
    int gid = blockIdx.x * 256 + threadIdx.x;
    if (gid >= M_TOT * 128) return;
    int col = gid & 127;
    g_U[gid] = g_Upart[0][gid] + g_Upart[1][gid] + g_Upart[2][gid] + g_Upart[3][gid]
             + g_ubias[col];
}

// ----------------------------------------------------------------------------
// Precompute Bc + ubias
// ----------------------------------------------------------------------------
__global__ __launch_bounds__(256)
void combine_proj_kernel(const float* __restrict__ sig_Wr, const float* __restrict__ sig_Wi,
                         const float* __restrict__ A_r, const float* __restrict__ A_i)
{
    __shared__ float sAr[128][16], sAi[128][16];
    __shared__ float sWr[16][128], sWi[16][128];
    const int e = blockIdx.y;
    const int h0 = blockIdx.x * 16;
    const int tid = threadIdx.x;
    const int h_loc = tid >> 4, r = tid & 15;
    float aur = 0.f, aui = 0.f;

    for (int s0 = 0; s0 < S; s0 += 128) {
        for (int i = tid; i < 128 * 16; i += 256) {
            int s = i >> 4, rr = i & 15;
            sAr[s][rr] = A_r[((size_t)e * S + s0 + s) * R + rr];
            sAi[s][rr] = A_i[((size_t)e * S + s0 + s) * R + rr];
        }
        for (int i = tid; i < 16 * 128; i += 256) {
            int hh = i >> 7, ss = i & 127;
            sWr[hh][ss] = sig_Wr[(size_t)(h0 + hh) * S + s0 + ss];
            sWi[hh][ss] = sig_Wi[(size_t)(h0 + hh) * S + s0 + ss];
        }
        __syncthreads();
        #pragma unroll 4
        for (int s = 0; s < 128; s++) {
            float wr = sWr[h_loc][s], wi = sWi[h_loc][s];
            float ar = sAr[s][r],     ai = sAi[s][r];
            aur = fmaf(wr, ar, aur);
            aur = fmaf(-wi, ai, aur);
            aui = fmaf(wr, ai, aui);
            aui = fmaf(wi, ar, aui);
        }
        __syncthreads();
    }
    g_Bc[(size_t)(h0 + h_loc) * 128 + e * 32 + r]      = aur;
    g_Bc[(size_t)(h0 + h_loc) * 128 + e * 32 + 16 + r] = aui;
}

__global__ void ubias_kernel(const float* __restrict__ sig_br, const float* __restrict__ sig_bi,
                             const float* __restrict__ A_r, const float* __restrict__ A_i)
{
    int j = threadIdx.x;
    int e = j >> 5, half = (j >> 4) & 1, r = j & 15;
    float acc = 0.f;
    for (int s = 0; s < S; s++) {
        float ar = A_r[((size_t)e * S + s) * R + r];
        float ai = A_i[((size_t)e * S + s) * R + r];
        float br = sig_br[s], bi = sig_bi[s];
        acc += half ? (br * ai + bi * ar) : (br * ar - bi * ai);
    }
    g_ubias[j] = acc;
}

// ----------------------------------------------------------------------------
// pquv split-K: grid (H/64, E, 4), each z handles K chunk of 256.
// ----------------------------------------------------------------------------
__global__ __launch_bounds__(256)
void pquv_part_kernel(const float* __restrict__ eh_Wr, const float* __restrict__ eh_Wi,
                      const float* __restrict__ fu_Wr, const float* __restrict__ fu_Wi)
{
    __shared__ float2 sA[40][32];
    __shared__ float2 sB[32][64];
    const int e = blockIdx.y;
    const int z = blockIdx.z;
    const int col0 = blockIdx.x * 64;
    const int tid = threadIdx.x;
    const int c = tid & 63, rg = tid >> 6;
    const int row0 = rg * 10;
    const int nrows = (rg == 3) ? 8 : 10;

    float wc1[10], wc2[10];
    #pragma unroll
    for (int i = 0; i < 10; i++) { wc1[i] = 0.f; wc2[i] = 0.f; }

    for (int kc = 0; kc < 8; kc++) {
        int k0 = z * 256 + kc * 32;
        for (int i = tid; i < FDIM * 32; i += 256) {
            int f = i >> 5, k = i & 31;
            size_t off = ((size_t)e * FDIM + f) * H + k0 + k;
            sA[f][k] = make_float2(eh_Wr[off], eh_Wi[off]);
        }
        for (int i = tid; i < 32 * 64; i += 256) {
            int k = i >> 6, cc = i & 63;
            size_t off = ((size_t)e * H + k0 + k) * H + col0 + cc;
            sB[k][cc] = make_float2(fu_Wr[off], fu_Wi[off]);
        }
        __syncthreads();
        for (int k = 0; k < 32; k++) {
            float2 b = sB[k][c];
            #pragma unroll
            for (int i = 0; i < 10; i++) {
                if (i < nrows) {
                    float2 a = sA[row0 + i][k];
                    wc1[i] = fmaf(a.x, b.x, wc1[i]);
                    wc1[i] = fmaf(-a.y, b.y, wc1[i]);
                    wc2[i] = fmaf(a.x, b.y, wc2[i]);
                    wc2[i] = fmaf(a.y, b.x, wc2[i]);
                }
            }
        }
        __syncthreads();
    }
    #pragma unroll
    for (int i = 0; i < 10; i++) {
        if (i < nrows) {
            g_pqp[z][e][row0 + i][col0 + c] = wc1[i];
            g_uvp[z][e][row0 + i][col0 + c] = wc2[i];
        }
    }
}

// reduce partials and scatter into WF [304][2048]
__global__ void wf_reduce_kernel()
{
    int gid = blockIdx.x * 256 + threadIdx.x;       // E*FDIM*1024
    if (gid >= E * FDIM * 1024) return;
    int cg = gid & 1023;
    int rem = gid >> 10;
    int row = rem % FDIM;
    int e = rem / FDIM;
    float wc1 = 0.f, wc2 = 0.f;
    #pragma unroll
    for (int z = 0; z < 4; z++) {
        wc1 += g_pqp[z][e][row][cg];
        wc2 += g_uvp[z][e][row][cg];
    }
    size_t b1 = (size_t)(e * 76 + row) * 2048;
    size_t b2 = (size_t)(e * 76 + 38 + row) * 2048;
    g_WF[b1 + cg]        = wc1;
    g_WF[b1 + 1024 + cg] = wc2;
    g_WF[b2 + cg]        = -wc2;
    g_WF[b2 + 1024 + cg] = wc1;
}

// ----------------------------------------------------------------------------
// crci / cgate  (crci 64 chunks for 2x MLP)
// ----------------------------------------------------------------------------
__global__ void crci_part_kernel(const float* __restrict__ eh_br, const float* __restrict__ eh_bi,
                                 const float* __restrict__ fu_Wr, const float* __restrict__ fu_Wi)
{
    const int o = blockIdx.x * 128 + threadIdx.x;
    const int eh0 = blockIdx.y * 64;
    float cr = 0.f, ci = 0.f;
    #pragma unroll 4
    for (int k = 0; k < 64; k++) {
        int eh = eh0 + k;
        float br = eh_br[eh], bi = eh_bi[eh];
        float wr = fu_Wr[(size_t)eh * H + o], wi = fu_Wi[(size_t)eh * H + o];
        cr = fmaf(br, wr, cr); cr = fmaf(-bi, wi, cr);
        ci = fmaf(br, wi, ci); ci = fmaf(bi, wr, ci);
    }
    g_CBpart[blockIdx.y][o]        = cr;
    g_CBpart[blockIdx.y][1024 + o] = ci;
}

__global__ void crci_reduce_kernel(const float* __restrict__ fu_br, const float* __restrict__ fu_bi)
{
    int o = blockIdx.x * 256 + threadIdx.x;
    float acc = (o < 1024) ? fu_br[o] : fu_bi[o - 1024];
    #pragma unroll
    for (int j = 0; j < 64; j++) acc += g_CBpart[j][o];
    g_CB[o] = acc;
}

__global__ void cgate_part_kernel(const float* __restrict__ g_W)
{
    const int o = blockIdx.x * 128 + threadIdx.x;
    const int h0 = blockIdx.y * 128;
    float acc = 0.f;
    #pragma unroll 4
    for (int k = 0; k < 128; k++) {
        int h = h0 + k;
        acc = fmaf(g_CB[h],        g_W[(size_t)(H + h) * H + o],     acc);
        acc = fmaf(g_CB[1024 + h], g_W[(size_t)(2 * H + h) * H + o], acc);
    }
    g_cgpart[blockIdx.y][o] = acc;
}

__global__ void cgate_reduce_kernel(const float* __restrict__ g_b)
{
    int o = blockIdx.x * 256 + threadIdx.x;
    float acc = g_b[o];
    #pragma unroll
    for (int j = 0; j < 8; j++) acc += g_cgpart[j][o];
    g_cgate[o] = acc;
}

// ----------------------------------------------------------------------------
// gcg split-K: grid (H/64, 8, 4); z handles K chunk of 512.
// ----------------------------------------------------------------------------
__global__ __launch_bounds__(256)
void gcg_part_kernel(const float* __restrict__ g_W)
{
    __shared__ float sA[40][32];
    __shared__ float sB[32][64];
    const int p0 = blockIdx.y * 38;
    const int z = blockIdx.z;
    const int col0 = blockIdx.x * 64;
    const int tid = threadIdx.x;
    const int c = tid & 63, rg = tid >> 6;
    const int row0 = rg * 10;
    const int nrows = (rg == 3) ? 8 : 10;

    float acc[10];
    #pragma unroll
    for (int i = 0; i < 10; i++) acc[i] = 0.f;

    for (int kc = 0; kc < 16; kc++) {
        int k0 = z * 512 + kc * 32;
        for (int i = tid; i < 38 * 32; i += 256) {
            int pp = i >> 5, k = i & 31;
            sA[pp][k] = g_WF[(size_t)(p0 + pp) * 2048 + k0 + k];
        }
        for (int i = tid; i < 32 * 64; i += 256) {
            int k = i >> 6, cc = i & 63;
            sB[k][cc] = g_W[(size_t)(H + k0 + k) * H + col0 + cc];
        }
        __syncthreads();
        for (int k = 0; k < 32; k++) {
            float b = sB[k][c];
            #pragma unroll
            for (int i = 0; i < 10; i++)
                if (i < nrows)
                    acc[i] = fmaf(sA[row0 + i][k], b, acc[i]);
        }
        __syncthreads();
    }
    #pragma unroll
    for (int i = 0; i < 10; i++)
        if (i < nrows)
            g_gcgp[z][p0 + row0 + i][col0 + c] = acc[i];
}

__global__ void gcg_reduce_kernel()
{
    int gid = blockIdx.x * 256 + threadIdx.x;    // GDIM*1024
    if (gid >= GDIM * 1024) return;
    int col = gid & 1023;
    int p = gid >> 10;
    float acc = 0.f;
    #pragma unroll
    for (int z = 0; z < 4; z++) acc += g_gcgp[z][p][col];
    g_GcG[(size_t)p * 1024 + col] = acc;
}

// ----------------------------------------------------------------------------
// A-side packing
// ----------------------------------------------------------------------------
__global__ void pack_G_kernel()
{
    int gid = blockIdx.x * 256 + threadIdx.x;
    if (gid >= M_TOT * KPG) return;
    int m = gid / KPG, kp = gid % KPG;
    float v0 = 0.f, v1 = 0.f;
    if (kp < GDIM / 2) {
        v0 = g_G[(size_t)m * GDIM + 2 * kp];
        v1 = g_G[(size_t)m * GDIM + 2 * kp + 1];
    }
    split2(v0, v1, g_Gh[gid], g_Gl[gid]);
}

__global__ void concat2_kernel(const float* __restrict__ x)
{
    const int row = blockIdx.x;
    const float* xr = x + (size_t)row * H;
    const float* gr = g_G + (size_t)row * GDIM;
    const float* fr = g_FRF + (size_t)row * 2048;
    uint32_t* dh = g_CCh + (size_t)row * KPC;
    uint32_t* dl = g_CCl + (size_t)row * KPC;

    for (int kp = threadIdx.x; kp < KPC; kp += 256) {
        float v0, v1;
        if (kp < 512) {
            v0 = xr[2 * kp]; v1 = xr[2 * kp + 1];
        } else if (kp < 664) {
            int cg = 2 * kp - 1024;
            v0 = gr[cg]; v1 = gr[cg + 1];
        } else if (kp < 1176) {
            int h = 2 * kp - 1328;
            float a0 = fr[h],     b0 = fr[1024 + h];
            float a1 = fr[h + 1], b1 = fr[1024 + h + 1];
            v0 = sqrtf(a0 * a0 + b0 * b0 + EPS);
            v1 = sqrtf(a1 * a1 + b1 * b1 + EPS);
        } else {
            v0 = 0.f; v1 = 0.f;
        }
        split2h(v0, v1, dh[kp], dl[kp]);
    }
}

// ----------------------------------------------------------------------------
// Recurrence as chunked parallel scan
// ----------------------------------------------------------------------------
__global__ void recur_p1(const float* __restrict__ lam_r, const float* __restrict__ lam_i)
{
    const int bid = blockIdx.x;
    const int seq = bid >> 5, c = bid & 31;
    const int e = seq >> 2, b = seq & 3;
    const int lane = threadIdx.x;
    if (lane >= R) return;
    const float lr = 0.9f * lam_r[e * R + lane];
    const float li = 0.9f * lam_i[e * R + lane];
    const float* up = g_U + ((size_t)b * T + c * LCH) * 128 + e * 32 + lane;
    float hr = 0.f, hi = 0.f;
    #pragma unroll 4
    for (int s = 0; s < LCH; s++) {
        float ur = up[(size_t)s * 128];
        float ui = up[(size_t)s * 128 + 16];
        float nhr = fmaf(lr, hr, fmaf(-li, hi, ETA * ur));
        float nhi = fmaf(lr, hi, fmaf(li, hr, ETA * ui));
        hr = nhr; hi = nhi;
    }
    g_hloc[seq][c][lane] = make_float2(hr, hi);
}

__global__ void recur_combine(const float* __restrict__ lam_r, const float* __restrict__ lam_i)
{
    int tid = threadIdx.x;
    int seq = tid >> 4, lane = tid & 15;
    int e = seq >> 2;
    float lr = 0.9f * lam_r[e * R + lane];
    float li = 0.9f * lam_i[e * R + lane];
    float pr = 1.f, pi = 0.f;
    for (int k = 0; k < LCH; k++) {
        float nr = pr * lr - pi * li;
        pi = pr * li + pi * lr;
        pr = nr;
    }
    float cr = 0.f, ci = 0.f;
    for (int c = 0; c < NCH; c++) {
        g_hinit[seq][c][lane] = make_float2(cr, ci);
        float2 hl = g_hloc[seq][c][lane];
        float nr = pr * cr - pi * ci + hl.x;
        ci = pr * ci + pi * cr + hl.y;
        cr = nr;
    }
}

__global__ void recur_p2(const float* __restrict__ lam_r, const float* __restrict__ lam_i)
{
    const int bid = blockIdx.x;
    const int seq = bid >> 5, c = bid & 31;
    const int e = seq >> 2, b = seq & 3;
    const int lane = threadIdx.x;
    if (lane >= R) return;

    const float lr = 0.9f * lam_r[e * R + lane];
    const float li = 0.9f * lam_i[e * R + lane];
    const int t0 = c * LCH;
    const float* up = g_U + ((size_t)b * T + t0) * 128 + e * 32 + lane;
    float* gp = g_G + ((size_t)b * T + t0) * GDIM + e * 76;

    float2 h0 = g_hinit[seq][c][lane];
    float hr = h0.x, hi = h0.y, acc = 0.f;
    const unsigned mask = 0xFFFFu;

    float u_r = up[0];
    float u_i = up[16];

    for (int s = 0; s < LCH; s++) {
        int sn = (t0 + s + 1 < T) ? (s + 1) : s;
        float nu_r = up[(size_t)sn * 128];
        float nu_i = up[(size_t)sn * 128 + 16];

        float nhr = lr * hr - li * hi + ETA * u_r;
        float nhi = lr * hi + li * hr + ETA * u_i;
        float m2 = nhr * nhr + nhi * nhi;

        float sm = m2, mx = m2;
        #pragma unroll
        for (int off = 8; off >= 1; off >>= 1) {
            sm += __shfl_xor_sync(mask, sm, off, 16);
            mx = fmaxf(mx, __shfl_xor_sync(mask, mx, off, 16));
        }
        float m_mean = sm * (1.f / 16.f);
        acc = 0.99f * acc + 0.01f * m_mean;
        float inv = rsqrtf(m_mean + EPS);
        float hnr = nhr * inv, hni = nhi * inv;

        float sr = hnr, si = hni;
        #pragma unroll
        for (int off = 8; off >= 1; off >>= 1) {
            sr += __shfl_xor_sync(mask, sr, off, 16);
            si += __shfl_xor_sync(mask, si, off, 16);
        }
        float mr = sr * (1.f / 16.f);
        float mi = si * (1.f / 16.f);

        float* g_t = gp + (size_t)s * GDIM;
        g_t[6 + lane]           = hnr;
        g_t[6 + R + lane]       = hni;
        g_t[38 + 6 + lane]      = hni;
        g_t[38 + 6 + R + lane]  = -hnr;
        if (lane == 0) {
            g_t[0] = mr;
            g_t[1] = mi;
            g_t[2] = sqrtf(m_mean + EPS);
            g_t[3] = sqrtf(mx + EPS);
            g_t[38 + 0] = mi;
            g_t[38 + 1] = -mr;
            g_t[38 + 2] = 0.f; g_t[38 + 3] = 0.f; g_t[38 + 4] = 0.f; g_t[38 + 5] = 0.f;
            g_lacc[seq][t0 + s] = acc;
        }
        hr = nhr; hi = nhi;
        u_r = nu_r; u_i = nu_i;
    }
    if (lane == 0) g_accend[seq][c] = acc;
}

__global__ void acc_combine_kernel()
{
    int seq = threadIdx.x;
    if (seq >= 16) return;
    float p = 1.f;
    for (int k = 0; k < LCH; k++) p *= 0.99f;
    float A = 0.f;
    for (int c = 0; c < NCH; c++) {
        g_accinit[seq][c] = A;
        A = p * A + g_accend[seq][c];
    }
}

__global__ void acc_fix_kernel()
{
    int gid = blockIdx.x * 256 + threadIdx.x;
    if (gid >= 16 * T) return;
    int seq = gid >> 11;
    int t = gid & (T - 1);
    int c = t >> 6;
    int k = (t & (LCH - 1)) + 1;
    float acc = __powf(0.99f, (float)k) * g_accinit[seq][c] + g_lacc[seq][t];
    int e = seq >> 2, b = seq & 3;
    float* g_t = g_G + ((size_t)b * T + t) * GDIM + e * 76;
    g_t[4] = acc;
    g_t[5] = log1pf(acc);
}

// ----------------------------------------------------------------------------
// Launch: precompute forked onto a side stream, joined before gemm_bf3.
// Streams/events created once (host objects, no device memory).
// ----------------------------------------------------------------------------
extern "C" void kernel_launch(void* const* d_in, const int* in_sizes, int n_in,
                              void* d_out, int out_size)
{
    const float* x      = (const float*)d_in[0];
    const float* sig_Wr = (const float*)d_in[1];
    const float* sig_Wi = (const float*)d_in[2];
    const float* sig_br = (const float*)d_in[3];
    const float* sig_bi = (const float*)d_in[4];
    const float* A_r    = (const float*)d_in[5];
    const float* A_i    = (const float*)d_in[6];
    const float* lam_r  = (const float*)d_in[7];
    const float* lam_i  = (const float*)d_in[8];
    const float* eh_Wr  = (const float*)d_in[9];
    const float* eh_Wi  = (const float*)d_in[10];
    const float* eh_br  = (const float*)d_in[11];
    const float* eh_bi  = (const float*)d_in[12];
    const float* fu_Wr  = (const float*)d_in[13];
    const float* fu_Wi  = (const float*)d_in[14];
    const float* fu_br  = (const float*)d_in[15];
    const float* fu_bi  = (const float*)d_in[16];
    const float* gW     = (const float*)d_in[17];
    const float* gb     = (const float*)d_in[18];
    float* out = (float*)d_out;

    float *Bc, *FRF, *CB, *cgate, *WF;
    uint32_t *Gh, *Gl, *WFh, *WFl, *CCh, *CCl, *W2h;
    cudaGetSymbolAddress((void**)&Bc,    g_Bc);
    cudaGetSymbolAddress((void**)&FRF,   g_FRF);
    cudaGetSymbolAddress((void**)&CB,    g_CB);
    cudaGetSymbolAddress((void**)&cgate, g_cgate);
    cudaGetSymbolAddress((void**)&WF,    g_WF);
    cudaGetSymbolAddress((void**)&Gh,    g_Gh);
    cudaGetSymbolAddress((void**)&Gl,    g_Gl);
    cudaGetSymbolAddress((void**)&WFh,   g_WFh);
    cudaGetSymbolAddress((void**)&WFl,   g_WFl);
    cudaGetSymbolAddress((void**)&CCh,   g_CCh);
    cudaGetSymbolAddress((void**)&CCl,   g_CCl);
    cudaGetSymbolAddress((void**)&W2h,   g_W2h);

    cudaFuncSetAttribute(gemm_bf3, cudaFuncAttributeMaxDynamicSharedMemorySize, SMEM4);
    cudaFuncSetAttribute(gemm_f16gate, cudaFuncAttributeMaxDynamicSharedMemorySize, SMEM3);

    // One-time host-object creation (first call is the uncaptured correctness run).
    static cudaStream_t sP = nullptr;
    static cudaEvent_t evFork = nullptr, evJoin = nullptr;
    if (sP == nullptr) {
        cudaStreamCreateWithFlags(&sP, cudaStreamNonBlocking);
        cudaEventCreateWithFlags(&evFork, cudaEventDisableTiming);
        cudaEventCreateWithFlags(&evJoin, cudaEventDisableTiming);
    }

    // Fork: side stream depends on start of this launch sequence.
    cudaEventRecord(evFork, 0);
    cudaStreamWaitEvent(sP, evFork, 0);

    // --- precompute (weight composition) on side stream ---
    pquv_part_kernel<<<dim3(H / 64, E, 4), 256, 0, sP>>>(eh_Wr, eh_Wi, fu_Wr, fu_Wi);
    wf_reduce_kernel<<<(E * FDIM * 1024 + 255) / 256, 256, 0, sP>>>();
    crci_part_kernel<<<dim3(8, 64), 128, 0, sP>>>(eh_br, eh_bi, fu_Wr, fu_Wi);
    crci_reduce_kernel<<<8, 256, 0, sP>>>(fu_br, fu_bi);
    tpack_kernel<<<dim3(2048 / 32, KEG / 32), dim3(32, 8), 0, sP>>>(WF, GDIM, 2048, KPG, WFh, WFl);
    gcg_part_kernel<<<dim3(H / 64, 8, 4), 256, 0, sP>>>(gW);
    gcg_reduce_kernel<<<(GDIM * 1024 + 255) / 256, 256, 0, sP>>>();
    gate_wpack_kernel<<<dim3(1024 / 32, KEC / 32), dim3(32, 8), 0, sP>>>(gW);
    cgate_part_kernel<<<dim3(8, 8), 128, 0, sP>>>(gW);
    cgate_reduce_kernel<<<4, 256, 0, sP>>>(gb);
    cudaEventRecord(evJoin, sP);

    // --- main path on default stream (independent until gemm_bf3) ---
    combine_proj_kernel<<<dim3(64, E), 256>>>(sig_Wr, sig_Wi, A_r, A_i);
    ubias_kernel<<<1, 128>>>(sig_br, sig_bi, A_r, A_i);
    sgemm_splitk<<<dim3(1, M_TOT / 128, 4), 256>>>(x, H, Bc, M_TOT, 128);
    ureduce_kernel<<<(M_TOT * 128 + 255) / 256, 256>>>();
    recur_p1<<<16 * NCH, 32>>>(lam_r, lam_i);
    recur_combine<<<1, 256>>>(lam_r, lam_i);
    recur_p2<<<16 * NCH, 32>>>(lam_r, lam_i);
    acc_combine_kernel<<<1, 16>>>();
    acc_fix_kernel<<<(16 * T + 255) / 256, 256>>>();
    pack_G_kernel<<<(M_TOT * KPG + 255) / 256, 256>>>();

    // Join: FRF needs WFh/WFl; gate needs W2h/cgate.
    cudaStreamWaitEvent(0, evJoin, 0);

    // FRF = G @ WF + CB  (bf16 3-term)
    gemm_bf3<<<dim3(2048 / 128, M_TOT / 128), 256, SMEM4>>>(
        Gh, Gl, WFh, WFl, FRF, M_TOT, 2048, KEG, CB);
    concat2_kernel<<<M_TOT, 256>>>(x);
    // gate GEMM (fp16 2-term) + fused epilogue
    gemm_f16gate<<<dim3(H / 128, M_TOT / 128), 256, SMEM3>>>(
        CCh, CCl, W2h, out, M_TOT, H, KEC, cgate, FRF, 2048, x, H);
}

// round 15
// speedup vs baseline: 13.5857x; 1.1847x over previous
#include <cuda_runtime.h>
#include <cuda_bf16.h>
#include <cuda_fp16.h>
#include <math.h>
#include <stdint.h>

#define BSZ 4
#define T 2048
#define H 1024
#define S 512
#define R 16
#define E 4
#define FDIM 38             // 6 + 2*R
#define M_TOT (BSZ*T)       // 8192
#define GDIM (E*2*FDIM)     // 304
#define CCW (H + GDIM + H)  // 2352
#define KEG 320             // padded K for FRF GEMM
#define KEC 2368            // padded K for gate GEMM
#define KPG (KEG/2)
#define KPC (KEC/2)
#define NCH 32
#define LCH 64
#define ETA 0.1f
#define EPS 1e-6f

// ----------------------------------------------------------------------------
// Scratch
// ----------------------------------------------------------------------------
__device__ float g_Bc[H * 128];
__device__ float g_ubias[128];
__device__ float g_Upart[4][M_TOT * 128];
__device__ float g_U[M_TOT * 128];
__device__ float g_G[(size_t)M_TOT * GDIM];
__device__ float g_WF[(size_t)GDIM * 2048];
__device__ float g_CB[2048];
__device__ float g_CBpart[64][2048];
__device__ float g_cgpart[8][1024];
__device__ float g_FRF[(size_t)M_TOT * 2048];
__device__ float g_cgate[H];
// pquv / gcg split-K partials
__device__ float g_pqp[4][E][FDIM][1024];
__device__ float g_uvp[4][E][FDIM][1024];
__device__ float g_gcgp[4][GDIM][1024];
__device__ float g_GcG[(size_t)GDIM * 1024];
// FRF operands: split bf16 (u32 = 2 adjacent-K bf16)
__device__ uint32_t g_Gh[(size_t)M_TOT * KPG];     // A hi [M][KPG]
__device__ uint32_t g_Gl[(size_t)M_TOT * KPG];
__device__ uint32_t g_WFh[(size_t)2048 * KPG];     // B hi [N][KPG]
__device__ uint32_t g_WFl[(size_t)2048 * KPG];
// gate operands: fp16 single (A and B)
__device__ uint32_t g_CCh[(size_t)M_TOT * KPC];    // A [M][KPC]
__device__ uint32_t g_W2h[(size_t)1024 * KPC];     // B [N][KPC]
// recurrence scan state
__device__ float2 g_hloc[16][NCH][16];
__device__ float2 g_hinit[16][NCH][16];
__device__ float g_lacc[16][T];
__device__ float g_accend[16][NCH];
__device__ float g_accinit[16][NCH];

// ----------------------------------------------------------------------------
// helpers
// ----------------------------------------------------------------------------
__device__ __forceinline__ void split2(float v0, float v1, uint32_t& ph, uint32_t& pl)
{
    __nv_bfloat162 h2 = __floats2bfloat162_rn(v0, v1);
    float r0 = v0 - __bfloat162float(h2.x);
    float r1 = v1 - __bfloat162float(h2.y);
    __nv_bfloat162 l2 = __floats2bfloat162_rn(r0, r1);
    ph = *reinterpret_cast<uint32_t*>(&h2);
    pl = *reinterpret_cast<uint32_t*>(&l2);
}

__device__ __forceinline__ uint32_t pack2h(float v0, float v1)
{
    __half2 h2 = __floats2half2_rn(v0, v1);
    return *reinterpret_cast<uint32_t*>(&h2);
}

__device__ __forceinline__ uint32_t smem_u32_of(const void* p)
{
    uint32_t a;
    asm("{ .reg .u64 t; cvta.to.shared.u64 t, %1; cvt.u32.u64 %0, t; }" : "=r"(a) : "l"(p));
    return a;
}

__device__ __forceinline__ void mma_bf(float* d, const uint32_t* a, const uint32_t* b)
{
    asm volatile(
        "mma.sync.aligned.m16n8k16.row.col.f32.bf16.bf16.f32 "
        "{%0,%1,%2,%3}, {%4,%5,%6,%7}, {%8,%9}, {%0,%1,%2,%3};"
        : "+f"(d[0]), "+f"(d[1]), "+f"(d[2]), "+f"(d[3])
        : "r"(a[0]), "r"(a[1]), "r"(a[2]), "r"(a[3]), "r"(b[0]), "r"(b[1]));
}

__device__ __forceinline__ void mma_f16(float* d, const uint32_t* a, const uint32_t* b)
{
    asm volatile(
        "mma.sync.aligned.m16n8k16.row.col.f32.f16.f16.f32 "
        "{%0,%1,%2,%3}, {%4,%5,%6,%7}, {%8,%9}, {%0,%1,%2,%3};"
        : "+f"(d[0]), "+f"(d[1]), "+f"(d[2]), "+f"(d[3])
        : "r"(a[0]), "r"(a[1]), "r"(a[2]), "r"(a[3]), "r"(b[0]), "r"(b[1]));
}

// pipelined-GEMM smem geometry
#define NSTG 3
#define ROWU 12                      // u32 per smem row: 8 data + 4 pad
#define TILE_U (128 * ROWU)          // 1536 u32 = 6 KB
#define STG4_U (4 * TILE_U)          // 4-tile stage (bf16 3-term)
#define SMEM4 (NSTG * STG4_U * 4)    // 73728 B
#define STG2_U (2 * TILE_U)          // 2-tile stage (fp16 single)
#define SMEM2 (NSTG * STG2_U * 4)    // 36864 B

// ----------------------------------------------------------------------------
// bf16 3-term pipelined GEMM (FRF): C = A @ Bt^T + bias
// ----------------------------------------------------------------------------
__global__ __launch_bounds__(256)
void gemm_bf3(const uint32_t* __restrict__ Ah, const uint32_t* __restrict__ Al,
              const uint32_t* __restrict__ Bh, const uint32_t* __restrict__ Bl,
              float* __restrict__ C, int M, int N, int KE,
              const float* __restrict__ bias)
{
    extern __shared__ uint32_t sm[];
    const uint32_t smem_base = smem_u32_of(sm);
    const int tid = threadIdx.x;
    const int wid = tid >> 5, lane = tid & 31;
    const int wm = wid & 1, wn = wid >> 1;
    const int grp = lane >> 2, tig = lane & 3;
    const int bx = blockIdx.x, by = blockIdx.y;
    const int KP = KE >> 1;
    const int NC = KE >> 4;

    const int crow = tid >> 1, c16 = tid & 1;
    const uint32_t* gsrc0 = Ah + (size_t)(by * 128 + crow) * KP + c16 * 4;
    const uint32_t* gsrc1 = Al + (size_t)(by * 128 + crow) * KP + c16 * 4;
    const uint32_t* gsrc2 = Bh + (size_t)(bx * 128 + crow) * KP + c16 * 4;
    const uint32_t* gsrc3 = Bl + (size_t)(bx * 128 + crow) * KP + c16 * 4;
    const uint32_t dst0 = smem_base + (crow * ROWU + c16 * 4) * 4;

    float acc[4][4][4];
    #pragma unroll
    for (int i = 0; i < 4; i++)
        #pragma unroll
        for (int j = 0; j < 4; j++)
            #pragma unroll
            for (int q = 0; q < 4; q++) acc[i][j][q] = 0.f;

#define ISSUE4(chunk) do { \
        uint32_t db_ = dst0 + ((chunk) % NSTG) * (STG4_U * 4); \
        asm volatile("cp.async.cg.shared.global [%0], [%1], 16;" :: "r"(db_),                  "l"(gsrc0 + (chunk) * 8)); \
        asm volatile("cp.async.cg.shared.global [%0], [%1], 16;" :: "r"(db_ + TILE_U * 4),     "l"(gsrc1 + (chunk) * 8)); \
        asm volatile("cp.async.cg.shared.global [%0], [%1], 16;" :: "r"(db_ + 2 * TILE_U * 4), "l"(gsrc2 + (chunk) * 8)); \
        asm volatile("cp.async.cg.shared.global [%0], [%1], 16;" :: "r"(db_ + 3 * TILE_U * 4), "l"(gsrc3 + (chunk) * 8)); \
        asm volatile("cp.async.commit_group;"); \
    } while (0)

    ISSUE4(0);
    ISSUE4(1);

    for (int i = 0; i < NC; i++) {
        if (i + 1 < NC) asm volatile("cp.async.wait_group 1;");
        else            asm volatile("cp.async.wait_group 0;");
        __syncthreads();
        if (i + 2 < NC) ISSUE4(i + 2);

        const uint32_t stu = (i % NSTG) * STG4_U;
        const uint32_t tAh = stu, tAl = stu + TILE_U;
        const uint32_t tBh = stu + 2 * TILE_U, tBl = stu + 3 * TILE_U;

        uint32_t bh[4][2], bl[4][2];
        #pragma unroll
        for (int j = 0; j < 4; j++) {
            int rn = (wn * 32 + j * 8 + grp) * ROWU;
            bh[j][0] = sm[tBh + rn + tig];
            bh[j][1] = sm[tBh + rn + tig + 4];
            bl[j][0] = sm[tBl + rn + tig];
            bl[j][1] = sm[tBl + rn + tig + 4];
        }
        #pragma unroll
        for (int ii = 0; ii < 4; ii++) {
            int ra = (wm * 64 + ii * 16 + grp) * ROWU;
            int rb = ra + 8 * ROWU;
            uint32_t ah[4], al[4];
            ah[0] = sm[tAh + ra + tig];
            ah[1] = sm[tAh + rb + tig];
            ah[2] = sm[tAh + ra + tig + 4];
            ah[3] = sm[tAh + rb + tig + 4];
            al[0] = sm[tAl + ra + tig];
            al[1] = sm[tAl + rb + tig];
            al[2] = sm[tAl + ra + tig + 4];
            al[3] = sm[tAl + rb + tig + 4];
            #pragma unroll
            for (int j = 0; j < 4; j++) {
                mma_bf(acc[ii][j], ah, bh[j]);
                mma_bf(acc[ii][j], ah, bl[j]);
                mma_bf(acc[ii][j], al, bh[j]);
            }
        }
    }
#undef ISSUE4

    #pragma unroll
    for (int i = 0; i < 4; i++) {
        #pragma unroll
        for (int j = 0; j < 4; j++) {
            int row0 = by * 128 + wm * 64 + i * 16 + grp;
            int col0 = bx * 128 + wn * 32 + j * 8 + tig * 2;
            #pragma unroll
            for (int q = 0; q < 4; q++) {
                int row = row0 + (q >> 1) * 8;
                int col = col0 + (q & 1);
                C[(size_t)row * N + col] = acc[i][j][q] + bias[col];
            }
        }
    }
}

// ----------------------------------------------------------------------------
// fp16 single pipelined GEMM (gate): A single, B single.
// Fused epilogue: g = sigmoid(v); C = g*e1 + (1-g)*e2
// ----------------------------------------------------------------------------
__global__ __launch_bounds__(256)
void gemm_f16gate(const uint32_t* __restrict__ A,
                  const uint32_t* __restrict__ B,
                  float* __restrict__ C, int M, int N, int KE,
                  const float* __restrict__ bias,
                  const float* __restrict__ e1, int ld1,
                  const float* __restrict__ e2, int ld2)
{
    extern __shared__ uint32_t sm[];
    const uint32_t smem_base = smem_u32_of(sm);
    const int tid = threadIdx.x;
    const int wid = tid >> 5, lane = tid & 31;
    const int wm = wid & 1, wn = wid >> 1;
    const int grp = lane >> 2, tig = lane & 3;
    const int bx = blockIdx.x, by = blockIdx.y;
    const int KP = KE >> 1;
    const int NC = KE >> 4;

    const int crow = tid >> 1, c16 = tid & 1;
    const uint32_t* gsrc0 = A + (size_t)(by * 128 + crow) * KP + c16 * 4;
    const uint32_t* gsrc1 = B + (size_t)(bx * 128 + crow) * KP + c16 * 4;
    const uint32_t dst0 = smem_base + (crow * ROWU + c16 * 4) * 4;

    float acc[4][4][4];
    #pragma unroll
    for (int i = 0; i < 4; i++)
        #pragma unroll
        for (int j = 0; j < 4; j++)
            #pragma unroll
            for (int q = 0; q < 4; q++) acc[i][j][q] = 0.f;

#define ISSUE2(chunk) do { \
        uint32_t db_ = dst0 + ((chunk) % NSTG) * (STG2_U * 4); \
        asm volatile("cp.async.cg.shared.global [%0], [%1], 16;" :: "r"(db_),              "l"(gsrc0 + (chunk) * 8)); \
        asm volatile("cp.async.cg.shared.global [%0], [%1], 16;" :: "r"(db_ + TILE_U * 4), "l"(gsrc1 + (chunk) * 8)); \
        asm volatile("cp.async.commit_group;"); \
    } while (0)

    ISSUE2(0);
    ISSUE2(1);

    for (int i = 0; i < NC; i++) {
        if (i + 1 < NC) asm volatile("cp.async.wait_group 1;");
        else            asm volatile("cp.async.wait_group 0;");
        __syncthreads();
        if (i + 2 < NC) ISSUE2(i + 2);

        const uint32_t stu = (i % NSTG) * STG2_U;
        const uint32_t tA = stu, tB = stu + TILE_U;

        uint32_t bfr[4][2];
        #pragma unroll
        for (int j = 0; j < 4; j++) {
            int rn = (wn * 32 + j * 8 + grp) * ROWU;
            bfr[j][0] = sm[tB + rn + tig];
            bfr[j][1] = sm[tB + rn + tig + 4];
        }
        #pragma unroll
        for (int ii = 0; ii < 4; ii++) {
            int ra = (wm * 64 + ii * 16 + grp) * ROWU;
            int rb = ra + 8 * ROWU;
            uint32_t afr[4];
            afr[0] = sm[tA + ra + tig];
            afr[1] = sm[tA + rb + tig];
            afr[2] = sm[tA + ra + tig + 4];
            afr[3] = sm[tA + rb + tig + 4];
            #pragma unroll
            for (int j = 0; j < 4; j++)
                mma_f16(acc[ii][j], afr, bfr[j]);
        }
    }
#undef ISSUE2

    #pragma unroll
    for (int i = 0; i < 4; i++) {
        #pragma unroll
        for (int j = 0; j < 4; j++) {
            int row0 = by * 128 + wm * 64 + i * 16 + grp;
            int col0 = bx * 128 + wn * 32 + j * 8 + tig * 2;
            #pragma unroll
            for (int q = 0; q < 4; q++) {
                int row = row0 + (q >> 1) * 8;
                int col = col0 + (q & 1);
                float v = acc[i][j][q] + bias[col];
                float g = 1.f / (1.f + expf(-v));
                C[(size_t)row * N + col] =
                    g * e1[(size_t)row * ld1 + col] + (1.f - g) * e2[(size_t)row * ld2 + col];
            }
        }
    }
}

// ----------------------------------------------------------------------------
// transpose-pack (bf16 split) for WF
// ----------------------------------------------------------------------------
__global__ void tpack_kernel(const float* __restrict__ src, int K, int N, int KP2,
                             uint32_t* __restrict__ dh, uint32_t* __restrict__ dl)
{
    __shared__ float tile[32][33];
    const int n0 = blockIdx.x * 32;
    const int k0 = blockIdx.y * 32;
    const int tx = threadIdx.x, ty = threadIdx.y;
    #pragma unroll
    for (int j = 0; j < 32; j += 8) {
        int k = k0 + ty + j;
        tile[ty + j][tx] = (k < K) ? src[(size_t)k * N + n0 + tx] : 0.f;
    }
    __syncthreads();
    int t = ty * 32 + tx;
    #pragma unroll
    for (int s = 0; s < 2; s++) {
        int idx = t + s * 256;
        int n = idx >> 4;
        int kp = idx & 15;
        float v0 = tile[2 * kp][n], v1 = tile[2 * kp + 1][n];
        uint32_t h, l;
        split2(v0, v1, h, l);
        size_t o = (size_t)(n0 + n) * KP2 + (k0 >> 1) + kp;
        dh[o] = h;
        dl[o] = l;
    }
}

// ----------------------------------------------------------------------------
// gate weight pack (fp16 single), sourced from gW rows + GcG
// ----------------------------------------------------------------------------
__global__ void gate_wpack_kernel(const float* __restrict__ g_W)
{
    __shared__ float tile[32][33];
    const int n0 = blockIdx.x * 32;
    const int k0 = blockIdx.y * 32;
    const int tx = threadIdx.x, ty = threadIdx.y;
    #pragma unroll
    for (int j = 0; j < 32; j += 8) {
        int k = k0 + ty + j;
        float v;
        if (k < 1024)       v = g_W[(size_t)k * H + n0 + tx];
        else if (k < 1328)  v = g_GcG[(size_t)(k - 1024) * 1024 + n0 + tx];
        else if (k < 2352)  v = g_W[(size_t)(3 * 1024 + (k - 1328)) * H + n0 + tx];
        else                v = 0.f;
        tile[ty + j][tx] = v;
    }
    __syncthreads();
    int t = ty * 32 + tx;
    #pragma unroll
    for (int s = 0; s < 2; s++) {
        int idx = t + s * 256;
        int n = idx >> 4;
        int kp = idx & 15;
        g_W2h[(size_t)(n0 + n) * KPC + (k0 >> 1) + kp] =
            pack2h(tile[2 * kp][n], tile[2 * kp + 1][n]);
    }
}

// ----------------------------------------------------------------------------
// SIMT split-K SGEMM for U projection
// ----------------------------------------------------------------------------
__global__ __launch_bounds__(256)
void sgemm_splitk(const float* __restrict__ A, int lda,
                  const float* __restrict__ B, int M, int N)
{
    const int z = blockIdx.z;
    const float* Az = A + z * 256;
    const float* Bz = B + (size_t)(z * 256) * N;
    float* Cz = g_Upart[z];

    __shared__ float As[8][128];
    __shared__ float Bs[8][128];
    const int tid = threadIdx.x;
    const int by = blockIdx.y;
    const int tx = tid & 15, ty = tid >> 4;
    const int aRow = tid >> 1, aCol = (tid & 1) * 4;
    const int bRow = tid >> 5, bCol = (tid & 31) * 4;
    const float* Ap = Az + (size_t)(by * 128 + aRow) * lda + aCol;
    const float* Bp = Bz + (size_t)bRow * N + bCol;

    float acc[8][8];
    #pragma unroll
    for (int i = 0; i < 8; i++)
        #pragma unroll
        for (int j = 0; j < 8; j++) acc[i][j] = 0.f;

    float4 a4 = *(const float4*)(Ap);
    float4 b4 = *(const float4*)(Bp);

    for (int k0 = 0; k0 < 256; k0 += 8) {
        As[aCol + 0][aRow] = a4.x;
        As[aCol + 1][aRow] = a4.y;
        As[aCol + 2][aRow] = a4.z;
        As[aCol + 3][aRow] = a4.w;
        *(float4*)&Bs[bRow][bCol] = b4;
        __syncthreads();
        if (k0 + 8 < 256) {
            a4 = *(const float4*)(Ap + k0 + 8);
            b4 = *(const float4*)(Bp + (size_t)(k0 + 8) * N);
        }
        #pragma unroll
        for (int kk = 0; kk < 8; kk++) {
            float4 a0 = *(const float4*)&As[kk][ty * 8];
            float4 a1 = *(const float4*)&As[kk][ty * 8 + 4];
            float4 b0 = *(const float4*)&Bs[kk][tx * 8];
            float4 b1 = *(const float4*)&Bs[kk][tx * 8 + 4];
            float ar[8] = {a0.x, a0.y, a0.z, a0.w, a1.x, a1.y, a1.z, a1.w};
            float br[8] = {b0.x, b0.y, b0.z, b0.w, b1.x, b1.y, b1.z, b1.w};
            #pragma unroll
            for (int i = 0; i < 8; i++)
                #pragma unroll
                for (int j = 0; j < 8; j++)
                    acc[i][j] = fmaf(ar[i], br[j], acc[i][j]);
        }
        __syncthreads();
    }
    #pragma unroll
    for (int i = 0; i < 8; i++) {
        int row = by * 128 + ty * 8 + i;
        #pragma unroll
        for (int j = 0; j < 8; j++)
            Cz[(size_t)row * N + tx * 8 + j] = acc[i][j];
    }
}

__global__ void ureduce_kernel()
{
    int gid = blockIdx.x * 256 + threadIdx.x;
    if (gid >= M_TOT * 128) return;
    int col = gid & 127;
    g_U[gid] = g_Upart[0][gid] + g_Upart[1][gid] + g_Upart[2][gid] + g_Upart[3][gid]
             + g_ubias[col];
}

// ----------------------------------------------------------------------------
// Precompute Bc + ubias
// ----------------------------------------------------------------------------
__global__ __launch_bounds__(256)
void combine_proj_kernel(const float* __restrict__ sig_Wr, const float* __restrict__ sig_Wi,
                         const float* __restrict__ A_r, const float* __restrict__ A_i)
{
    __shared__ float sAr[128][16], sAi[128][16];
    __shared__ float sWr[16][128], sWi[16][128];
    const int e = blockIdx.y;
    const int h0 = blockIdx.x * 16;
    const int tid = threadIdx.x;
    const int h_loc = tid >> 4, r = tid & 15;
    float aur = 0.f, aui = 0.f;

    for (int s0 = 0; s0 < S; s0 += 128) {
        for (int i = tid; i < 128 * 16; i += 256) {
            int s = i >> 4, rr = i & 15;
            sAr[s][rr] = A_r[((size_t)e * S + s0 + s) * R + rr];
            sAi[s][rr] = A_i[((size_t)e * S + s0 + s) * R + rr];
        }
        for (int i = tid; i < 16 * 128; i += 256) {
            int hh = i >> 7, ss = i & 127;
            sWr[hh][ss] = sig_Wr[(size_t)(h0 + hh) * S + s0 + ss];
            sWi[hh][ss] = sig_Wi[(size_t)(h0 + hh) * S + s0 + ss];
        }
        __syncthreads();
        #pragma unroll 4
        for (int s = 0; s < 128; s++) {
            float wr = sWr[h_loc][s], wi = sWi[h_loc][s];
            float ar = sAr[s][r],     ai = sAi[s][r];
            aur = fmaf(wr, ar, aur);
            aur = fmaf(-wi, ai, aur);
            aui = fmaf(wr, ai, aui);
            aui = fmaf(wi, ar, aui);
        }
        __syncthreads();
    }
    g_Bc[(size_t)(h0 + h_loc) * 128 + e * 32 + r]      = aur;
    g_Bc[(size_t)(h0 + h_loc) * 128 + e * 32 + 16 + r] = aui;
}

__global__ void ubias_kernel(const float* __restrict__ sig_br, const float* __restrict__ sig_bi,
                             const float* __restrict__ A_r, const float* __restrict__ A_i)
{
    int j = threadIdx.x;
    int e = j >> 5, half = (j >> 4) & 1, r = j & 15;
    float acc = 0.f;
    for (int s = 0; s < S; s++) {
        float ar = A_r[((size_t)e * S + s) * R + r];
        float ai = A_i[((size_t)e * S + s) * R + r];
        float br = sig_br[s], bi = sig_bi[s];
        acc += half ? (br * ai + bi * ar) : (br * ar - bi * ai);
    }
    g_ubias[j] = acc;
}

// ----------------------------------------------------------------------------
// pquv split-K: grid (H/64, E, 4), each z handles K chunk of 256.
// ----------------------------------------------------------------------------
__global__ __launch_bounds__(256)
void pquv_part_kernel(const float* __restrict__ eh_Wr, const float* __restrict__ eh_Wi,
                      const float* __restrict__ fu_Wr, const float* __restrict__ fu_Wi)
{
    __shared__ float2 sA[40][32];
    __shared__ float2 sB[32][64];
    const int e = blockIdx.y;
    const int z = blockIdx.z;
    const int col0 = blockIdx.x * 64;
    const int tid = threadIdx.x;
    const int c = tid & 63, rg = tid >> 6;
    const int row0 = rg * 10;
    const int nrows = (rg == 3) ? 8 : 10;

    float wc1[10], wc2[10];
    #pragma unroll
    for (int i = 0; i < 10; i++) { wc1[i] = 0.f; wc2[i] = 0.f; }

    for (int kc = 0; kc < 8; kc++) {
        int k0 = z * 256 + kc * 32;
        for (int i = tid; i < FDIM * 32; i += 256) {
            int f = i >> 5, k = i & 31;
            size_t off = ((size_t)e * FDIM + f) * H + k0 + k;
            sA[f][k] = make_float2(eh_Wr[off], eh_Wi[off]);
        }
        for (int i = tid; i < 32 * 64; i += 256) {
            int k = i >> 6, cc = i & 63;
            size_t off = ((size_t)e * H + k0 + k) * H + col0 + cc;
            sB[k][cc] = make_float2(fu_Wr[off], fu_Wi[off]);
        }
        __syncthreads();
        for (int k = 0; k < 32; k++) {
            float2 b = sB[k][c];
            #pragma unroll
            for (int i = 0; i < 10; i++) {
                if (i < nrows) {
                    float2 a = sA[row0 + i][k];
                    wc1[i] = fmaf(a.x, b.x, wc1[i]);
                    wc1[i] = fmaf(-a.y, b.y, wc1[i]);
                    wc2[i] = fmaf(a.x, b.y, wc2[i]);
                    wc2[i] = fmaf(a.y, b.x, wc2[i]);
                }
            }
        }
        __syncthreads();
    }
    #pragma unroll
    for (int i = 0; i < 10; i++) {
        if (i < nrows) {
            g_pqp[z][e][row0 + i][col0 + c] = wc1[i];
            g_uvp[z][e][row0 + i][col0 + c] = wc2[i];
        }
    }
}

// reduce partials and scatter into WF [304][2048]
__global__ void wf_reduce_kernel()
{
    int gid = blockIdx.x * 256 + threadIdx.x;
    if (gid >= E * FDIM * 1024) return;
    int cg = gid & 1023;
    int rem = gid >> 10;
    int row = rem % FDIM;
    int e = rem / FDIM;
    float wc1 = 0.f, wc2 = 0.f;
    #pragma unroll
    for (int z = 0; z < 4; z++) {
        wc1 += g_pqp[z][e][row][cg];
        wc2 += g_uvp[z][e][row][cg];
    }
    size_t b1 = (size_t)(e * 76 + row) * 2048;
    size_t b2 = (size_t)(e * 76 + 38 + row) * 2048;
    g_WF[b1 + cg]        = wc1;
    g_WF[b1 + 1024 + cg] = wc2;
    g_WF[b2 + cg]        = -wc2;
    g_WF[b2 + 1024 + cg] = wc1;
}

// ----------------------------------------------------------------------------
// crci / cgate
// ----------------------------------------------------------------------------
__global__ void crci_part_kernel(const float* __restrict__ eh_br, const float* __restrict__ eh_bi,
                                 const float* __restrict__ fu_Wr, const float* __restrict__ fu_Wi)
{
    const int o = blockIdx.x * 128 + threadIdx.x;
    const int eh0 = blockIdx.y * 64;
    float cr = 0.f, ci = 0.f;
    #pragma unroll 4
    for (int k = 0; k < 64; k++) {
        int eh = eh0 + k;
        float br = eh_br[eh], bi = eh_bi[eh];
        float wr = fu_Wr[(size_t)eh * H + o], wi = fu_Wi[(size_t)eh * H + o];
        cr = fmaf(br, wr, cr); cr = fmaf(-bi, wi, cr);
        ci = fmaf(br, wi, ci); ci = fmaf(bi, wr, ci);
    }
    g_CBpart[blockIdx.y][o]        = cr;
    g_CBpart[blockIdx.y][1024 + o] = ci;
}

__global__ void crci_reduce_kernel(const float* __restrict__ fu_br, const float* __restrict__ fu_bi)
{
    int o = blockIdx.x * 256 + threadIdx.x;
    float acc = (o < 1024) ? fu_br[o] : fu_bi[o - 1024];
    #pragma unroll
    for (int j = 0; j < 64; j++) acc += g_CBpart[j][o];
    g_CB[o] = acc;
}

__global__ void cgate_part_kernel(const float* __restrict__ g_W)
{
    const int o = blockIdx.x * 128 + threadIdx.x;
    const int h0 = blockIdx.y * 128;
    float acc = 0.f;
    #pragma unroll 4
    for (int k = 0; k < 128; k++) {
        int h = h0 + k;
        acc = fmaf(g_CB[h],        g_W[(size_t)(H + h) * H + o],     acc);
        acc = fmaf(g_CB[1024 + h], g_W[(size_t)(2 * H + h) * H + o], acc);
    }
    g_cgpart[blockIdx.y][o] = acc;
}

__global__ void cgate_reduce_kernel(const float* __restrict__ g_b)
{
    int o = blockIdx.x * 256 + threadIdx.x;
    float acc = g_b[o];
    #pragma unroll
    for (int j = 0; j < 8; j++) acc += g_cgpart[j][o];
    g_cgate[o] = acc;
}

// ----------------------------------------------------------------------------
// gcg split-K: grid (H/64, 8, 4); z handles K chunk of 512.
// ----------------------------------------------------------------------------
__global__ __launch_bounds__(256)
void gcg_part_kernel(const float* __restrict__ g_W)
{
    __shared__ float sA[40][32];
    __shared__ float sB[32][64];
    const int p0 = blockIdx.y * 38;
    const int z = blockIdx.z;
    const int col0 = blockIdx.x * 64;
    const int tid = threadIdx.x;
    const int c = tid & 63, rg = tid >> 6;
    const int row0 = rg * 10;
    const int nrows = (rg == 3) ? 8 : 10;

    float acc[10];
    #pragma unroll
    for (int i = 0; i < 10; i++) acc[i] = 0.f;

    for (int kc = 0; kc < 16; kc++) {
        int k0 = z * 512 + kc * 32;
        for (int i = tid; i < 38 * 32; i += 256) {
            int pp = i >> 5, k = i & 31;
            sA[pp][k] = g_WF[(size_t)(p0 + pp) * 2048 + k0 + k];
        }
        for (int i = tid; i < 32 * 64; i += 256) {
            int k = i >> 6, cc = i & 63;
            sB[k][cc] = g_W[(size_t)(H + k0 + k) * H + col0 + cc];
        }
        __syncthreads();
        for (int k = 0; k < 32; k++) {
            float b = sB[k][c];
            #pragma unroll
            for (int i = 0; i < 10; i++)
                if (i < nrows)
                    acc[i] = fmaf(sA[row0 + i][k], b, acc[i]);
        }
        __syncthreads();
    }
    #pragma unroll
    for (int i = 0; i < 10; i++)
        if (i < nrows)
            g_gcgp[z][p0 + row0 + i][col0 + c] = acc[i];
}

__global__ void gcg_reduce_kernel()
{
    int gid = blockIdx.x * 256 + threadIdx.x;
    if (gid >= GDIM * 1024) return;
    int col = gid & 1023;
    int p = gid >> 10;
    float acc = 0.f;
    #pragma unroll
    for (int z = 0; z < 4; z++) acc += g_gcgp[z][p][col];
    g_GcG[(size_t)p * 1024 + col] = acc;
}

// ----------------------------------------------------------------------------
// A-side packing
// ----------------------------------------------------------------------------
__global__ void pack_G_kernel()
{
    int gid = blockIdx.x * 256 + threadIdx.x;
    if (gid >= M_TOT * KPG) return;
    int m = gid / KPG, kp = gid % KPG;
    float v0 = 0.f, v1 = 0.f;
    if (kp < GDIM / 2) {
        v0 = g_G[(size_t)m * GDIM + 2 * kp];
        v1 = g_G[(size_t)m * GDIM + 2 * kp + 1];
    }
    split2(v0, v1, g_Gh[gid], g_Gl[gid]);
}

__global__ void concat2_kernel(const float* __restrict__ x)
{
    const int row = blockIdx.x;
    const float* xr = x + (size_t)row * H;
    const float* gr = g_G + (size_t)row * GDIM;
    const float* fr = g_FRF + (size_t)row * 2048;
    uint32_t* dh = g_CCh + (size_t)row * KPC;

    for (int kp = threadIdx.x; kp < KPC; kp += 256) {
        float v0, v1;
        if (kp < 512) {
            v0 = xr[2 * kp]; v1 = xr[2 * kp + 1];
        } else if (kp < 664) {
            int cg = 2 * kp - 1024;
            v0 = gr[cg]; v1 = gr[cg + 1];
        } else if (kp < 1176) {
            int h = 2 * kp - 1328;
            float a0 = fr[h],     b0 = fr[1024 + h];
            float a1 = fr[h + 1], b1 = fr[1024 + h + 1];
            v0 = sqrtf(a0 * a0 + b0 * b0 + EPS);
            v1 = sqrtf(a1 * a1 + b1 * b1 + EPS);
        } else {
            v0 = 0.f; v1 = 0.f;
        }
        dh[kp] = pack2h(v0, v1);
    }
}

// ----------------------------------------------------------------------------
// Recurrence as chunked parallel scan
// ----------------------------------------------------------------------------
__global__ void recur_p1(const float* __restrict__ lam_r, const float* __restrict__ lam_i)
{
    const int bid = blockIdx.x;
    const int seq = bid >> 5, c = bid & 31;
    const int e = seq >> 2, b = seq & 3;
    const int lane = threadIdx.x;
    if (lane >= R) return;
    const float lr = 0.9f * lam_r[e * R + lane];
    const float li = 0.9f * lam_i[e * R + lane];
    const float* up = g_U + ((size_t)b * T + c * LCH) * 128 + e * 32 + lane;
    float hr = 0.f, hi = 0.f;
    #pragma unroll 4
    for (int s = 0; s < LCH; s++) {
        float ur = up[(size_t)s * 128];
        float ui = up[(size_t)s * 128 + 16];
        float nhr = fmaf(lr, hr, fmaf(-li, hi, ETA * ur));
        float nhi = fmaf(lr, hi, fmaf(li, hr, ETA * ui));
        hr = nhr; hi = nhi;
    }
    g_hloc[seq][c][lane] = make_float2(hr, hi);
}

__global__ void recur_combine(const float* __restrict__ lam_r, const float* __restrict__ lam_i)
{
    int tid = threadIdx.x;
    int seq = tid >> 4, lane = tid & 15;
    int e = seq >> 2;
    float lr = 0.9f * lam_r[e * R + lane];
    float li = 0.9f * lam_i[e * R + lane];
    float pr = 1.f, pi = 0.f;
    for (int k = 0; k < LCH; k++) {
        float nr = pr * lr - pi * li;
        pi = pr * li + pi * lr;
        pr = nr;
    }
    float cr = 0.f, ci = 0.f;
    for (int c = 0; c < NCH; c++) {
        g_hinit[seq][c][lane] = make_float2(cr, ci);
        float2 hl = g_hloc[seq][c][lane];
        float nr = pr * cr - pi * ci + hl.x;
        ci = pr * ci + pi * cr + hl.y;
        cr = nr;
    }
}

__global__ void recur_p2(const float* __restrict__ lam_r, const float* __restrict__ lam_i)
{
    const int bid = blockIdx.x;
    const int seq = bid >> 5, c = bid & 31;
    const int e = seq >> 2, b = seq & 3;
    const int lane = threadIdx.x;
    if (lane >= R) return;

    const float lr = 0.9f * lam_r[e * R + lane];
    const float li = 0.9f * lam_i[e * R + lane];
    const int t0 = c * LCH;
    const float* up = g_U + ((size_t)b * T + t0) * 128 + e * 32 + lane;
    float* gp = g_G + ((size_t)b * T + t0) * GDIM + e * 76;

    float2 h0 = g_hinit[seq][c][lane];
    float hr = h0.x, hi = h0.y, acc = 0.f;
    const unsigned mask = 0xFFFFu;

    float u_r = up[0];
    float u_i = up[16];

    for (int s = 0; s < LCH; s++) {
        int sn = (t0 + s + 1 < T) ? (s + 1) : s;
        float nu_r = up[(size_t)sn * 128];
        float nu_i = up[(size_t)sn * 128 + 16];

        float nhr = lr * hr - li * hi + ETA * u_r;
        float nhi = lr * hi + li * hr + ETA * u_i;
        float m2 = nhr * nhr + nhi * nhi;

        float sm = m2, mx = m2;
        #pragma unroll
        for (int off = 8; off >= 1; off >>= 1) {
            sm += __shfl_xor_sync(mask, sm, off, 16);
            mx = fmaxf(mx, __shfl_xor_sync(mask, mx, off, 16));
        }
        float m_mean = sm * (1.f / 16.f);
        acc = 0.99f * acc + 0.01f * m_mean;
        float inv = rsqrtf(m_mean + EPS);
        float hnr = nhr * inv, hni = nhi * inv;

        float sr = hnr, si = hni;
        #pragma unroll
        for (int off = 8; off >= 1; off >>= 1) {
            sr += __shfl_xor_sync(mask, sr, off, 16);
            si += __shfl_xor_sync(mask, si, off, 16);
        }
        float mr = sr * (1.f / 16.f);
        float mi = si * (1.f / 16.f);

        float* g_t = gp + (size_t)s * GDIM;
        g_t[6 + lane]           = hnr;
        g_t[6 + R + lane]       = hni;
        g_t[38 + 6 + lane]      = hni;
        g_t[38 + 6 + R + lane]  = -hnr;
        if (lane == 0) {
            g_t[0] = mr;
            g_t[1] = mi;
            g_t[2] = sqrtf(m_mean + EPS);
            g_t[3] = sqrtf(mx + EPS);
            g_t[38 + 0] = mi;
            g_t[38 + 1] = -mr;
            g_t[38 + 2] = 0.f; g_t[38 + 3] = 0.f; g_t[38 + 4] = 0.f; g_t[38 + 5] = 0.f;
            g_lacc[seq][t0 + s] = acc;
        }
        hr = nhr; hi = nhi;
        u_r = nu_r; u_i = nu_i;
    }
    if (lane == 0) g_accend[seq][c] = acc;
}

__global__ void acc_combine_kernel()
{
    int seq = threadIdx.x;
    if (seq >= 16) return;
    float p = 1.f;
    for (int k = 0; k < LCH; k++) p *= 0.99f;
    float A = 0.f;
    for (int c = 0; c < NCH; c++) {
        g_accinit[seq][c] = A;
        A = p * A + g_accend[seq][c];
    }
}

__global__ void acc_fix_kernel()
{
    int gid = blockIdx.x * 256 + threadIdx.x;
    if (gid >= 16 * T) return;
    int seq = gid >> 11;
    int t = gid & (T - 1);
    int c = t >> 6;
    int k = (t & (LCH - 1)) + 1;
    float acc = __powf(0.99f, (float)k) * g_accinit[seq][c] + g_lacc[seq][t];
    int e = seq >> 2, b = seq & 3;
    float* g_t = g_G + ((size_t)b * T + t) * GDIM + e * 76;
    g_t[4] = acc;
    g_t[5] = log1pf(acc);
}

// ----------------------------------------------------------------------------
// Launch: precompute forked onto a side stream, joined before gemm_bf3.
// ----------------------------------------------------------------------------
extern "C" void kernel_launch(void* const* d_in, const int* in_sizes, int n_in,
                              void* d_out, int out_size)
{
    const float* x      = (const float*)d_in[0];
    const float* sig_Wr = (const float*)d_in[1];
    const float* sig_Wi = (const float*)d_in[2];
    const float* sig_br = (const float*)d_in[3];
    const float* sig_bi = (const float*)d_in[4];
    const float* A_r    = (const float*)d_in[5];
    const float* A_i    = (const float*)d_in[6];
    const float* lam_r  = (const float*)d_in[7];
    const float* lam_i  = (const float*)d_in[8];
    const float* eh_Wr  = (const float*)d_in[9];
    const float* eh_Wi  = (const float*)d_in[10];
    const float* eh_br  = (const float*)d_in[11];
    const float* eh_bi  = (const float*)d_in[12];
    const float* fu_Wr  = (const float*)d_in[13];
    const float* fu_Wi  = (const float*)d_in[14];
    const float* fu_br  = (const float*)d_in[15];
    const float* fu_bi  = (const float*)d_in[16];
    const float* gW     = (const float*)d_in[17];
    const float* gb     = (const float*)d_in[18];
    float* out = (float*)d_out;

    float *Bc, *FRF, *CB, *cgate, *WF;
    uint32_t *Gh, *Gl, *WFh, *WFl, *CCh, *W2h;
    cudaGetSymbolAddress((void**)&Bc,    g_Bc);
    cudaGetSymbolAddress((void**)&FRF,   g_FRF);
    cudaGetSymbolAddress((void**)&CB,    g_CB);
    cudaGetSymbolAddress((void**)&cgate, g_cgate);
    cudaGetSymbolAddress((void**)&WF,    g_WF);
    cudaGetSymbolAddress((void**)&Gh,    g_Gh);
    cudaGetSymbolAddress((void**)&Gl,    g_Gl);
    cudaGetSymbolAddress((void**)&WFh,   g_WFh);
    cudaGetSymbolAddress((void**)&WFl,   g_WFl);
    cudaGetSymbolAddress((void**)&CCh,   g_CCh);
    cudaGetSymbolAddress((void**)&W2h,   g_W2h);

    cudaFuncSetAttribute(gemm_bf3, cudaFuncAttributeMaxDynamicSharedMemorySize, SMEM4);
    cudaFuncSetAttribute(gemm_f16gate, cudaFuncAttributeMaxDynamicSharedMemorySize, SMEM2);

    static cudaStream_t sP = nullptr;
    static cudaEvent_t evFork = nullptr, evJoin = nullptr;
    if (sP == nullptr) {
        cudaStreamCreateWithFlags(&sP, cudaStreamNonBlocking);
        cudaEventCreateWithFlags(&evFork, cudaEventDisableTiming);
        cudaEventCreateWithFlags(&evJoin, cudaEventDisableTiming);
    }

    cudaEventRecord(evFork, 0);
    cudaStreamWaitEvent(sP, evFork, 0);

    // --- precompute (weight composition) on side stream ---
    pquv_part_kernel<<<dim3(H / 64, E, 4), 256, 0, sP>>>(eh_Wr, eh_Wi, fu_Wr, fu_Wi);
    wf_reduce_kernel<<<(E * FDIM * 1024 + 255) / 256, 256, 0, sP>>>();
    crci_part_kernel<<<dim3(8, 64), 128, 0, sP>>>(eh_br, eh_bi, fu_Wr, fu_Wi);
    crci_reduce_kernel<<<8, 256, 0, sP>>>(fu_br, fu_bi);
    tpack_kernel<<<dim3(2048 / 32, KEG / 32), dim3(32, 8), 0, sP>>>(WF, GDIM, 2048, KPG, WFh, WFl);
    gcg_part_kernel<<<dim3(H / 64, 8, 4), 256, 0, sP>>>(gW);
    gcg_reduce_kernel<<<(GDIM * 1024 + 255) / 256, 256, 0, sP>>>();
    gate_wpack_kernel<<<dim3(1024 / 32, KEC / 32), dim3(32, 8), 0, sP>>>(gW);
    cgate_part_kernel<<<dim3(8, 8), 128, 0, sP>>>(gW);
    cgate_reduce_kernel<<<4, 256, 0, sP>>>(gb);
    cudaEventRecord(evJoin, sP);

    // --- main path on default stream ---
    combine_proj_kernel<<<dim3(64, E), 256>>>(sig_Wr, sig_Wi, A_r, A_i);
    ubias_kernel<<<1, 128>>>(sig_br, sig_bi, A_r, A_i);
    sgemm_splitk<<<dim3(1, M_TOT / 128, 4), 256>>>(x, H, Bc, M_TOT, 128);
    ureduce_kernel<<<(M_TOT * 128 + 255) / 256, 256>>>();
    recur_p1<<<16 * NCH, 32>>>(lam_r, lam_i);
    recur_combine<<<1, 256>>>(lam_r, lam_i);
    recur_p2<<<16 * NCH, 32>>>(lam_r, lam_i);
    acc_combine_kernel<<<1, 16>>>();
    acc_fix_kernel<<<(16 * T + 255) / 256, 256>>>();
    pack_G_kernel<<<(M_TOT * KPG + 255) / 256, 256>>>();

    cudaStreamWaitEvent(0, evJoin, 0);

    // FRF = G @ WF + CB  (bf16 3-term)
    gemm_bf3<<<dim3(2048 / 128, M_TOT / 128), 256, SMEM4>>>(
        Gh, Gl, WFh, WFl, FRF, M_TOT, 2048, KEG, CB);
    concat2_kernel<<<M_TOT, 256>>>(x);
    // gate GEMM (fp16 single) + fused epilogue
    gemm_f16gate<<<dim3(H / 128, M_TOT / 128), 256, SMEM2>>>(
        CCh, W2h, out, M_TOT, H, KEC, cgate, FRF, 2048, x, H);
}

// round 16
// speedup vs baseline: 14.9139x; 1.0978x over previous
#include <cuda_runtime.h>
#include <cuda_bf16.h>
#include <cuda_fp16.h>
#include <math.h>
#include <stdint.h>

#define BSZ 4
#define T 2048
#define H 1024
#define S 512
#define R 16
#define E 4
#define FDIM 38             // 6 + 2*R
#define M_TOT (BSZ*T)       // 8192
#define GDIM (E*2*FDIM)     // 304
#define CCW (H + GDIM + H)  // 2352
#define KEG 320             // padded K for FRF GEMM
#define KEC 2368            // padded K for gate GEMM
#define KPG (KEG/2)
#define KPC (KEC/2)
#define NCH 32
#define LCH 64
#define ETA 0.1f
#define EPS 1e-6f

// ----------------------------------------------------------------------------
// Scratch
// ----------------------------------------------------------------------------
__device__ float g_Bc[H * 128];
__device__ float g_ubias[128];
__device__ float g_Upart[4][M_TOT * 128];
__device__ float g_U[M_TOT * 128];
__device__ float g_G[(size_t)M_TOT * GDIM];
__device__ float g_WF[(size_t)GDIM * 2048];
__device__ float g_CB[2048];
__device__ float g_CBpart[64][2048];
__device__ float g_cgpart[8][1024];
__device__ float g_FRF[(size_t)M_TOT * 2048];
__device__ float g_cgate[H];
// pquv / gcg split-K partials
__device__ float g_pqp[4][E][FDIM][1024];
__device__ float g_uvp[4][E][FDIM][1024];
__device__ float g_gcgp[4][GDIM][1024];
__device__ float g_GcG[(size_t)GDIM * 1024];
// FRF operands: A split fp16 (Gh+Gl), B single fp16 (WFh)
__device__ uint32_t g_Gh[(size_t)M_TOT * KPG];
__device__ uint32_t g_Gl[(size_t)M_TOT * KPG];
__device__ uint32_t g_WFh[(size_t)2048 * KPG];
// gate operands: fp16 single (A and B)
__device__ uint32_t g_CCh[(size_t)M_TOT * KPC];
__device__ uint32_t g_W2h[(size_t)1024 * KPC];
// recurrence scan state
__device__ float2 g_hloc[16][NCH][16];
__device__ float2 g_hinit[16][NCH][16];
__device__ float g_lacc[16][T];
__device__ float g_accend[16][NCH];
__device__ float g_accinit[16][NCH];

// ----------------------------------------------------------------------------
// helpers
// ----------------------------------------------------------------------------
__device__ __forceinline__ void split2h(float v0, float v1, uint32_t& ph, uint32_t& pl)
{
    __half2 h2 = __floats2half2_rn(v0, v1);
    float r0 = v0 - __half2float(__low2half(h2));
    float r1 = v1 - __half2float(__high2half(h2));
    __half2 l2 = __floats2half2_rn(r0, r1);
    ph = *reinterpret_cast<uint32_t*>(&h2);
    pl = *reinterpret_cast<uint32_t*>(&l2);
}

__device__ __forceinline__ uint32_t pack2h(float v0, float v1)
{
    __half2 h2 = __floats2half2_rn(v0, v1);
    return *reinterpret_cast<uint32_t*>(&h2);
}

__device__ __forceinline__ uint32_t smem_u32_of(const void* p)
{
    uint32_t a;
    asm("{ .reg .u64 t; cvta.to.shared.u64 t, %1; cvt.u32.u64 %0, t; }" : "=r"(a) : "l"(p));
    return a;
}

__device__ __forceinline__ void mma_f16(float* d, const uint32_t* a, const uint32_t* b)
{
    asm volatile(
        "mma.sync.aligned.m16n8k16.row.col.f32.f16.f16.f32 "
        "{%0,%1,%2,%3}, {%4,%5,%6,%7}, {%8,%9}, {%0,%1,%2,%3};"
        : "+f"(d[0]), "+f"(d[1]), "+f"(d[2]), "+f"(d[3])
        : "r"(a[0]), "r"(a[1]), "r"(a[2]), "r"(a[3]), "r"(b[0]), "r"(b[1]));
}

#define LDSM4(r0, r1, r2, r3, addr) \
    asm volatile("ldmatrix.sync.aligned.m8n8.x4.shared.b16 {%0,%1,%2,%3}, [%4];" \
        : "=r"(r0), "=r"(r1), "=r"(r2), "=r"(r3) : "r"(addr))

// pipelined-GEMM smem geometry
#define NSTG 3
#define ROWU 12                      // u32 per smem row: 8 data + 4 pad (48B)
#define TILE_U (128 * ROWU)          // 1536 u32 = 6 KB

// ----------------------------------------------------------------------------
// fp16 pipelined GEMM (ldmatrix fragments):
//   ASPLIT=1: A = Ah + Al (2 mma/fragment), ASPLIT=0: A single.
//   EPI=1: g = sigmoid(v); C = g*e1 + (1-g)*e2; else C = v.
// C[M,N] = A[M,KE] @ Bt[N,KE]^T + bias.  grid (N/128, M/128), 256 thr.
// ----------------------------------------------------------------------------
template<int ASPLIT, int EPI>
__global__ __launch_bounds__(256)
void gemm_f16(const uint32_t* __restrict__ Ah, const uint32_t* __restrict__ Al,
              const uint32_t* __restrict__ B,
              float* __restrict__ C, int M, int N, int KE,
              const float* __restrict__ bias,
              const float* __restrict__ e1, int ld1,
              const float* __restrict__ e2, int ld2)
{
    extern __shared__ uint32_t sm[];
    const uint32_t smem_base = smem_u32_of(sm);
    const int tid = threadIdx.x;
    const int wid = tid >> 5, lane = tid & 31;
    const int wm = wid & 1, wn = wid >> 1;
    const int grp = lane >> 2, tig = lane & 3;
    const int bx = blockIdx.x, by = blockIdx.y;
    const int KP = KE >> 1;
    const int NC = KE >> 4;

    const int NT = 2 + ASPLIT;            // tiles per stage
    const int STGU = NT * TILE_U;
    const uint32_t TBOFF = (1 + ASPLIT) * TILE_U * 4;

    // cp.async: one 16B unit per tile per chunk per thread
    const int crow = tid >> 1, c16 = tid & 1;
    const uint32_t* gsrc0 = Ah + (size_t)(by * 128 + crow) * KP + c16 * 4;
    const uint32_t* gsrc1 = ASPLIT ? (Al + (size_t)(by * 128 + crow) * KP + c16 * 4) : nullptr;
    const uint32_t* gsrc2 = B + (size_t)(bx * 128 + crow) * KP + c16 * 4;
    const uint32_t dst0 = smem_base + (crow * ROWU + c16 * 4) * 4;

    // ldmatrix per-lane offsets (bytes)
    const uint32_t aoff = ((lane & 15) * ROWU + (lane >> 4) * 4) * 4;
    const uint32_t boff = (((lane & 7) + ((lane >> 4) << 3)) * ROWU + (((lane >> 3) & 1) << 2)) * 4;

    float acc[4][4][4];
    #pragma unroll
    for (int i = 0; i < 4; i++)
        #pragma unroll
        for (int j = 0; j < 4; j++)
            #pragma unroll
            for (int q = 0; q < 4; q++) acc[i][j][q] = 0.f;

#define ISSUE(chunk) do { \
        uint32_t db_ = dst0 + ((chunk) % NSTG) * (STGU * 4); \
        asm volatile("cp.async.cg.shared.global [%0], [%1], 16;" :: "r"(db_), "l"(gsrc0 + (chunk) * 8)); \
        if (ASPLIT) \
            asm volatile("cp.async.cg.shared.global [%0], [%1], 16;" :: "r"(db_ + TILE_U * 4), "l"(gsrc1 + (chunk) * 8)); \
        asm volatile("cp.async.cg.shared.global [%0], [%1], 16;" :: "r"(db_ + TBOFF), "l"(gsrc2 + (chunk) * 8)); \
        asm volatile("cp.async.commit_group;"); \
    } while (0)

    ISSUE(0);
    ISSUE(1);

    for (int i = 0; i < NC; i++) {
        if (i + 1 < NC) asm volatile("cp.async.wait_group 1;");
        else            asm volatile("cp.async.wait_group 0;");
        __syncthreads();
        if (i + 2 < NC) ISSUE(i + 2);

        const uint32_t stb = smem_base + (i % NSTG) * (STGU * 4);

        // B fragments: 2 ldmatrix.x4, each covering two j-tiles
        uint32_t bfr[4][2];
        {
            uint32_t b0 = stb + TBOFF + (uint32_t)(wn * 32) * ROWU * 4 + boff;
            LDSM4(bfr[0][0], bfr[0][1], bfr[1][0], bfr[1][1], b0);
            LDSM4(bfr[2][0], bfr[2][1], bfr[3][0], bfr[3][1], b0 + 16 * ROWU * 4);
        }
        #pragma unroll
        for (int ii = 0; ii < 4; ii++) {
            uint32_t aB = stb + (uint32_t)(wm * 64 + ii * 16) * ROWU * 4 + aoff;
            uint32_t ah[4];
            LDSM4(ah[0], ah[1], ah[2], ah[3], aB);
            if (ASPLIT) {
                uint32_t al[4];
                LDSM4(al[0], al[1], al[2], al[3], aB + TILE_U * 4);
                #pragma unroll
                for (int j = 0; j < 4; j++) {
                    mma_f16(acc[ii][j], ah, bfr[j]);
                    mma_f16(acc[ii][j], al, bfr[j]);
                }
            } else {
                #pragma unroll
                for (int j = 0; j < 4; j++)
                    mma_f16(acc[ii][j], ah, bfr[j]);
            }
        }
    }
#undef ISSUE

    #pragma unroll
    for (int i = 0; i < 4; i++) {
        #pragma unroll
        for (int j = 0; j < 4; j++) {
            int row0 = by * 128 + wm * 64 + i * 16 + grp;
            int col0 = bx * 128 + wn * 32 + j * 8 + tig * 2;
            #pragma unroll
            for (int q = 0; q < 4; q++) {
                int row = row0 + (q >> 1) * 8;
                int col = col0 + (q & 1);
                float v = acc[i][j][q] + bias[col];
                if (EPI == 0) {
                    C[(size_t)row * N + col] = v;
                } else {
                    float g = 1.f / (1.f + expf(-v));
                    C[(size_t)row * N + col] =
                        g * e1[(size_t)row * ld1 + col] + (1.f - g) * e2[(size_t)row * ld2 + col];
                }
            }
        }
    }
}

#define SMEMF (NSTG * 3 * TILE_U * 4)   // 55296 B (FRF: Ah+Al+B)
#define SMEMG (NSTG * 2 * TILE_U * 4)   // 36864 B (gate: A+B)

// ----------------------------------------------------------------------------
// transpose-pack fp16 single: src fp32 [K][N] -> dh [N][KP2]
// ----------------------------------------------------------------------------
__global__ void tpack_h_kernel(const float* __restrict__ src, int K, int N, int KP2,
                               uint32_t* __restrict__ dh)
{
    __shared__ float tile[32][33];
    const int n0 = blockIdx.x * 32;
    const int k0 = blockIdx.y * 32;
    const int tx = threadIdx.x, ty = threadIdx.y;
    #pragma unroll
    for (int j = 0; j < 32; j += 8) {
        int k = k0 + ty + j;
        tile[ty + j][tx] = (k < K) ? src[(size_t)k * N + n0 + tx] : 0.f;
    }
    __syncthreads();
    int t = ty * 32 + tx;
    #pragma unroll
    for (int s = 0; s < 2; s++) {
        int idx = t + s * 256;
        int n = idx >> 4;
        int kp = idx & 15;
        dh[(size_t)(n0 + n) * KP2 + (k0 >> 1) + kp] =
            pack2h(tile[2 * kp][n], tile[2 * kp + 1][n]);
    }
}

// ----------------------------------------------------------------------------
// gate weight pack (fp16 single), sourced from gW rows + GcG
// ----------------------------------------------------------------------------
__global__ void gate_wpack_kernel(const float* __restrict__ g_W)
{
    __shared__ float tile[32][33];
    const int n0 = blockIdx.x * 32;
    const int k0 = blockIdx.y * 32;
    const int tx = threadIdx.x, ty = threadIdx.y;
    #pragma unroll
    for (int j = 0; j < 32; j += 8) {
        int k = k0 + ty + j;
        float v;
        if (k < 1024)       v = g_W[(size_t)k * H + n0 + tx];
        else if (k < 1328)  v = g_GcG[(size_t)(k - 1024) * 1024 + n0 + tx];
        else if (k < 2352)  v = g_W[(size_t)(3 * 1024 + (k - 1328)) * H + n0 + tx];
        else                v = 0.f;
        tile[ty + j][tx] = v;
    }
    __syncthreads();
    int t = ty * 32 + tx;
    #pragma unroll
    for (int s = 0; s < 2; s++) {
        int idx = t + s * 256;
        int n = idx >> 4;
        int kp = idx & 15;
        g_W2h[(size_t)(n0 + n) * KPC + (k0 >> 1) + kp] =
            pack2h(tile[2 * kp][n], tile[2 * kp + 1][n]);
    }
}

// ----------------------------------------------------------------------------
// SIMT split-K SGEMM for U projection
// ----------------------------------------------------------------------------
__global__ __launch_bounds__(256)
void sgemm_splitk(const float* __restrict__ A, int lda,
                  const float* __restrict__ B, int M, int N)
{
    const int z = blockIdx.z;
    const float* Az = A + z * 256;
    const float* Bz = B + (size_t)(z * 256) * N;
    float* Cz = g_Upart[z];

    __shared__ float As[8][128];
    __shared__ float Bs[8][128];
    const int tid = threadIdx.x;
    const int by = blockIdx.y;
    const int tx = tid & 15, ty = tid >> 4;
    const int aRow = tid >> 1, aCol = (tid & 1) * 4;
    const int bRow = tid >> 5, bCol = (tid & 31) * 4;
    const float* Ap = Az + (size_t)(by * 128 + aRow) * lda + aCol;
    const float* Bp = Bz + (size_t)bRow * N + bCol;

    float acc[8][8];
    #pragma unroll
    for (int i = 0; i < 8; i++)
        #pragma unroll
        for (int j = 0; j < 8; j++) acc[i][j] = 0.f;

    float4 a4 = *(const float4*)(Ap);
    float4 b4 = *(const float4*)(Bp);

    for (int k0 = 0; k0 < 256; k0 += 8) {
        As[aCol + 0][aRow] = a4.x;
        As[aCol + 1][aRow] = a4.y;
        As[aCol + 2][aRow] = a4.z;
        As[aCol + 3][aRow] = a4.w;
        *(float4*)&Bs[bRow][bCol] = b4;
        __syncthreads();
        if (k0 + 8 < 256) {
            a4 = *(const float4*)(Ap + k0 + 8);
            b4 = *(const float4*)(Bp + (size_t)(k0 + 8) * N);
        }
        #pragma unroll
        for (int kk = 0; kk < 8; kk++) {
            float4 a0 = *(const float4*)&As[kk][ty * 8];
            float4 a1 = *(const float4*)&As[kk][ty * 8 + 4];
            float4 b0 = *(const float4*)&Bs[kk][tx * 8];
            float4 b1 = *(const float4*)&Bs[kk][tx * 8 + 4];
            float ar[8] = {a0.x, a0.y, a0.z, a0.w, a1.x, a1.y, a1.z, a1.w};
            float br[8] = {b0.x, b0.y, b0.z, b0.w, b1.x, b1.y, b1.z, b1.w};
            #pragma unroll
            for (int i = 0; i < 8; i++)
                #pragma unroll
                for (int j = 0; j < 8; j++)
                    acc[i][j] = fmaf(ar[i], br[j], acc[i][j]);
        }
        __syncthreads();
    }
    #pragma unroll
    for (int i = 0; i < 8; i++) {
        int row = by * 128 + ty * 8 + i;
        #pragma unroll
        for (int j = 0; j < 8; j++)
            Cz[(size_t)row * N + tx * 8 + j] = acc[i][j];
    }
}

__global__ void ureduce_kernel()
{
    int gid = blockIdx.x * 256 + threadIdx.x;
    if (gid >= M_TOT * 128) return;
    int col = gid & 127;
    g_U[gid] = g_Upart[0][gid] + g_Upart[1][gid] + g_Upart[2][gid] + g_Upart[3][gid]
             + g_ubias[col];
}

// ----------------------------------------------------------------------------
// Precompute Bc + ubias
// ----------------------------------------------------------------------------
__global__ __launch_bounds__(256)
void combine_proj_kernel(const float* __restrict__ sig_Wr, const float* __restrict__ sig_Wi,
                         const float* __restrict__ A_r, const float* __restrict__ A_i)
{
    __shared__ float sAr[128][16], sAi[128][16];
    __shared__ float sWr[16][128], sWi[16][128];
    const int e = blockIdx.y;
    const int h0 = blockIdx.x * 16;
    const int tid = threadIdx.x;
    const int h_loc = tid >> 4, r = tid & 15;
    float aur = 0.f, aui = 0.f;

    for (int s0 = 0; s0 < S; s0 += 128) {
        for (int i = tid; i < 128 * 16; i += 256) {
            int s = i >> 4, rr = i & 15;
            sAr[s][rr] = A_r[((size_t)e * S + s0 + s) * R + rr];
            sAi[s][rr] = A_i[((size_t)e * S + s0 + s) * R + rr];
        }
        for (int i = tid; i < 16 * 128; i += 256) {
            int hh = i >> 7, ss = i & 127;
            sWr[hh][ss] = sig_Wr[(size_t)(h0 + hh) * S + s0 + ss];
            sWi[hh][ss] = sig_Wi[(size_t)(h0 + hh) * S + s0 + ss];
        }
        __syncthreads();
        #pragma unroll 4
        for (int s = 0; s < 128; s++) {
            float wr = sWr[h_loc][s], wi = sWi[h_loc][s];
            float ar = sAr[s][r],     ai = sAi[s][r];
            aur = fmaf(wr, ar, aur);
            aur = fmaf(-wi, ai, aur);
            aui = fmaf(wr, ai, aui);
            aui = fmaf(wi, ar, aui);
        }
        __syncthreads();
    }
    g_Bc[(size_t)(h0 + h_loc) * 128 + e * 32 + r]      = aur;
    g_Bc[(size_t)(h0 + h_loc) * 128 + e * 32 + 16 + r] = aui;
}

__global__ void ubias_kernel(const float* __restrict__ sig_br, const float* __restrict__ sig_bi,
                             const float* __restrict__ A_r, const float* __restrict__ A_i)
{
    int j = threadIdx.x;
    int e = j >> 5, half = (j >> 4) & 1, r = j & 15;
    float acc = 0.f;
    for (int s = 0; s < S; s++) {
        float ar = A_r[((size_t)e * S + s) * R + r];
        float ai = A_i[((size_t)e * S + s) * R + r];
        float br = sig_br[s], bi = sig_bi[s];
        acc += half ? (br * ai + bi * ar) : (br * ar - bi * ai);
    }
    g_ubias[j] = acc;
}

// ----------------------------------------------------------------------------
// pquv split-K
// ----------------------------------------------------------------------------
__global__ __launch_bounds__(256)
void pquv_part_kernel(const float* __restrict__ eh_Wr, const float* __restrict__ eh_Wi,
                      const float* __restrict__ fu_Wr, const float* __restrict__ fu_Wi)
{
    __shared__ float2 sA[40][32];
    __shared__ float2 sB[32][64];
    const int e = blockIdx.y;
    const int z = blockIdx.z;
    const int col0 = blockIdx.x * 64;
    const int tid = threadIdx.x;
    const int c = tid & 63, rg = tid >> 6;
    const int row0 = rg * 10;
    const int nrows = (rg == 3) ? 8 : 10;

    float wc1[10], wc2[10];
    #pragma unroll
    for (int i = 0; i < 10; i++) { wc1[i] = 0.f; wc2[i] = 0.f; }

    for (int kc = 0; kc < 8; kc++) {
        int k0 = z * 256 + kc * 32;
        for (int i = tid; i < FDIM * 32; i += 256) {
            int f = i >> 5, k = i & 31;
            size_t off = ((size_t)e * FDIM + f) * H + k0 + k;
            sA[f][k] = make_float2(eh_Wr[off], eh_Wi[off]);
        }
        for (int i = tid; i < 32 * 64; i += 256) {
            int k = i >> 6, cc = i & 63;
            size_t off = ((size_t)e * H + k0 + k) * H + col0 + cc;
            sB[k][cc] = make_float2(fu_Wr[off], fu_Wi[off]);
        }
        __syncthreads();
        for (int k = 0; k < 32; k++) {
            float2 b = sB[k][c];
            #pragma unroll
            for (int i = 0; i < 10; i++) {
                if (i < nrows) {
                    float2 a = sA[row0 + i][k];
                    wc1[i] = fmaf(a.x, b.x, wc1[i]);
                    wc1[i] = fmaf(-a.y, b.y, wc1[i]);
                    wc2[i] = fmaf(a.x, b.y, wc2[i]);
                    wc2[i] = fmaf(a.y, b.x, wc2[i]);
                }
            }
        }
        __syncthreads();
    }
    #pragma unroll
    for (int i = 0; i < 10; i++) {
        if (i < nrows) {
            g_pqp[z][e][row0 + i][col0 + c] = wc1[i];
            g_uvp[z][e][row0 + i][col0 + c] = wc2[i];
        }
    }
}

__global__ void wf_reduce_kernel()
{
    int gid = blockIdx.x * 256 + threadIdx.x;
    if (gid >= E * FDIM * 1024) return;
    int cg = gid & 1023;
    int rem = gid >> 10;
    int row = rem % FDIM;
    int e = rem / FDIM;
    float wc1 = 0.f, wc2 = 0.f;
    #pragma unroll
    for (int z = 0; z < 4; z++) {
        wc1 += g_pqp[z][e][row][cg];
        wc2 += g_uvp[z][e][row][cg];
    }
    size_t b1 = (size_t)(e * 76 + row) * 2048;
    size_t b2 = (size_t)(e * 76 + 38 + row) * 2048;
    g_WF[b1 + cg]        = wc1;
    g_WF[b1 + 1024 + cg] = wc2;
    g_WF[b2 + cg]        = -wc2;
    g_WF[b2 + 1024 + cg] = wc1;
}

// ----------------------------------------------------------------------------
// crci / cgate
// ----------------------------------------------------------------------------
__global__ void crci_part_kernel(const float* __restrict__ eh_br, const float* __restrict__ eh_bi,
                                 const float* __restrict__ fu_Wr, const float* __restrict__ fu_Wi)
{
    const int o = blockIdx.x * 128 + threadIdx.x;
    const int eh0 = blockIdx.y * 64;
    float cr = 0.f, ci = 0.f;
    #pragma unroll 4
    for (int k = 0; k < 64; k++) {
        int eh = eh0 + k;
        float br = eh_br[eh], bi = eh_bi[eh];
        float wr = fu_Wr[(size_t)eh * H + o], wi = fu_Wi[(size_t)eh * H + o];
        cr = fmaf(br, wr, cr); cr = fmaf(-bi, wi, cr);
        ci = fmaf(br, wi, ci); ci = fmaf(bi, wr, ci);
    }
    g_CBpart[blockIdx.y][o]        = cr;
    g_CBpart[blockIdx.y][1024 + o] = ci;
}

__global__ void crci_reduce_kernel(const float* __restrict__ fu_br, const float* __restrict__ fu_bi)
{
    int o = blockIdx.x * 256 + threadIdx.x;
    float acc = (o < 1024) ? fu_br[o] : fu_bi[o - 1024];
    #pragma unroll
    for (int j = 0; j < 64; j++) acc += g_CBpart[j][o];
    g_CB[o] = acc;
}

__global__ void cgate_part_kernel(const float* __restrict__ g_W)
{
    const int o = blockIdx.x * 128 + threadIdx.x;
    const int h0 = blockIdx.y * 128;
    float acc = 0.f;
    #pragma unroll 4
    for (int k = 0; k < 128; k++) {
        int h = h0 + k;
        acc = fmaf(g_CB[h],        g_W[(size_t)(H + h) * H + o],     acc);
        acc = fmaf(g_CB[1024 + h], g_W[(size_t)(2 * H + h) * H + o], acc);
    }
    g_cgpart[blockIdx.y][o] = acc;
}

__global__ void cgate_reduce_kernel(const float* __restrict__ g_b)
{
    int o = blockIdx.x * 256 + threadIdx.x;
    float acc = g_b[o];
    #pragma unroll
    for (int j = 0; j < 8; j++) acc += g_cgpart[j][o];
    g_cgate[o] = acc;
}

// ----------------------------------------------------------------------------
// gcg split-K
// ----------------------------------------------------------------------------
__global__ __launch_bounds__(256)
void gcg_part_kernel(const float* __restrict__ g_W)
{
    __shared__ float sA[40][32];
    __shared__ float sB[32][64];
    const int p0 = blockIdx.y * 38;
    const int z = blockIdx.z;
    const int col0 = blockIdx.x * 64;
    const int tid = threadIdx.x;
    const int c = tid & 63, rg = tid >> 6;
    const int row0 = rg * 10;
    const int nrows = (rg == 3) ? 8 : 10;

    float acc[10];
    #pragma unroll
    for (int i = 0; i < 10; i++) acc[i] = 0.f;

    for (int kc = 0; kc < 16; kc++) {
        int k0 = z * 512 + kc * 32;
        for (int i = tid; i < 38 * 32; i += 256) {
            int pp = i >> 5, k = i & 31;
            sA[pp][k] = g_WF[(size_t)(p0 + pp) * 2048 + k0 + k];
        }
        for (int i = tid; i < 32 * 64; i += 256) {
            int k = i >> 6, cc = i & 63;
            sB[k][cc] = g_W[(size_t)(H + k0 + k) * H + col0 + cc];
        }
        __syncthreads();
        for (int k = 0; k < 32; k++) {
            float b = sB[k][c];
            #pragma unroll
            for (int i = 0; i < 10; i++)
                if (i < nrows)
                    acc[i] = fmaf(sA[row0 + i][k], b, acc[i]);
        }
        __syncthreads();
    }
    #pragma unroll
    for (int i = 0; i < 10; i++)
        if (i < nrows)
            g_gcgp[z][p0 + row0 + i][col0 + c] = acc[i];
}

__global__ void gcg_reduce_kernel()
{
    int gid = blockIdx.x * 256 + threadIdx.x;
    if (gid >= GDIM * 1024) return;
    int col = gid & 1023;
    int p = gid >> 10;
    float acc = 0.f;
    #pragma unroll
    for (int z = 0; z < 4; z++) acc += g_gcgp[z][p][col];
    g_GcG[(size_t)p * 1024 + col] = acc;
}

// ----------------------------------------------------------------------------
// A-side packing
// ----------------------------------------------------------------------------
__global__ void pack_G_kernel()
{
    int gid = blockIdx.x * 256 + threadIdx.x;
    if (gid >= M_TOT * KPG) return;
    int m = gid / KPG, kp = gid % KPG;
    float v0 = 0.f, v1 = 0.f;
    if (kp < GDIM / 2) {
        v0 = g_G[(size_t)m * GDIM + 2 * kp];
        v1 = g_G[(size_t)m * GDIM + 2 * kp + 1];
    }
    split2h(v0, v1, g_Gh[gid], g_Gl[gid]);
}

__global__ void concat2_kernel(const float* __restrict__ x)
{
    const int row = blockIdx.x;
    const float* xr = x + (size_t)row * H;
    const float* gr = g_G + (size_t)row * GDIM;
    const float* fr = g_FRF + (size_t)row * 2048;
    uint32_t* dh = g_CCh + (size_t)row * KPC;

    for (int kp = threadIdx.x; kp < KPC; kp += 256) {
        float v0, v1;
        if (kp < 512) {
            v0 = xr[2 * kp]; v1 = xr[2 * kp + 1];
        } else if (kp < 664) {
            int cg = 2 * kp - 1024;
            v0 = gr[cg]; v1 = gr[cg + 1];
        } else if (kp < 1176) {
            int h = 2 * kp - 1328;
            float a0 = fr[h],     b0 = fr[1024 + h];
            float a1 = fr[h + 1], b1 = fr[1024 + h + 1];
            v0 = sqrtf(a0 * a0 + b0 * b0 + EPS);
            v1 = sqrtf(a1 * a1 + b1 * b1 + EPS);
        } else {
            v0 = 0.f; v1 = 0.f;
        }
        dh[kp] = pack2h(v0, v1);
    }
}

// ----------------------------------------------------------------------------
// Recurrence as chunked parallel scan
// ----------------------------------------------------------------------------
__global__ void recur_p1(const float* __restrict__ lam_r, const float* __restrict__ lam_i)
{
    const int bid = blockIdx.x;
    const int seq = bid >> 5, c = bid & 31;
    const int e = seq >> 2, b = seq & 3;
    const int lane = threadIdx.x;
    if (lane >= R) return;
    const float lr = 0.9f * lam_r[e * R + lane];
    const float li = 0.9f * lam_i[e * R + lane];
    const float* up = g_U + ((size_t)b * T + c * LCH) * 128 + e * 32 + lane;
    float hr = 0.f, hi = 0.f;
    #pragma unroll 4
    for (int s = 0; s < LCH; s++) {
        float ur = up[(size_t)s * 128];
        float ui = up[(size_t)s * 128 + 16];
        float nhr = fmaf(lr, hr, fmaf(-li, hi, ETA * ur));
        float nhi = fmaf(lr, hi, fmaf(li, hr, ETA * ui));
        hr = nhr; hi = nhi;
    }
    g_hloc[seq][c][lane] = make_float2(hr, hi);
}

__global__ void recur_combine(const float* __restrict__ lam_r, const float* __restrict__ lam_i)
{
    int tid = threadIdx.x;
    int seq = tid >> 4, lane = tid & 15;
    int e = seq >> 2;
    float lr = 0.9f * lam_r[e * R + lane];
    float li = 0.9f * lam_i[e * R + lane];
    float pr = 1.f, pi = 0.f;
    for (int k = 0; k < LCH; k++) {
        float nr = pr * lr - pi * li;
        pi = pr * li + pi * lr;
        pr = nr;
    }
    float cr = 0.f, ci = 0.f;
    for (int c = 0; c < NCH; c++) {
        g_hinit[seq][c][lane] = make_float2(cr, ci);
        float2 hl = g_hloc[seq][c][lane];
        float nr = pr * cr - pi * ci + hl.x;
        ci = pr * ci + pi * cr + hl.y;
        cr = nr;
    }
}

__global__ void recur_p2(const float* __restrict__ lam_r, const float* __restrict__ lam_i)
{
    const int bid = blockIdx.x;
    const int seq = bid >> 5, c = bid & 31;
    const int e = seq >> 2, b = seq & 3;
    const int lane = threadIdx.x;
    if (lane >= R) return;

    const float lr = 0.9f * lam_r[e * R + lane];
    const float li = 0.9f * lam_i[e * R + lane];
    const int t0 = c * LCH;
    const float* up = g_U + ((size_t)b * T + t0) * 128 + e * 32 + lane;
    float* gp = g_G + ((size_t)b * T + t0) * GDIM + e * 76;

    float2 h0 = g_hinit[seq][c][lane];
    float hr = h0.x, hi = h0.y, acc = 0.f;
    const unsigned mask = 0xFFFFu;

    float u_r = up[0];
    float u_i = up[16];

    for (int s = 0; s < LCH; s++) {
        int sn = (t0 + s + 1 < T) ? (s + 1) : s;
        float nu_r = up[(size_t)sn * 128];
        float nu_i = up[(size_t)sn * 128 + 16];

        float nhr = lr * hr - li * hi + ETA * u_r;
        float nhi = lr * hi + li * hr + ETA * u_i;
        float m2 = nhr * nhr + nhi * nhi;

        float sm = m2, mx = m2;
        #pragma unroll
        for (int off = 8; off >= 1; off >>= 1) {
            sm += __shfl_xor_sync(mask, sm, off, 16);
            mx = fmaxf(mx, __shfl_xor_sync(mask, mx, off, 16));
        }
        float m_mean = sm * (1.f / 16.f);
        acc = 0.99f * acc + 0.01f * m_mean;
        float inv = rsqrtf(m_mean + EPS);
        float hnr = nhr * inv, hni = nhi * inv;

        float sr = hnr, si = hni;
        #pragma unroll
        for (int off = 8; off >= 1; off >>= 1) {
            sr += __shfl_xor_sync(mask, sr, off, 16);
            si += __shfl_xor_sync(mask, si, off, 16);
        }
        float mr = sr * (1.f / 16.f);
        float mi = si * (1.f / 16.f);

        float* g_t = gp + (size_t)s * GDIM;
        g_t[6 + lane]           = hnr;
        g_t[6 + R + lane]       = hni;
        g_t[38 + 6 + lane]      = hni;
        g_t[38 + 6 + R + lane]  = -hnr;
        if (lane == 0) {
            g_t[0] = mr;
            g_t[1] = mi;
            g_t[2] = sqrtf(m_mean + EPS);
            g_t[3] = sqrtf(mx + EPS);
            g_t[38 + 0] = mi;
            g_t[38 + 1] = -mr;
            g_t[38 + 2] = 0.f; g_t[38 + 3] = 0.f; g_t[38 + 4] = 0.f; g_t[38 + 5] = 0.f;
            g_lacc[seq][t0 + s] = acc;
        }
        hr = nhr; hi = nhi;
        u_r = nu_r; u_i = nu_i;
    }
    if (lane == 0) g_accend[seq][c] = acc;
}

__global__ void acc_combine_kernel()
{
    int seq = threadIdx.x;
    if (seq >= 16) return;
    float p = 1.f;
    for (int k = 0; k < LCH; k++) p *= 0.99f;
    float A = 0.f;
    for (int c = 0; c < NCH; c++) {
        g_accinit[seq][c] = A;
        A = p * A + g_accend[seq][c];
    }
}

__global__ void acc_fix_kernel()
{
    int gid = blockIdx.x * 256 + threadIdx.x;
    if (gid >= 16 * T) return;
    int seq = gid >> 11;
    int t = gid & (T - 1);
    int c = t >> 6;
    int k = (t & (LCH - 1)) + 1;
    float acc = __powf(0.99f, (float)k) * g_accinit[seq][c] + g_lacc[seq][t];
    int e = seq >> 2, b = seq & 3;
    float* g_t = g_G + ((size_t)b * T + t) * GDIM + e * 76;
    g_t[4] = acc;
    g_t[5] = log1pf(acc);
}

// ----------------------------------------------------------------------------
// Launch
// ----------------------------------------------------------------------------
extern "C" void kernel_launch(void* const* d_in, const int* in_sizes, int n_in,
                              void* d_out, int out_size)
{
    const float* x      = (const float*)d_in[0];
    const float* sig_Wr = (const float*)d_in[1];
    const float* sig_Wi = (const float*)d_in[2];
    const float* sig_br = (const float*)d_in[3];
    const float* sig_bi = (const float*)d_in[4];
    const float* A_r    = (const float*)d_in[5];
    const float* A_i    = (const float*)d_in[6];
    const float* lam_r  = (const float*)d_in[7];
    const float* lam_i  = (const float*)d_in[8];
    const float* eh_Wr  = (const float*)d_in[9];
    const float* eh_Wi  = (const float*)d_in[10];
    const float* eh_br  = (const float*)d_in[11];
    const float* eh_bi  = (const float*)d_in[12];
    const float* fu_Wr  = (const float*)d_in[13];
    const float* fu_Wi  = (const float*)d_in[14];
    const float* fu_br  = (const float*)d_in[15];
    const float* fu_bi  = (const float*)d_in[16];
    const float* gW     = (const float*)d_in[17];
    const float* gb     = (const float*)d_in[18];
    float* out = (float*)d_out;

    float *Bc, *FRF, *CB, *cgate, *WF;
    uint32_t *Gh, *Gl, *WFh, *CCh, *W2h;
    cudaGetSymbolAddress((void**)&Bc,    g_Bc);
    cudaGetSymbolAddress((void**)&FRF,   g_FRF);
    cudaGetSymbolAddress((void**)&CB,    g_CB);
    cudaGetSymbolAddress((void**)&cgate, g_cgate);
    cudaGetSymbolAddress((void**)&WF,    g_WF);
    cudaGetSymbolAddress((void**)&Gh,    g_Gh);
    cudaGetSymbolAddress((void**)&Gl,    g_Gl);
    cudaGetSymbolAddress((void**)&WFh,   g_WFh);
    cudaGetSymbolAddress((void**)&CCh,   g_CCh);
    cudaGetSymbolAddress((void**)&W2h,   g_W2h);

    cudaFuncSetAttribute(gemm_f16<1, 0>, cudaFuncAttributeMaxDynamicSharedMemorySize, SMEMF);
    cudaFuncSetAttribute(gemm_f16<0, 1>, cudaFuncAttributeMaxDynamicSharedMemorySize, SMEMG);

    static cudaStream_t sP = nullptr;
    static cudaEvent_t evFork = nullptr, evJoin = nullptr;
    if (sP == nullptr) {
        cudaStreamCreateWithFlags(&sP, cudaStreamNonBlocking);
        cudaEventCreateWithFlags(&evFork, cudaEventDisableTiming);
        cudaEventCreateWithFlags(&evJoin, cudaEventDisableTiming);
    }

    cudaEventRecord(evFork, 0);
    cudaStreamWaitEvent(sP, evFork, 0);

    // --- precompute (weight composition) on side stream ---
    pquv_part_kernel<<<dim3(H / 64, E, 4), 256, 0, sP>>>(eh_Wr, eh_Wi, fu_Wr, fu_Wi);
    wf_reduce_kernel<<<(E * FDIM * 1024 + 255) / 256, 256, 0, sP>>>();
    crci_part_kernel<<<dim3(8, 64), 128, 0, sP>>>(eh_br, eh_bi, fu_Wr, fu_Wi);
    crci_reduce_kernel<<<8, 256, 0, sP>>>(fu_br, fu_bi);
    tpack_h_kernel<<<dim3(2048 / 32, KEG / 32), dim3(32, 8), 0, sP>>>(WF, GDIM, 2048, KPG, WFh);
    gcg_part_kernel<<<dim3(H / 64, 8, 4), 256, 0, sP>>>(gW);
    gcg_reduce_kernel<<<(GDIM * 1024 + 255) / 256, 256, 0, sP>>>();
    gate_wpack_kernel<<<dim3(1024 / 32, KEC / 32), dim3(32, 8), 0, sP>>>(gW);
    cgate_part_kernel<<<dim3(8, 8), 128, 0, sP>>>(gW);
    cgate_reduce_kernel<<<4, 256, 0, sP>>>(gb);
    cudaEventRecord(evJoin, sP);

    // --- main path on default stream ---
    combine_proj_kernel<<<dim3(64, E), 256>>>(sig_Wr, sig_Wi, A_r, A_i);
    ubias_kernel<<<1, 128>>>(sig_br, sig_bi, A_r, A_i);
    sgemm_splitk<<<dim3(1, M_TOT / 128, 4), 256>>>(x, H, Bc, M_TOT, 128);
    ureduce_kernel<<<(M_TOT * 128 + 255) / 256, 256>>>();
    recur_p1<<<16 * NCH, 32>>>(lam_r, lam_i);
    recur_combine<<<1, 256>>>(lam_r, lam_i);
    recur_p2<<<16 * NCH, 32>>>(lam_r, lam_i);
    acc_combine_kernel<<<1, 16>>>();
    acc_fix_kernel<<<(16 * T + 255) / 256, 256>>>();
    pack_G_kernel<<<(M_TOT * KPG + 255) / 256, 256>>>();

    cudaStreamWaitEvent(0, evJoin, 0);

    // FRF = G @ WF + CB  (fp16, A split 2-term, ldmatrix)
    gemm_f16<1, 0><<<dim3(2048 / 128, M_TOT / 128), 256, SMEMF>>>(
        Gh, Gl, WFh, FRF, M_TOT, 2048, KEG, CB, nullptr, 0, nullptr, 0);
    concat2_kernel<<<M_TOT, 256>>>(x);
    // gate GEMM (fp16 single, ldmatrix) + fused epilogue
    gemm_f16<0, 1><<<dim3(H / 128, M_TOT / 128), 256, SMEMG>>>(
        CCh, nullptr, W2h, out, M_TOT, H, KEC, cgate, FRF, 2048, x, H);
}

// round 17
// speedup vs baseline: 15.8523x; 1.0629x over previous
#include <cuda_runtime.h>
#include <cuda_fp16.h>
#include <math.h>
#include <stdint.h>

#define BSZ 4
#define T 2048
#define H 1024
#define S 512
#define R 16
#define E 4
#define FDIM 38             // 6 + 2*R
#define M_TOT (BSZ*T)       // 8192
#define GDIM (E*2*FDIM)     // 304
#define CCW (H + GDIM + H)  // 2352
#define KEG 320             // padded K for FRF GEMM
#define KEC 2368            // padded K for gate GEMM
#define KPG (KEG/2)
#define KPC (KEC/2)
#define NCH 32
#define LCH 64
#define ETA 0.1f
#define EPS 1e-6f

// ----------------------------------------------------------------------------
// Scratch
// ----------------------------------------------------------------------------
__device__ float g_Bc[H * 128];
__device__ float g_ubias[128];
__device__ float g_U[M_TOT * 128];
__device__ float g_G[(size_t)M_TOT * GDIM];
__device__ float g_WF[(size_t)GDIM * 2048];
__device__ float g_CB[2048];
__device__ float g_CBpart[64][2048];
__device__ float g_cgpart[8][1024];
__device__ float g_FRF[(size_t)M_TOT * 2048];
__device__ float g_cgate[H];
// pquv / gcg split-K partials
__device__ float g_pqp[4][E][FDIM][1024];
__device__ float g_uvp[4][E][FDIM][1024];
__device__ float g_gcgp[4][GDIM][1024];
__device__ float g_GcG[(size_t)GDIM * 1024];
// U GEMM operands: x split fp16, Bc split fp16 (transposed [128][512])
__device__ uint32_t g_Xh[(size_t)M_TOT * 512];
__device__ uint32_t g_Xl[(size_t)M_TOT * 512];
__device__ uint32_t g_Bch[128 * 512];
__device__ uint32_t g_Bcl[128 * 512];
// FRF operands: A split fp16 (Gh+Gl), B single fp16 (WFh)
__device__ uint32_t g_Gh[(size_t)M_TOT * KPG];
__device__ uint32_t g_Gl[(size_t)M_TOT * KPG];
__device__ uint32_t g_WFh[(size_t)2048 * KPG];
// gate operands: fp16 single
__device__ uint32_t g_CCh[(size_t)M_TOT * KPC];
__device__ uint32_t g_W2h[(size_t)1024 * KPC];
// recurrence scan state
__device__ float2 g_hloc[16][NCH][16];
__device__ float2 g_hinit[16][NCH][16];
__device__ float g_lacc[16][T];
__device__ float g_accend[16][NCH];
__device__ float g_accinit[16][NCH];

// ----------------------------------------------------------------------------
// helpers
// ----------------------------------------------------------------------------
__device__ __forceinline__ void split2h(float v0, float v1, uint32_t& ph, uint32_t& pl)
{
    __half2 h2 = __floats2half2_rn(v0, v1);
    float r0 = v0 - __half2float(__low2half(h2));
    float r1 = v1 - __half2float(__high2half(h2));
    __half2 l2 = __floats2half2_rn(r0, r1);
    ph = *reinterpret_cast<uint32_t*>(&h2);
    pl = *reinterpret_cast<uint32_t*>(&l2);
}

__device__ __forceinline__ uint32_t pack2h(float v0, float v1)
{
    __half2 h2 = __floats2half2_rn(v0, v1);
    return *reinterpret_cast<uint32_t*>(&h2);
}

__device__ __forceinline__ uint32_t smem_u32_of(const void* p)
{
    uint32_t a;
    asm("{ .reg .u64 t; cvta.to.shared.u64 t, %1; cvt.u32.u64 %0, t; }" : "=r"(a) : "l"(p));
    return a;
}

__device__ __forceinline__ void mma_f16(float* d, const uint32_t* a, const uint32_t* b)
{
    asm volatile(
        "mma.sync.aligned.m16n8k16.row.col.f32.f16.f16.f32 "
        "{%0,%1,%2,%3}, {%4,%5,%6,%7}, {%8,%9}, {%0,%1,%2,%3};"
        : "+f"(d[0]), "+f"(d[1]), "+f"(d[2]), "+f"(d[3])
        : "r"(a[0]), "r"(a[1]), "r"(a[2]), "r"(a[3]), "r"(b[0]), "r"(b[1]));
}

#define LDSM4(r0, r1, r2, r3, addr) \
    asm volatile("ldmatrix.sync.aligned.m8n8.x4.shared.b16 {%0,%1,%2,%3}, [%4];" \
        : "=r"(r0), "=r"(r1), "=r"(r2), "=r"(r3) : "r"(addr))

// pipelined-GEMM smem geometry
#define NSTG 3
#define ROWU 12                      // u32 per smem row: 8 data + 4 pad (48B)
#define TILE_U (128 * ROWU)          // 1536 u32 = 6 KB

// ----------------------------------------------------------------------------
// fp16 pipelined GEMM (ldmatrix fragments):
//   ASPLIT: A = Ah (+Al), BSPLIT: B = Bh (+Bl). Terms: ah*bh [+ al*bh] [+ ah*bl].
//   EPI=1: g = sigmoid(v); C = g*e1 + (1-g)*e2; else C = v.
// C[M,N] = A[M,KE] @ Bt[N,KE]^T + bias.  grid (N/128, M/128), 256 thr.
// ----------------------------------------------------------------------------
template<int ASPLIT, int BSPLIT, int EPI>
__global__ __launch_bounds__(256)
void gemm_f16(const uint32_t* __restrict__ Ah, const uint32_t* __restrict__ Al,
              const uint32_t* __restrict__ Bh, const uint32_t* __restrict__ Bl,
              float* __restrict__ C, int M, int N, int KE,
              const float* __restrict__ bias,
              const float* __restrict__ e1, int ld1,
              const float* __restrict__ e2, int ld2)
{
    extern __shared__ uint32_t sm[];
    const uint32_t smem_base = smem_u32_of(sm);
    const int tid = threadIdx.x;
    const int wid = tid >> 5, lane = tid & 31;
    const int wm = wid & 1, wn = wid >> 1;
    const int grp = lane >> 2, tig = lane & 3;
    const int bx = blockIdx.x, by = blockIdx.y;
    const int KP = KE >> 1;
    const int NC = KE >> 4;

    const int NT = 2 + ASPLIT + BSPLIT;
    const int STGU = NT * TILE_U;
    const uint32_t TBOFF = (1 + ASPLIT) * TILE_U * 4;

    const int crow = tid >> 1, c16 = tid & 1;
    const uint32_t* gsrc0 = Ah + (size_t)(by * 128 + crow) * KP + c16 * 4;
    const uint32_t* gsrc1 = ASPLIT ? (Al + (size_t)(by * 128 + crow) * KP + c16 * 4) : nullptr;
    const uint32_t* gsrc2 = Bh + (size_t)(bx * 128 + crow) * KP + c16 * 4;
    const uint32_t* gsrc3 = BSPLIT ? (Bl + (size_t)(bx * 128 + crow) * KP + c16 * 4) : nullptr;
    const uint32_t dst0 = smem_base + (crow * ROWU + c16 * 4) * 4;

    const uint32_t aoff = ((lane & 15) * ROWU + (lane >> 4) * 4) * 4;
    const uint32_t boff = (((lane & 7) + ((lane >> 4) << 3)) * ROWU + (((lane >> 3) & 1) << 2)) * 4;

    float acc[4][4][4];
    #pragma unroll
    for (int i = 0; i < 4; i++)
        #pragma unroll
        for (int j = 0; j < 4; j++)
            #pragma unroll
            for (int q = 0; q < 4; q++) acc[i][j][q] = 0.f;

#define ISSUE(chunk) do { \
        uint32_t db_ = dst0 + ((chunk) % NSTG) * (STGU * 4); \
        asm volatile("cp.async.cg.shared.global [%0], [%1], 16;" :: "r"(db_), "l"(gsrc0 + (chunk) * 8)); \
        if (ASPLIT) \
            asm volatile("cp.async.cg.shared.global [%0], [%1], 16;" :: "r"(db_ + TILE_U * 4), "l"(gsrc1 + (chunk) * 8)); \
        asm volatile("cp.async.cg.shared.global [%0], [%1], 16;" :: "r"(db_ + TBOFF), "l"(gsrc2 + (chunk) * 8)); \
        if (BSPLIT) \
            asm volatile("cp.async.cg.shared.global [%0], [%1], 16;" :: "r"(db_ + TBOFF + TILE_U * 4), "l"(gsrc3 + (chunk) * 8)); \
        asm volatile("cp.async.commit_group;"); \
    } while (0)

    ISSUE(0);
    ISSUE(1);

    for (int i = 0; i < NC; i++) {
        if (i + 1 < NC) asm volatile("cp.async.wait_group 1;");
        else            asm volatile("cp.async.wait_group 0;");
        __syncthreads();
        if (i + 2 < NC) ISSUE(i + 2);

        const uint32_t stb = smem_base + (i % NSTG) * (STGU * 4);

        uint32_t bfr[4][2];
        uint32_t blo[4][2];
        {
            uint32_t b0 = stb + TBOFF + (uint32_t)(wn * 32) * ROWU * 4 + boff;
            LDSM4(bfr[0][0], bfr[0][1], bfr[1][0], bfr[1][1], b0);
            LDSM4(bfr[2][0], bfr[2][1], bfr[3][0], bfr[3][1], b0 + 16 * ROWU * 4);
            if (BSPLIT) {
                uint32_t bL = b0 + TILE_U * 4;
                LDSM4(blo[0][0], blo[0][1], blo[1][0], blo[1][1], bL);
                LDSM4(blo[2][0], blo[2][1], blo[3][0], blo[3][1], bL + 16 * ROWU * 4);
            }
        }
        #pragma unroll
        for (int ii = 0; ii < 4; ii++) {
            uint32_t aB = stb + (uint32_t)(wm * 64 + ii * 16) * ROWU * 4 + aoff;
            uint32_t ah[4];
            LDSM4(ah[0], ah[1], ah[2], ah[3], aB);
            uint32_t al[4];
            if (ASPLIT) LDSM4(al[0], al[1], al[2], al[3], aB + TILE_U * 4);
            #pragma unroll
            for (int j = 0; j < 4; j++) {
                mma_f16(acc[ii][j], ah, bfr[j]);
                if (ASPLIT) mma_f16(acc[ii][j], al, bfr[j]);
                if (BSPLIT) mma_f16(acc[ii][j], ah, blo[j]);
            }
        }
    }
#undef ISSUE

    #pragma unroll
    for (int i = 0; i < 4; i++) {
        #pragma unroll
        for (int j = 0; j < 4; j++) {
            int row0 = by * 128 + wm * 64 + i * 16 + grp;
            int col0 = bx * 128 + wn * 32 + j * 8 + tig * 2;
            #pragma unroll
            for (int q = 0; q < 4; q++) {
                int row = row0 + (q >> 1) * 8;
                int col = col0 + (q & 1);
                float v = acc[i][j][q] + bias[col];
                if (EPI == 0) {
                    C[(size_t)row * N + col] = v;
                } else {
                    float g = 1.f / (1.f + expf(-v));
                    C[(size_t)row * N + col] =
                        g * e1[(size_t)row * ld1 + col] + (1.f - g) * e2[(size_t)row * ld2 + col];
                }
            }
        }
    }
}

#define SMEMU (NSTG * 4 * TILE_U * 4)   // 73728 (U: Ah+Al+Bh+Bl)
#define SMEMF (NSTG * 3 * TILE_U * 4)   // 55296 (FRF: Ah+Al+B)
#define SMEMG (NSTG * 2 * TILE_U * 4)   // 36864 (gate: A+B)

// ----------------------------------------------------------------------------
// pack x: fp32 [M][1024] -> Xh/Xl [M][512] u32 pairs, and gate CC x-section.
// ----------------------------------------------------------------------------
__global__ void pack_x_kernel(const float* __restrict__ x)
{
    int gid = blockIdx.x * 256 + threadIdx.x;
    if (gid >= M_TOT * 512) return;
    int m = gid >> 9, kp = gid & 511;
    float v0 = x[(size_t)m * H + 2 * kp];
    float v1 = x[(size_t)m * H + 2 * kp + 1];
    uint32_t h, l;
    split2h(v0, v1, h, l);
    g_Xh[gid] = h;
    g_Xl[gid] = l;
    g_CCh[(size_t)m * KPC + kp] = h;
}

// pack Bc: fp32 [1024][128] -> Bch/Bcl [128][512] (transposed), split fp16.
__global__ void pack_Bc_kernel()
{
    __shared__ float tile[32][33];
    const int n0 = blockIdx.x * 32;   // 4 blocks
    const int k0 = blockIdx.y * 32;   // 32 blocks
    const int tx = threadIdx.x, ty = threadIdx.y;
    #pragma unroll
    for (int j = 0; j < 32; j += 8)
        tile[ty + j][tx] = g_Bc[(size_t)(k0 + ty + j) * 128 + n0 + tx];
    __syncthreads();
    int t = ty * 32 + tx;
    #pragma unroll
    for (int s = 0; s < 2; s++) {
        int idx = t + s * 256;
        int n = idx >> 4;
        int kp = idx & 15;
        uint32_t h, l;
        split2h(tile[2 * kp][n], tile[2 * kp + 1][n], h, l);
        size_t o = (size_t)(n0 + n) * 512 + (k0 >> 1) + kp;
        g_Bch[o] = h;
        g_Bcl[o] = l;
    }
}

// ----------------------------------------------------------------------------
// transpose-pack fp16 single: src fp32 [K][N] -> dh [N][KP2]
// ----------------------------------------------------------------------------
__global__ void tpack_h_kernel(const float* __restrict__ src, int K, int N, int KP2,
                               uint32_t* __restrict__ dh)
{
    __shared__ float tile[32][33];
    const int n0 = blockIdx.x * 32;
    const int k0 = blockIdx.y * 32;
    const int tx = threadIdx.x, ty = threadIdx.y;
    #pragma unroll
    for (int j = 0; j < 32; j += 8) {
        int k = k0 + ty + j;
        tile[ty + j][tx] = (k < K) ? src[(size_t)k * N + n0 + tx] : 0.f;
    }
    __syncthreads();
    int t = ty * 32 + tx;
    #pragma unroll
    for (int s = 0; s < 2; s++) {
        int idx = t + s * 256;
        int n = idx >> 4;
        int kp = idx & 15;
        dh[(size_t)(n0 + n) * KP2 + (k0 >> 1) + kp] =
            pack2h(tile[2 * kp][n], tile[2 * kp + 1][n]);
    }
}

// ----------------------------------------------------------------------------
// gate weight pack (fp16 single), sourced from gW rows + GcG
// ----------------------------------------------------------------------------
__global__ void gate_wpack_kernel(const float* __restrict__ g_W)
{
    __shared__ float tile[32][33];
    const int n0 = blockIdx.x * 32;
    const int k0 = blockIdx.y * 32;
    const int tx = threadIdx.x, ty = threadIdx.y;
    #pragma unroll
    for (int j = 0; j < 32; j += 8) {
        int k = k0 + ty + j;
        float v;
        if (k < 1024)       v = g_W[(size_t)k * H + n0 + tx];
        else if (k < 1328)  v = g_GcG[(size_t)(k - 1024) * 1024 + n0 + tx];
        else if (k < 2352)  v = g_W[(size_t)(3 * 1024 + (k - 1328)) * H + n0 + tx];
        else                v = 0.f;
        tile[ty + j][tx] = v;
    }
    __syncthreads();
    int t = ty * 32 + tx;
    #pragma unroll
    for (int s = 0; s < 2; s++) {
        int idx = t + s * 256;
        int n = idx >> 4;
        int kp = idx & 15;
        g_W2h[(size_t)(n0 + n) * KPC + (k0 >> 1) + kp] =
            pack2h(tile[2 * kp][n], tile[2 * kp + 1][n]);
    }
}

// ----------------------------------------------------------------------------
// Precompute Bc + ubias
// ----------------------------------------------------------------------------
__global__ __launch_bounds__(256)
void combine_proj_kernel(const float* __restrict__ sig_Wr, const float* __restrict__ sig_Wi,
                         const float* __restrict__ A_r, const float* __restrict__ A_i)
{
    __shared__ float sAr[128][16], sAi[128][16];
    __shared__ float sWr[16][128], sWi[16][128];
    const int e = blockIdx.y;
    const int h0 = blockIdx.x * 16;
    const int tid = threadIdx.x;
    const int h_loc = tid >> 4, r = tid & 15;
    float aur = 0.f, aui = 0.f;

    for (int s0 = 0; s0 < S; s0 += 128) {
        for (int i = tid; i < 128 * 16; i += 256) {
            int s = i >> 4, rr = i & 15;
            sAr[s][rr] = A_r[((size_t)e * S + s0 + s) * R + rr];
            sAi[s][rr] = A_i[((size_t)e * S + s0 + s) * R + rr];
        }
        for (int i = tid; i < 16 * 128; i += 256) {
            int hh = i >> 7, ss = i & 127;
            sWr[hh][ss] = sig_Wr[(size_t)(h0 + hh) * S + s0 + ss];
            sWi[hh][ss] = sig_Wi[(size_t)(h0 + hh) * S + s0 + ss];
        }
        __syncthreads();
        #pragma unroll 4
        for (int s = 0; s < 128; s++) {
            float wr = sWr[h_loc][s], wi = sWi[h_loc][s];
            float ar = sAr[s][r],     ai = sAi[s][r];
            aur = fmaf(wr, ar, aur);
            aur = fmaf(-wi, ai, aur);
            aui = fmaf(wr, ai, aui);
            aui = fmaf(wi, ar, aui);
        }
        __syncthreads();
    }
    g_Bc[(size_t)(h0 + h_loc) * 128 + e * 32 + r]      = aur;
    g_Bc[(size_t)(h0 + h_loc) * 128 + e * 32 + 16 + r] = aui;
}

__global__ void ubias_kernel(const float* __restrict__ sig_br, const float* __restrict__ sig_bi,
                             const float* __restrict__ A_r, const float* __restrict__ A_i)
{
    int j = threadIdx.x;
    int e = j >> 5, half = (j >> 4) & 1, r = j & 15;
    float acc = 0.f;
    for (int s = 0; s < S; s++) {
        float ar = A_r[((size_t)e * S + s) * R + r];
        float ai = A_i[((size_t)e * S + s) * R + r];
        float br = sig_br[s], bi = sig_bi[s];
        acc += half ? (br * ai + bi * ar) : (br * ar - bi * ai);
    }
    g_ubias[j] = acc;
}

// ----------------------------------------------------------------------------
// pquv split-K
// ----------------------------------------------------------------------------
__global__ __launch_bounds__(256)
void pquv_part_kernel(const float* __restrict__ eh_Wr, const float* __restrict__ eh_Wi,
                      const float* __restrict__ fu_Wr, const float* __restrict__ fu_Wi)
{
    __shared__ float2 sA[40][32];
    __shared__ float2 sB[32][64];
    const int e = blockIdx.y;
    const int z = blockIdx.z;
    const int col0 = blockIdx.x * 64;
    const int tid = threadIdx.x;
    const int c = tid & 63, rg = tid >> 6;
    const int row0 = rg * 10;
    const int nrows = (rg == 3) ? 8 : 10;

    float wc1[10], wc2[10];
    #pragma unroll
    for (int i = 0; i < 10; i++) { wc1[i] = 0.f; wc2[i] = 0.f; }

    for (int kc = 0; kc < 8; kc++) {
        int k0 = z * 256 + kc * 32;
        for (int i = tid; i < FDIM * 32; i += 256) {
            int f = i >> 5, k = i & 31;
            size_t off = ((size_t)e * FDIM + f) * H + k0 + k;
            sA[f][k] = make_float2(eh_Wr[off], eh_Wi[off]);
        }
        for (int i = tid; i < 32 * 64; i += 256) {
            int k = i >> 6, cc = i & 63;
            size_t off = ((size_t)e * H + k0 + k) * H + col0 + cc;
            sB[k][cc] = make_float2(fu_Wr[off], fu_Wi[off]);
        }
        __syncthreads();
        for (int k = 0; k < 32; k++) {
            float2 b = sB[k][c];
            #pragma unroll
            for (int i = 0; i < 10; i++) {
                if (i < nrows) {
                    float2 a = sA[row0 + i][k];
                    wc1[i] = fmaf(a.x, b.x, wc1[i]);
                    wc1[i] = fmaf(-a.y, b.y, wc1[i]);
                    wc2[i] = fmaf(a.x, b.y, wc2[i]);
                    wc2[i] = fmaf(a.y, b.x, wc2[i]);
                }
            }
        }
        __syncthreads();
    }
    #pragma unroll
    for (int i = 0; i < 10; i++) {
        if (i < nrows) {
            g_pqp[z][e][row0 + i][col0 + c] = wc1[i];
            g_uvp[z][e][row0 + i][col0 + c] = wc2[i];
        }
    }
}

__global__ void wf_reduce_kernel()
{
    int gid = blockIdx.x * 256 + threadIdx.x;
    if (gid >= E * FDIM * 1024) return;
    int cg = gid & 1023;
    int rem = gid >> 10;
    int row = rem % FDIM;
    int e = rem / FDIM;
    float wc1 = 0.f, wc2 = 0.f;
    #pragma unroll
    for (int z = 0; z < 4; z++) {
        wc1 += g_pqp[z][e][row][cg];
        wc2 += g_uvp[z][e][row][cg];
    }
    size_t b1 = (size_t)(e * 76 + row) * 2048;
    size_t b2 = (size_t)(e * 76 + 38 + row) * 2048;
    g_WF[b1 + cg]        = wc1;
    g_WF[b1 + 1024 + cg] = wc2;
    g_WF[b2 + cg]        = -wc2;
    g_WF[b2 + 1024 + cg] = wc1;
}

// ----------------------------------------------------------------------------
// crci / cgate
// ----------------------------------------------------------------------------
__global__ void crci_part_kernel(const float* __restrict__ eh_br, const float* __restrict__ eh_bi,
                                 const float* __restrict__ fu_Wr, const float* __restrict__ fu_Wi)
{
    const int o = blockIdx.x * 128 + threadIdx.x;
    const int eh0 = blockIdx.y * 64;
    float cr = 0.f, ci = 0.f;
    #pragma unroll 4
    for (int k = 0; k < 64; k++) {
        int eh = eh0 + k;
        float br = eh_br[eh], bi = eh_bi[eh];
        float wr = fu_Wr[(size_t)eh * H + o], wi = fu_Wi[(size_t)eh * H + o];
        cr = fmaf(br, wr, cr); cr = fmaf(-bi, wi, cr);
        ci = fmaf(br, wi, ci); ci = fmaf(bi, wr, ci);
    }
    g_CBpart[blockIdx.y][o]        = cr;
    g_CBpart[blockIdx.y][1024 + o] = ci;
}

__global__ void crci_reduce_kernel(const float* __restrict__ fu_br, const float* __restrict__ fu_bi)
{
    int o = blockIdx.x * 256 + threadIdx.x;
    float acc = (o < 1024) ? fu_br[o] : fu_bi[o - 1024];
    #pragma unroll
    for (int j = 0; j < 64; j++) acc += g_CBpart[j][o];
    g_CB[o] = acc;
}

__global__ void cgate_part_kernel(const float* __restrict__ g_W)
{
    const int o = blockIdx.x * 128 + threadIdx.x;
    const int h0 = blockIdx.y * 128;
    float acc = 0.f;
    #pragma unroll 4
    for (int k = 0; k < 128; k++) {
        int h = h0 + k;
        acc = fmaf(g_CB[h],        g_W[(size_t)(H + h) * H + o],     acc);
        acc = fmaf(g_CB[1024 + h], g_W[(size_t)(2 * H + h) * H + o], acc);
    }
    g_cgpart[blockIdx.y][o] = acc;
}

__global__ void cgate_reduce_kernel(const float* __restrict__ g_b)
{
    int o = blockIdx.x * 256 + threadIdx.x;
    float acc = g_b[o];
    #pragma unroll
    for (int j = 0; j < 8; j++) acc += g_cgpart[j][o];
    g_cgate[o] = acc;
}

// ----------------------------------------------------------------------------
// gcg split-K
// ----------------------------------------------------------------------------
__global__ __launch_bounds__(256)
void gcg_part_kernel(const float* __restrict__ g_W)
{
    __shared__ float sA[40][32];
    __shared__ float sB[32][64];
    const int p0 = blockIdx.y * 38;
    const int z = blockIdx.z;
    const int col0 = blockIdx.x * 64;
    const int tid = threadIdx.x;
    const int c = tid & 63, rg = tid >> 6;
    const int row0 = rg * 10;
    const int nrows = (rg == 3) ? 8 : 10;

    float acc[10];
    #pragma unroll
    for (int i = 0; i < 10; i++) acc[i] = 0.f;

    for (int kc = 0; kc < 16; kc++) {
        int k0 = z * 512 + kc * 32;
        for (int i = tid; i < 38 * 32; i += 256) {
            int pp = i >> 5, k = i & 31;
            sA[pp][k] = g_WF[(size_t)(p0 + pp) * 2048 + k0 + k];
        }
        for (int i = tid; i < 32 * 64; i += 256) {
            int k = i >> 6, cc = i & 63;
            sB[k][cc] = g_W[(size_t)(H + k0 + k) * H + col0 + cc];
        }
        __syncthreads();
        for (int k = 0; k < 32; k++) {
            float b = sB[k][c];
            #pragma unroll
            for (int i = 0; i < 10; i++)
                if (i < nrows)
                    acc[i] = fmaf(sA[row0 + i][k], b, acc[i]);
        }
        __syncthreads();
    }
    #pragma unroll
    for (int i = 0; i < 10; i++)
        if (i < nrows)
            g_gcgp[z][p0 + row0 + i][col0 + c] = acc[i];
}

__global__ void gcg_reduce_kernel()
{
    int gid = blockIdx.x * 256 + threadIdx.x;
    if (gid >= GDIM * 1024) return;
    int col = gid & 1023;
    int p = gid >> 10;
    float acc = 0.f;
    #pragma unroll
    for (int z = 0; z < 4; z++) acc += g_gcgp[z][p][col];
    g_GcG[(size_t)p * 1024 + col] = acc;
}

// ----------------------------------------------------------------------------
// A-side packing: G (FRF operand + gate CC G-section)
// ----------------------------------------------------------------------------
__global__ void pack_G_kernel()
{
    int gid = blockIdx.x * 256 + threadIdx.x;
    if (gid >= M_TOT * KPG) return;
    int m = gid / KPG, kp = gid % KPG;
    float v0 = 0.f, v1 = 0.f;
    if (kp < GDIM / 2) {
        v0 = g_G[(size_t)m * GDIM + 2 * kp];
        v1 = g_G[(size_t)m * GDIM + 2 * kp + 1];
    }
    uint32_t h, l;
    split2h(v0, v1, h, l);
    g_Gh[gid] = h;
    g_Gl[gid] = l;
    if (kp < GDIM / 2)
        g_CCh[(size_t)m * KPC + 512 + kp] = h;
}

// mag section of gate CC (post-FRF): kp in [664, 1184)
__global__ void concat_mag_kernel()
{
    const int row = blockIdx.x;
    const float* fr = g_FRF + (size_t)row * 2048;
    uint32_t* dh = g_CCh + (size_t)row * KPC;
    for (int kp = 664 + threadIdx.x; kp < KPC; kp += 256) {
        float v0 = 0.f, v1 = 0.f;
        if (kp < 1176) {
            int h = 2 * kp - 1328;
            float a0 = fr[h],     b0 = fr[1024 + h];
            float a1 = fr[h + 1], b1 = fr[1024 + h + 1];
            v0 = sqrtf(a0 * a0 + b0 * b0 + EPS);
            v1 = sqrtf(a1 * a1 + b1 * b1 + EPS);
        }
        dh[kp] = pack2h(v0, v1);
    }
}

// ----------------------------------------------------------------------------
// Recurrence as chunked parallel scan
// ----------------------------------------------------------------------------
__global__ void recur_p1(const float* __restrict__ lam_r, const float* __restrict__ lam_i)
{
    const int bid = blockIdx.x;
    const int seq = bid >> 5, c = bid & 31;
    const int e = seq >> 2, b = seq & 3;
    const int lane = threadIdx.x;
    if (lane >= R) return;
    const float lr = 0.9f * lam_r[e * R + lane];
    const float li = 0.9f * lam_i[e * R + lane];
    const float* up = g_U + ((size_t)b * T + c * LCH) * 128 + e * 32 + lane;
    float hr = 0.f, hi = 0.f;
    #pragma unroll 4
    for (int s = 0; s < LCH; s++) {
        float ur = up[(size_t)s * 128];
        float ui = up[(size_t)s * 128 + 16];
        float nhr = fmaf(lr, hr, fmaf(-li, hi, ETA * ur));
        float nhi = fmaf(lr, hi, fmaf(li, hr, ETA * ui));
        hr = nhr; hi = nhi;
    }
    g_hloc[seq][c][lane] = make_float2(hr, hi);
}

__global__ void recur_combine(const float* __restrict__ lam_r, const float* __restrict__ lam_i)
{
    int tid = threadIdx.x;
    int seq = tid >> 4, lane = tid & 15;
    int e = seq >> 2;
    float lr = 0.9f * lam_r[e * R + lane];
    float li = 0.9f * lam_i[e * R + lane];
    float pr = 1.f, pi = 0.f;
    for (int k = 0; k < LCH; k++) {
        float nr = pr * lr - pi * li;
        pi = pr * li + pi * lr;
        pr = nr;
    }
    float cr = 0.f, ci = 0.f;
    for (int c = 0; c < NCH; c++) {
        g_hinit[seq][c][lane] = make_float2(cr, ci);
        float2 hl = g_hloc[seq][c][lane];
        float nr = pr * cr - pi * ci + hl.x;
        ci = pr * ci + pi * cr + hl.y;
        cr = nr;
    }
}

__global__ void recur_p2(const float* __restrict__ lam_r, const float* __restrict__ lam_i)
{
    const int bid = blockIdx.x;
    const int seq = bid >> 5, c = bid & 31;
    const int e = seq >> 2, b = seq & 3;
    const int lane = threadIdx.x;
    if (lane >= R) return;

    const float lr = 0.9f * lam_r[e * R + lane];
    const float li = 0.9f * lam_i[e * R + lane];
    const int t0 = c * LCH;
    const float* up = g_U + ((size_t)b * T + t0) * 128 + e * 32 + lane;
    float* gp = g_G + ((size_t)b * T + t0) * GDIM + e * 76;

    float2 h0 = g_hinit[seq][c][lane];
    float hr = h0.x, hi = h0.y, acc = 0.f;
    const unsigned mask = 0xFFFFu;

    float u_r = up[0];
    float u_i = up[16];

    for (int s = 0; s < LCH; s++) {
        int sn = (t0 + s + 1 < T) ? (s + 1) : s;
        float nu_r = up[(size_t)sn * 128];
        float nu_i = up[(size_t)sn * 128 + 16];

        float nhr = lr * hr - li * hi + ETA * u_r;
        float nhi = lr * hi + li * hr + ETA * u_i;
        float m2 = nhr * nhr + nhi * nhi;

        float sm = m2, mx = m2;
        #pragma unroll
        for (int off = 8; off >= 1; off >>= 1) {
            sm += __shfl_xor_sync(mask, sm, off, 16);
            mx = fmaxf(mx, __shfl_xor_sync(mask, mx, off, 16));
        }
        float m_mean = sm * (1.f / 16.f);
        acc = 0.99f * acc + 0.01f * m_mean;
        float inv = rsqrtf(m_mean + EPS);
        float hnr = nhr * inv, hni = nhi * inv;

        float sr = hnr, si = hni;
        #pragma unroll
        for (int off = 8; off >= 1; off >>= 1) {
            sr += __shfl_xor_sync(mask, sr, off, 16);
            si += __shfl_xor_sync(mask, si, off, 16);
        }
        float mr = sr * (1.f / 16.f);
        float mi = si * (1.f / 16.f);

        float* g_t = gp + (size_t)s * GDIM;
        g_t[6 + lane]           = hnr;
        g_t[6 + R + lane]       = hni;
        g_t[38 + 6 + lane]      = hni;
        g_t[38 + 6 + R + lane]  = -hnr;
        if (lane == 0) {
            g_t[0] = mr;
            g_t[1] = mi;
            g_t[2] = sqrtf(m_mean + EPS);
            g_t[3] = sqrtf(mx + EPS);
            g_t[38 + 0] = mi;
            g_t[38 + 1] = -mr;
            g_t[38 + 2] = 0.f; g_t[38 + 3] = 0.f; g_t[38 + 4] = 0.f; g_t[38 + 5] = 0.f;
            g_lacc[seq][t0 + s] = acc;
        }
        hr = nhr; hi = nhi;
        u_r = nu_r; u_i = nu_i;
    }
    if (lane == 0) g_accend[seq][c] = acc;
}

__global__ void acc_combine_kernel()
{
    int seq = threadIdx.x;
    if (seq >= 16) return;
    float p = 1.f;
    for (int k = 0; k < LCH; k++) p *= 0.99f;
    float A = 0.f;
    for (int c = 0; c < NCH; c++) {
        g_accinit[seq][c] = A;
        A = p * A + g_accend[seq][c];
    }
}

__global__ void acc_fix_kernel()
{
    int gid = blockIdx.x * 256 + threadIdx.x;
    if (gid >= 16 * T) return;
    int seq = gid >> 11;
    int t = gid & (T - 1);
    int c = t >> 6;
    int k = (t & (LCH - 1)) + 1;
    float acc = __powf(0.99f, (float)k) * g_accinit[seq][c] + g_lacc[seq][t];
    int e = seq >> 2, b = seq & 3;
    float* g_t = g_G + ((size_t)b * T + t) * GDIM + e * 76;
    g_t[4] = acc;
    g_t[5] = log1pf(acc);
}

// ----------------------------------------------------------------------------
// Launch
// ----------------------------------------------------------------------------
extern "C" void kernel_launch(void* const* d_in, const int* in_sizes, int n_in,
                              void* d_out, int out_size)
{
    const float* x      = (const float*)d_in[0];
    const float* sig_Wr = (const float*)d_in[1];
    const float* sig_Wi = (const float*)d_in[2];
    const float* sig_br = (const float*)d_in[3];
    const float* sig_bi = (const float*)d_in[4];
    const float* A_r    = (const float*)d_in[5];
    const float* A_i    = (const float*)d_in[6];
    const float* lam_r  = (const float*)d_in[7];
    const float* lam_i  = (const float*)d_in[8];
    const float* eh_Wr  = (const float*)d_in[9];
    const float* eh_Wi  = (const float*)d_in[10];
    const float* eh_br  = (const float*)d_in[11];
    const float* eh_bi  = (const float*)d_in[12];
    const float* fu_Wr  = (const float*)d_in[13];
    const float* fu_Wi  = (const float*)d_in[14];
    const float* fu_br  = (const float*)d_in[15];
    const float* fu_bi  = (const float*)d_in[16];
    const float* gW     = (const float*)d_in[17];
    const float* gb     = (const float*)d_in[18];
    float* out = (float*)d_out;

    float *FRF, *CB, *cgate, *WF, *U, *ubias;
    uint32_t *Gh, *Gl, *WFh, *CCh, *W2h, *Xh, *Xl, *Bch, *Bcl;
    cudaGetSymbolAddress((void**)&FRF,   g_FRF);
    cudaGetSymbolAddress((void**)&CB,    g_CB);
    cudaGetSymbolAddress((void**)&cgate, g_cgate);
    cudaGetSymbolAddress((void**)&WF,    g_WF);
    cudaGetSymbolAddress((void**)&U,     g_U);
    cudaGetSymbolAddress((void**)&ubias, g_ubias);
    cudaGetSymbolAddress((void**)&Gh,    g_Gh);
    cudaGetSymbolAddress((void**)&Gl,    g_Gl);
    cudaGetSymbolAddress((void**)&WFh,   g_WFh);
    cudaGetSymbolAddress((void**)&CCh,   g_CCh);
    cudaGetSymbolAddress((void**)&W2h,   g_W2h);
    cudaGetSymbolAddress((void**)&Xh,    g_Xh);
    cudaGetSymbolAddress((void**)&Xl,    g_Xl);
    cudaGetSymbolAddress((void**)&Bch,   g_Bch);
    cudaGetSymbolAddress((void**)&Bcl,   g_Bcl);

    cudaFuncSetAttribute(gemm_f16<1, 1, 0>, cudaFuncAttributeMaxDynamicSharedMemorySize, SMEMU);
    cudaFuncSetAttribute(gemm_f16<1, 0, 0>, cudaFuncAttributeMaxDynamicSharedMemorySize, SMEMF);
    cudaFuncSetAttribute(gemm_f16<0, 0, 1>, cudaFuncAttributeMaxDynamicSharedMemorySize, SMEMG);

    static cudaStream_t sP = nullptr;
    static cudaEvent_t evFork = nullptr, evJoin = nullptr;
    if (sP == nullptr) {
        cudaStreamCreateWithFlags(&sP, cudaStreamNonBlocking);
        cudaEventCreateWithFlags(&evFork, cudaEventDisableTiming);
        cudaEventCreateWithFlags(&evJoin, cudaEventDisableTiming);
    }

    cudaEventRecord(evFork, 0);
    cudaStreamWaitEvent(sP, evFork, 0);

    // --- precompute (weight composition) on side stream ---
    pquv_part_kernel<<<dim3(H / 64, E, 4), 256, 0, sP>>>(eh_Wr, eh_Wi, fu_Wr, fu_Wi);
    wf_reduce_kernel<<<(E * FDIM * 1024 + 255) / 256, 256, 0, sP>>>();
    crci_part_kernel<<<dim3(8, 64), 128, 0, sP>>>(eh_br, eh_bi, fu_Wr, fu_Wi);
    crci_reduce_kernel<<<8, 256, 0, sP>>>(fu_br, fu_bi);
    tpack_h_kernel<<<dim3(2048 / 32, KEG / 32), dim3(32, 8), 0, sP>>>(WF, GDIM, 2048, KPG, WFh);
    gcg_part_kernel<<<dim3(H / 64, 8, 4), 256, 0, sP>>>(gW);
    gcg_reduce_kernel<<<(GDIM * 1024 + 255) / 256, 256, 0, sP>>>();
    gate_wpack_kernel<<<dim3(1024 / 32, KEC / 32), dim3(32, 8), 0, sP>>>(gW);
    cgate_part_kernel<<<dim3(8, 8), 128, 0, sP>>>(gW);
    cgate_reduce_kernel<<<4, 256, 0, sP>>>(gb);
    cudaEventRecord(evJoin, sP);

    // --- main path on default stream ---
    pack_x_kernel<<<(M_TOT * 512 + 255) / 256, 256>>>(x);
    combine_proj_kernel<<<dim3(64, E), 256>>>(sig_Wr, sig_Wi, A_r, A_i);
    ubias_kernel<<<1, 128>>>(sig_br, sig_bi, A_r, A_i);
    pack_Bc_kernel<<<dim3(4, 32), dim3(32, 8)>>>();
    // U = x @ Bc + ubias  (fp16 3-term: ah*bh + al*bh + ah*bl)
    gemm_f16<1, 1, 0><<<dim3(1, M_TOT / 128), 256, SMEMU>>>(
        Xh, Xl, Bch, Bcl, U, M_TOT, 128, 1024, ubias, nullptr, 0, nullptr, 0);
    recur_p1<<<16 * NCH, 32>>>(lam_r, lam_i);
    recur_combine<<<1, 256>>>(lam_r, lam_i);
    recur_p2<<<16 * NCH, 32>>>(lam_r, lam_i);
    acc_combine_kernel<<<1, 16>>>();
    acc_fix_kernel<<<(16 * T + 255) / 256, 256>>>();
    pack_G_kernel<<<(M_TOT * KPG + 255) / 256, 256>>>();

    cudaStreamWaitEvent(0, evJoin, 0);

    // FRF = G @ WF + CB  (fp16, A split 2-term, ldmatrix)
    gemm_f16<1, 0, 0><<<dim3(2048 / 128, M_TOT / 128), 256, SMEMF>>>(
        Gh, Gl, WFh, nullptr, FRF, M_TOT, 2048, KEG, CB, nullptr, 0, nullptr, 0);
    concat_mag_kernel<<<M_TOT, 256>>>();
    // gate GEMM (fp16 single, ldmatrix) + fused epilogue
    gemm_f16<0, 0, 1><<<dim3(H / 128, M_TOT / 128), 256, SMEMG>>>(
        CCh, nullptr, W2h, nullptr, out, M_TOT, H, KEC, cgate, FRF, 2048, x, H);
}